// round 1
// baseline (speedup 1.0000x reference)
#include <cuda_runtime.h>
#include <math.h>

// ---------------------------------------------------------------------------
// Fused causal MHA forward, fp32, packed f32x2 FMA everywhere.
//   x[2,4096,2048] -> QKV proj -> RoPE -> causal flash attn -> out proj
// Scratch lives in __device__ globals (no allocation allowed).
// ---------------------------------------------------------------------------

#define SEQ   4096
#define BATCH 2
#define DM    2048
#define NH    16
#define DH    128
#define ROWS  (BATCH * SEQ)      // 8192

__device__ float g_Q[ROWS * DM];
__device__ float g_K[ROWS * DM];
__device__ float g_V[ROWS * DM];
__device__ float g_A[ROWS * DM];
__device__ float g_cos[SEQ * 64];
__device__ float g_sin[SEQ * 64];

// Packed fp32x2 FMA: d += a * b elementwise on both halves. PTX-only on sm_103a.
union F2U { float2 f; unsigned long long u; };
__device__ __forceinline__ void ffma2(float2& d, float2 a, float2 b) {
    F2U ud, ua, ub;
    ud.f = d; ua.f = a; ub.f = b;
    asm("fma.rn.f32x2 %0, %1, %2, %0;" : "+l"(ud.u) : "l"(ua.u), "l"(ub.u));
    d = ud.f;
}

// ---------------------------------------------------------------------------
// RoPE tables. Ref computes arg in fp32 then cos/sin; we take exact double
// sin/cos of the fp32-rounded arg (fp32 __cosf is useless at arg ~4096).
// ---------------------------------------------------------------------------
__global__ void rope_tables_kernel() {
    int idx = blockIdx.x * blockDim.x + threadIdx.x;   // [0, 4096*64)
    int s = idx >> 6, i = idx & 63;
    double invd = pow(10000.0, -((double)(2 * i)) / 128.0);
    float arg = (float)s * (float)invd;
    double sv, cv;
    sincos((double)arg, &sv, &cv);
    g_cos[idx] = (float)cv;
    g_sin[idx] = (float)sv;
}

// ---------------------------------------------------------------------------
// C[m,n] = sum_k A[m,k] * B[n,k]   (both K-major). 128x128x16 tiles, 256 thr,
// 8x8 microtile, accumulators paired along N as f32x2.
// ---------------------------------------------------------------------------
__global__ __launch_bounds__(256) void sgemm_nt(const float* __restrict__ A,
                                                const float* __restrict__ B,
                                                float* __restrict__ C,
                                                int M, int N, int K) {
    const int STR = 132;                 // 16B-aligned padded stride
    __shared__ float As[16 * STR];       // [k][m] transposed
    __shared__ float Bs[16 * STR];       // [k][n] transposed

    int tid = threadIdx.x;
    int tx = tid & 15, ty = tid >> 4;
    int bx = blockIdx.x, by = blockIdx.y;
    const float* Ab = A + (size_t)by * 128 * K;
    const float* Bb = B + (size_t)bx * 128 * K;

    float2 acc[8][4];
#pragma unroll
    for (int i = 0; i < 8; i++)
#pragma unroll
        for (int j = 0; j < 4; j++) acc[i][j] = make_float2(0.f, 0.f);

    int lrow = tid >> 2;
    int lcc  = (tid & 3) << 2;

    for (int k0 = 0; k0 < K; k0 += 16) {
#pragma unroll
        for (int l = 0; l < 2; ++l) {
            int row = lrow + l * 64;
            float4 va = *(const float4*)&Ab[(size_t)row * K + k0 + lcc];
            As[(lcc + 0) * STR + row] = va.x;
            As[(lcc + 1) * STR + row] = va.y;
            As[(lcc + 2) * STR + row] = va.z;
            As[(lcc + 3) * STR + row] = va.w;
            float4 vb = *(const float4*)&Bb[(size_t)row * K + k0 + lcc];
            Bs[(lcc + 0) * STR + row] = vb.x;
            Bs[(lcc + 1) * STR + row] = vb.y;
            Bs[(lcc + 2) * STR + row] = vb.z;
            Bs[(lcc + 3) * STR + row] = vb.w;
        }
        __syncthreads();
#pragma unroll
        for (int c = 0; c < 16; ++c) {
            float4 a0 = *(const float4*)&As[c * STR + ty * 4];
            float4 a1 = *(const float4*)&As[c * STR + 64 + ty * 4];
            float4 b0 = *(const float4*)&Bs[c * STR + tx * 4];
            float4 b1 = *(const float4*)&Bs[c * STR + 64 + tx * 4];
            float av[8] = {a0.x, a0.y, a0.z, a0.w, a1.x, a1.y, a1.z, a1.w};
            float2 b2[4] = {make_float2(b0.x, b0.y), make_float2(b0.z, b0.w),
                            make_float2(b1.x, b1.y), make_float2(b1.z, b1.w)};
#pragma unroll
            for (int mi = 0; mi < 8; ++mi) {
                float2 aa = make_float2(av[mi], av[mi]);
#pragma unroll
                for (int nj = 0; nj < 4; ++nj) ffma2(acc[mi][nj], aa, b2[nj]);
            }
        }
        __syncthreads();
    }

#pragma unroll
    for (int mi = 0; mi < 8; ++mi) {
        int row = by * 128 + ((mi & 4) ? 64 : 0) + ty * 4 + (mi & 3);
        float4 o0 = make_float4(acc[mi][0].x, acc[mi][0].y, acc[mi][1].x, acc[mi][1].y);
        float4 o1 = make_float4(acc[mi][2].x, acc[mi][2].y, acc[mi][3].x, acc[mi][3].y);
        *(float4*)&C[(size_t)row * N + bx * 128 + tx * 4] = o0;
        *(float4*)&C[(size_t)row * N + bx * 128 + 64 + tx * 4] = o1;
    }
}

// ---------------------------------------------------------------------------
// Interleaved RoPE, in-place on Q and K. Q also absorbs 1/sqrt(DH).
// ---------------------------------------------------------------------------
__global__ void rope_apply_kernel(float* __restrict__ Q, float* __restrict__ K) {
    int idx = blockIdx.x * blockDim.x + threadIdx.x;  // [0, 8192*1024)
    int row = idx >> 10;
    int p = idx & 1023;
    int h = p >> 6, i = p & 63;
    int s = row & (SEQ - 1);
    float c  = g_cos[(s << 6) + i];
    float sn = g_sin[(s << 6) + i];
    size_t off = (size_t)row * DM + h * DH + 2 * i;
    const float SC = 0.08838834764831845f;   // 1/sqrt(128)
    float2 q = *(float2*)&Q[off];
    float2 k = *(float2*)&K[off];
    float2 qo = make_float2((q.x * c - q.y * sn) * SC, (q.y * c + q.x * sn) * SC);
    float2 ko = make_float2(k.x * c - k.y * sn, k.y * c + k.x * sn);
    *(float2*)&Q[off] = qo;
    *(float2*)&K[off] = ko;
}

// ---------------------------------------------------------------------------
// Causal flash attention. One CTA = 64 q rows of one (b,h). 256 threads:
// tx in [0,16) owns strided score cols {tx+16j}, ty in [0,16) owns rows
// {ty*4+i}. All smem strides 132 floats -> conflict-free float4 access.
// ---------------------------------------------------------------------------
#define FA_SMEM_FLOATS (3 * 64 * 132 + 64 * 64)
#define FA_SMEM_BYTES  (FA_SMEM_FLOATS * 4)

__global__ __launch_bounds__(256) void flash_kernel(const float* __restrict__ Q,
                                                    const float* __restrict__ Kp,
                                                    const float* __restrict__ Vp,
                                                    float* __restrict__ Ap) {
    extern __shared__ float sm[];
    float* Qs = sm;                    // [64][132]
    float* Ks = sm + 64 * 132;         // [64][132]
    float* Vs = sm + 2 * 64 * 132;     // [64][132]
    float* Ps = sm + 3 * 64 * 132;     // [64][64]

    int tid = threadIdx.x;
    int tx = tid & 15, ty = tid >> 4;
    int qi = blockIdx.x;
    int bh = blockIdx.y;
    int b = bh >> 4, h = bh & 15;

    const float* Qg = Q + ((size_t)(b * SEQ + qi * 64)) * DM + h * DH;
#pragma unroll
    for (int l = 0; l < 8; ++l) {
        int f = tid + l * 256;
        int r = f >> 5, d4 = (f & 31) << 2;
        *(float4*)&Qs[r * 132 + d4] = *(const float4*)&Qg[(size_t)r * DM + d4];
    }

    float2 o2[4][4];
#pragma unroll
    for (int i = 0; i < 4; i++)
#pragma unroll
        for (int j = 0; j < 4; j++) o2[i][j] = make_float2(0.f, 0.f);
    float mrow[4], lrow[4];
#pragma unroll
    for (int i = 0; i < 4; i++) { mrow[i] = -INFINITY; lrow[i] = 0.f; }

    for (int kt = 0; kt <= qi; ++kt) {
        __syncthreads();   // prev PV done before tiles are overwritten
        const float* Kg = Kp + ((size_t)(b * SEQ + kt * 64)) * DM + h * DH;
        const float* Vg = Vp + ((size_t)(b * SEQ + kt * 64)) * DM + h * DH;
#pragma unroll
        for (int l = 0; l < 8; ++l) {
            int f = tid + l * 256;
            int r = f >> 5, d4 = (f & 31) << 2;
            *(float4*)&Ks[r * 132 + d4] = *(const float4*)&Kg[(size_t)r * DM + d4];
            *(float4*)&Vs[r * 132 + d4] = *(const float4*)&Vg[(size_t)r * DM + d4];
        }
        __syncthreads();

        // ---- S = Qs * Ks^T (scale pre-folded into Q), packed along d ----
        float2 s2[4][4];
#pragma unroll
        for (int i = 0; i < 4; i++)
#pragma unroll
            for (int j = 0; j < 4; j++) s2[i][j] = make_float2(0.f, 0.f);
#pragma unroll 8
        for (int d4 = 0; d4 < 32; ++d4) {
            float4 qv[4], kv[4];
#pragma unroll
            for (int i = 0; i < 4; i++) qv[i] = *(const float4*)&Qs[(ty * 4 + i) * 132 + d4 * 4];
#pragma unroll
            for (int j = 0; j < 4; j++) kv[j] = *(const float4*)&Ks[(tx + 16 * j) * 132 + d4 * 4];
#pragma unroll
            for (int i = 0; i < 4; i++) {
                float2 qlo = make_float2(qv[i].x, qv[i].y);
                float2 qhi = make_float2(qv[i].z, qv[i].w);
#pragma unroll
                for (int j = 0; j < 4; j++) {
                    ffma2(s2[i][j], qlo, make_float2(kv[j].x, kv[j].y));
                    ffma2(s2[i][j], qhi, make_float2(kv[j].z, kv[j].w));
                }
            }
        }
        float sc[4][4];
#pragma unroll
        for (int i = 0; i < 4; i++)
#pragma unroll
            for (int j = 0; j < 4; j++) sc[i][j] = s2[i][j].x + s2[i][j].y;

        if (kt == qi) {   // causal mask inside diagonal tile
#pragma unroll
            for (int i = 0; i < 4; i++)
#pragma unroll
                for (int j = 0; j < 4; j++)
                    if (tx + 16 * j > ty * 4 + i) sc[i][j] = -INFINITY;
        }

        // ---- online softmax ----
        float mnew[4], alpha[4];
#pragma unroll
        for (int i = 0; i < 4; i++) {
            float mx = fmaxf(fmaxf(sc[i][0], sc[i][1]), fmaxf(sc[i][2], sc[i][3]));
            mx = fmaxf(mx, __shfl_xor_sync(0xffffffffu, mx, 8));
            mx = fmaxf(mx, __shfl_xor_sync(0xffffffffu, mx, 4));
            mx = fmaxf(mx, __shfl_xor_sync(0xffffffffu, mx, 2));
            mx = fmaxf(mx, __shfl_xor_sync(0xffffffffu, mx, 1));
            mnew[i] = fmaxf(mrow[i], mx);
            alpha[i] = __expf(mrow[i] - mnew[i]);
            mrow[i] = mnew[i];
        }
        float pp[4][4], rsum[4];
#pragma unroll
        for (int i = 0; i < 4; i++) {
            rsum[i] = 0.f;
#pragma unroll
            for (int j = 0; j < 4; j++) {
                pp[i][j] = __expf(sc[i][j] - mnew[i]);
                rsum[i] += pp[i][j];
            }
            rsum[i] += __shfl_xor_sync(0xffffffffu, rsum[i], 8);
            rsum[i] += __shfl_xor_sync(0xffffffffu, rsum[i], 4);
            rsum[i] += __shfl_xor_sync(0xffffffffu, rsum[i], 2);
            rsum[i] += __shfl_xor_sync(0xffffffffu, rsum[i], 1);
            lrow[i] = lrow[i] * alpha[i] + rsum[i];
#pragma unroll
            for (int j = 0; j < 4; j++) { o2[i][j].x *= alpha[i]; o2[i][j].y *= alpha[i]; }
        }
#pragma unroll
        for (int i = 0; i < 4; i++)
#pragma unroll
            for (int j = 0; j < 4; j++)
                Ps[(ty * 4 + i) * 64 + tx + 16 * j] = pp[i][j];
        __syncthreads();

        // ---- O += P * V, packed along d-columns ----
#pragma unroll 4
        for (int c = 0; c < 64; ++c) {
            float4 v0 = *(const float4*)&Vs[c * 132 + tx * 4];
            float4 v1 = *(const float4*)&Vs[c * 132 + 64 + tx * 4];
            float2 v2[4] = {make_float2(v0.x, v0.y), make_float2(v0.z, v0.w),
                            make_float2(v1.x, v1.y), make_float2(v1.z, v1.w)};
#pragma unroll
            for (int i = 0; i < 4; i++) {
                float pc = Ps[(ty * 4 + i) * 64 + c];
                float2 pd = make_float2(pc, pc);
#pragma unroll
                for (int j = 0; j < 4; j++) ffma2(o2[i][j], pd, v2[j]);
            }
        }
    }

    // epilogue: normalize and store to A[b*S + row][h*128 + d]
#pragma unroll
    for (int i = 0; i < 4; i++) {
        float inv = 1.0f / lrow[i];
        size_t rowoff = (size_t)(b * SEQ + qi * 64 + ty * 4 + i) * DM + h * DH;
        float4 o0 = make_float4(o2[i][0].x * inv, o2[i][0].y * inv,
                                o2[i][1].x * inv, o2[i][1].y * inv);
        float4 o1 = make_float4(o2[i][2].x * inv, o2[i][2].y * inv,
                                o2[i][3].x * inv, o2[i][3].y * inv);
        *(float4*)&Ap[rowoff + tx * 4] = o0;
        *(float4*)&Ap[rowoff + 64 + tx * 4] = o1;
    }
}

// ---------------------------------------------------------------------------
extern "C" void kernel_launch(void* const* d_in, const int* in_sizes, int n_in,
                              void* d_out, int out_size) {
    const float* x  = (const float*)d_in[0];
    const float* Wq = (const float*)d_in[1];
    const float* Wk = (const float*)d_in[2];
    const float* Wv = (const float*)d_in[3];
    const float* Wo = (const float*)d_in[4];
    float* out = (float*)d_out;

    float *Q, *K, *V, *A;
    cudaGetSymbolAddress((void**)&Q, g_Q);
    cudaGetSymbolAddress((void**)&K, g_K);
    cudaGetSymbolAddress((void**)&V, g_V);
    cudaGetSymbolAddress((void**)&A, g_A);

    rope_tables_kernel<<<(SEQ * 64) / 256, 256>>>();

    dim3 gg(DM / 128, ROWS / 128);   // (16, 64)
    sgemm_nt<<<gg, 256>>>(x, Wq, Q, ROWS, DM, DM);
    sgemm_nt<<<gg, 256>>>(x, Wk, K, ROWS, DM, DM);
    sgemm_nt<<<gg, 256>>>(x, Wv, V, ROWS, DM, DM);

    rope_apply_kernel<<<(ROWS * (DM / 2)) / 256, 256>>>(Q, K);

    cudaFuncSetAttribute(flash_kernel, cudaFuncAttributeMaxDynamicSharedMemorySize,
                         FA_SMEM_BYTES);
    flash_kernel<<<dim3(SEQ / 64, BATCH * NH), 256, FA_SMEM_BYTES>>>(Q, K, V, A);

    sgemm_nt<<<gg, 256>>>(A, Wo, out, ROWS, DM, DM);
}

// round 2
// speedup vs baseline: 1.1140x; 1.1140x over previous
#include <cuda_runtime.h>
#include <math.h>

// ---------------------------------------------------------------------------
// Fused causal MHA forward.
//   GEMMs: tf32 tensor-core mma.sync, B split hi/lo for fp32-class accuracy.
//   Attention: fp32 flash kernel with packed f32x2 FMA.
// ---------------------------------------------------------------------------

#define SEQ   4096
#define BATCH 2
#define DM    2048
#define NH    16
#define DH    128
#define ROWS  (BATCH * SEQ)      // 8192

__device__ float g_Q[ROWS * DM];
__device__ float g_K[ROWS * DM];
__device__ float g_V[ROWS * DM];
__device__ float g_A[ROWS * DM];
__device__ float g_cos[SEQ * 64];
__device__ float g_sin[SEQ * 64];

// Packed fp32x2 FMA (PTX-only on sm_103a).
union F2U { float2 f; unsigned long long u; };
__device__ __forceinline__ void ffma2(float2& d, float2 a, float2 b) {
    F2U ud, ua, ub;
    ud.f = d; ua.f = a; ub.f = b;
    asm("fma.rn.f32x2 %0, %1, %2, %0;" : "+l"(ud.u) : "l"(ua.u), "l"(ub.u));
    d = ud.f;
}

__device__ __forceinline__ unsigned cvt_tf32(float x) {
    unsigned r;
    asm("cvt.rna.tf32.f32 %0, %1;" : "=r"(r) : "f"(x));
    return r;
}

__device__ __forceinline__ void mma_tf32(float4& c,
                                         unsigned a0, unsigned a1, unsigned a2, unsigned a3,
                                         unsigned b0, unsigned b1) {
    asm("mma.sync.aligned.m16n8k8.row.col.f32.tf32.tf32.f32 "
        "{%0,%1,%2,%3}, {%4,%5,%6,%7}, {%8,%9}, {%0,%1,%2,%3};"
        : "+f"(c.x), "+f"(c.y), "+f"(c.z), "+f"(c.w)
        : "r"(a0), "r"(a1), "r"(a2), "r"(a3), "r"(b0), "r"(b1));
}

// ---------------------------------------------------------------------------
// RoPE tables (exact double sincos of the fp32-rounded arg).
// ---------------------------------------------------------------------------
__global__ void rope_tables_kernel() {
    int idx = blockIdx.x * blockDim.x + threadIdx.x;   // [0, 4096*64)
    int s = idx >> 6, i = idx & 63;
    double invd = pow(10000.0, -((double)(2 * i)) / 128.0);
    float arg = (float)s * (float)invd;
    double sv, cv;
    sincos((double)arg, &sv, &cv);
    g_cos[idx] = (float)cv;
    g_sin[idx] = (float)sv;
}

// ---------------------------------------------------------------------------
// C[m,n] = sum_k A[m,k] * B[n,k], tensor-core tf32.
// A rounded to tf32 (rna); B split into hi+lo tf32 -> 2 MMAs, compensated.
// 128x128x32 tiles, 8 warps (2x4), warp tile 64x32 (4x4 m16n8k8 tiles).
// smem stride 36 floats -> conflict-free fragment loads.
// ---------------------------------------------------------------------------
#define MG_STR   36
#define MG_SMEM_BYTES (3 * 128 * MG_STR * 4)   // As, Bhi, Blo

__global__ __launch_bounds__(256) void mgemm_nt(const float* __restrict__ A,
                                                const float* __restrict__ B,
                                                float* __restrict__ C,
                                                int M, int N, int K) {
    extern __shared__ unsigned smu[];
    unsigned* As = smu;                       // [128][36] tf32 bits
    unsigned* Bh = smu + 128 * MG_STR;        // [128][36]
    unsigned* Bl = smu + 2 * 128 * MG_STR;    // [128][36]

    int tid = threadIdx.x;
    int wid = tid >> 5, lane = tid & 31;
    int wm = wid >> 2, wn = wid & 3;          // warp tile: rows wm*64, cols wn*32
    int grp = lane >> 2, qd = lane & 3;
    int bx = blockIdx.x, by = blockIdx.y;

    const float* Ab = A + (size_t)(by * 128) * K;
    const float* Bb = B + (size_t)(bx * 128) * K;

    float4 acc[4][4];
#pragma unroll
    for (int i = 0; i < 4; i++)
#pragma unroll
        for (int j = 0; j < 4; j++) acc[i][j] = make_float4(0.f, 0.f, 0.f, 0.f);

    int lrow = tid >> 3;            // 0..31
    int lc4  = (tid & 7) << 2;      // float4 col

    for (int k0 = 0; k0 < K; k0 += 32) {
#pragma unroll
        for (int l = 0; l < 4; ++l) {
            int row = lrow + 32 * l;
            float4 va = *(const float4*)&Ab[(size_t)row * K + k0 + lc4];
            unsigned* ap = &As[row * MG_STR + lc4];
            ap[0] = cvt_tf32(va.x); ap[1] = cvt_tf32(va.y);
            ap[2] = cvt_tf32(va.z); ap[3] = cvt_tf32(va.w);

            float4 vb = *(const float4*)&Bb[(size_t)row * K + k0 + lc4];
            unsigned h0 = cvt_tf32(vb.x), h1 = cvt_tf32(vb.y);
            unsigned h2 = cvt_tf32(vb.z), h3 = cvt_tf32(vb.w);
            unsigned* hp = &Bh[row * MG_STR + lc4];
            hp[0] = h0; hp[1] = h1; hp[2] = h2; hp[3] = h3;
            unsigned* lp = &Bl[row * MG_STR + lc4];
            lp[0] = cvt_tf32(vb.x - __uint_as_float(h0));
            lp[1] = cvt_tf32(vb.y - __uint_as_float(h1));
            lp[2] = cvt_tf32(vb.z - __uint_as_float(h2));
            lp[3] = cvt_tf32(vb.w - __uint_as_float(h3));
        }
        __syncthreads();

#pragma unroll
        for (int ks = 0; ks < 4; ++ks) {
            int kk = ks * 8;
            unsigned a[4][4];
#pragma unroll
            for (int mi = 0; mi < 4; ++mi) {
                int r = wm * 64 + mi * 16 + grp;
                a[mi][0] = As[r * MG_STR + kk + qd];
                a[mi][1] = As[(r + 8) * MG_STR + kk + qd];
                a[mi][2] = As[r * MG_STR + kk + 4 + qd];
                a[mi][3] = As[(r + 8) * MG_STR + kk + 4 + qd];
            }
            unsigned bh[4][2], bl[4][2];
#pragma unroll
            for (int ni = 0; ni < 4; ++ni) {
                int c = wn * 32 + ni * 8 + grp;
                bh[ni][0] = Bh[c * MG_STR + kk + qd];
                bh[ni][1] = Bh[c * MG_STR + kk + 4 + qd];
                bl[ni][0] = Bl[c * MG_STR + kk + qd];
                bl[ni][1] = Bl[c * MG_STR + kk + 4 + qd];
            }
#pragma unroll
            for (int mi = 0; mi < 4; ++mi)
#pragma unroll
                for (int ni = 0; ni < 4; ++ni) {
                    mma_tf32(acc[mi][ni], a[mi][0], a[mi][1], a[mi][2], a[mi][3],
                             bh[ni][0], bh[ni][1]);
                    mma_tf32(acc[mi][ni], a[mi][0], a[mi][1], a[mi][2], a[mi][3],
                             bl[ni][0], bl[ni][1]);
                }
        }
        __syncthreads();
    }

#pragma unroll
    for (int mi = 0; mi < 4; ++mi)
#pragma unroll
        for (int ni = 0; ni < 4; ++ni) {
            int r0 = by * 128 + wm * 64 + mi * 16 + grp;
            int c0 = bx * 128 + wn * 32 + ni * 8 + 2 * qd;
            *(float2*)&C[(size_t)r0 * N + c0] = make_float2(acc[mi][ni].x, acc[mi][ni].y);
            *(float2*)&C[(size_t)(r0 + 8) * N + c0] = make_float2(acc[mi][ni].z, acc[mi][ni].w);
        }
}

// ---------------------------------------------------------------------------
// Interleaved RoPE, in-place on Q and K. Q also absorbs 1/sqrt(DH).
// ---------------------------------------------------------------------------
__global__ void rope_apply_kernel(float* __restrict__ Q, float* __restrict__ K) {
    int idx = blockIdx.x * blockDim.x + threadIdx.x;  // [0, 8192*1024)
    int row = idx >> 10;
    int p = idx & 1023;
    int h = p >> 6, i = p & 63;
    int s = row & (SEQ - 1);
    float c  = g_cos[(s << 6) + i];
    float sn = g_sin[(s << 6) + i];
    size_t off = (size_t)row * DM + h * DH + 2 * i;
    const float SC = 0.08838834764831845f;   // 1/sqrt(128)
    float2 q = *(float2*)&Q[off];
    float2 k = *(float2*)&K[off];
    float2 qo = make_float2((q.x * c - q.y * sn) * SC, (q.y * c + q.x * sn) * SC);
    float2 ko = make_float2(k.x * c - k.y * sn, k.y * c + k.x * sn);
    *(float2*)&Q[off] = qo;
    *(float2*)&K[off] = ko;
}

// ---------------------------------------------------------------------------
// Causal flash attention (fp32, f32x2 FMA). One CTA = 64 q rows of one (b,h).
// ---------------------------------------------------------------------------
#define FA_SMEM_FLOATS (3 * 64 * 132 + 64 * 64)
#define FA_SMEM_BYTES  (FA_SMEM_FLOATS * 4)

__global__ __launch_bounds__(256) void flash_kernel(const float* __restrict__ Q,
                                                    const float* __restrict__ Kp,
                                                    const float* __restrict__ Vp,
                                                    float* __restrict__ Ap) {
    extern __shared__ float sm[];
    float* Qs = sm;                    // [64][132]
    float* Ks = sm + 64 * 132;         // [64][132]
    float* Vs = sm + 2 * 64 * 132;     // [64][132]
    float* Ps = sm + 3 * 64 * 132;     // [64][64]

    int tid = threadIdx.x;
    int tx = tid & 15, ty = tid >> 4;
    int qi = blockIdx.x;
    int bh = blockIdx.y;
    int b = bh >> 4, h = bh & 15;

    const float* Qg = Q + ((size_t)(b * SEQ + qi * 64)) * DM + h * DH;
#pragma unroll
    for (int l = 0; l < 8; ++l) {
        int f = tid + l * 256;
        int r = f >> 5, d4 = (f & 31) << 2;
        *(float4*)&Qs[r * 132 + d4] = *(const float4*)&Qg[(size_t)r * DM + d4];
    }

    float2 o2[4][4];
#pragma unroll
    for (int i = 0; i < 4; i++)
#pragma unroll
        for (int j = 0; j < 4; j++) o2[i][j] = make_float2(0.f, 0.f);
    float mrow[4], lrow[4];
#pragma unroll
    for (int i = 0; i < 4; i++) { mrow[i] = -INFINITY; lrow[i] = 0.f; }

    for (int kt = 0; kt <= qi; ++kt) {
        __syncthreads();
        const float* Kg = Kp + ((size_t)(b * SEQ + kt * 64)) * DM + h * DH;
        const float* Vg = Vp + ((size_t)(b * SEQ + kt * 64)) * DM + h * DH;
#pragma unroll
        for (int l = 0; l < 8; ++l) {
            int f = tid + l * 256;
            int r = f >> 5, d4 = (f & 31) << 2;
            *(float4*)&Ks[r * 132 + d4] = *(const float4*)&Kg[(size_t)r * DM + d4];
            *(float4*)&Vs[r * 132 + d4] = *(const float4*)&Vg[(size_t)r * DM + d4];
        }
        __syncthreads();

        float2 s2[4][4];
#pragma unroll
        for (int i = 0; i < 4; i++)
#pragma unroll
            for (int j = 0; j < 4; j++) s2[i][j] = make_float2(0.f, 0.f);
#pragma unroll 8
        for (int d4 = 0; d4 < 32; ++d4) {
            float4 qv[4], kv[4];
#pragma unroll
            for (int i = 0; i < 4; i++) qv[i] = *(const float4*)&Qs[(ty * 4 + i) * 132 + d4 * 4];
#pragma unroll
            for (int j = 0; j < 4; j++) kv[j] = *(const float4*)&Ks[(tx + 16 * j) * 132 + d4 * 4];
#pragma unroll
            for (int i = 0; i < 4; i++) {
                float2 qlo = make_float2(qv[i].x, qv[i].y);
                float2 qhi = make_float2(qv[i].z, qv[i].w);
#pragma unroll
                for (int j = 0; j < 4; j++) {
                    ffma2(s2[i][j], qlo, make_float2(kv[j].x, kv[j].y));
                    ffma2(s2[i][j], qhi, make_float2(kv[j].z, kv[j].w));
                }
            }
        }
        float sc[4][4];
#pragma unroll
        for (int i = 0; i < 4; i++)
#pragma unroll
            for (int j = 0; j < 4; j++) sc[i][j] = s2[i][j].x + s2[i][j].y;

        if (kt == qi) {
#pragma unroll
            for (int i = 0; i < 4; i++)
#pragma unroll
                for (int j = 0; j < 4; j++)
                    if (tx + 16 * j > ty * 4 + i) sc[i][j] = -INFINITY;
        }

        float mnew[4], alpha[4];
#pragma unroll
        for (int i = 0; i < 4; i++) {
            float mx = fmaxf(fmaxf(sc[i][0], sc[i][1]), fmaxf(sc[i][2], sc[i][3]));
            mx = fmaxf(mx, __shfl_xor_sync(0xffffffffu, mx, 8));
            mx = fmaxf(mx, __shfl_xor_sync(0xffffffffu, mx, 4));
            mx = fmaxf(mx, __shfl_xor_sync(0xffffffffu, mx, 2));
            mx = fmaxf(mx, __shfl_xor_sync(0xffffffffu, mx, 1));
            mnew[i] = fmaxf(mrow[i], mx);
            alpha[i] = __expf(mrow[i] - mnew[i]);
            mrow[i] = mnew[i];
        }
        float pp[4][4], rsum[4];
#pragma unroll
        for (int i = 0; i < 4; i++) {
            rsum[i] = 0.f;
#pragma unroll
            for (int j = 0; j < 4; j++) {
                pp[i][j] = __expf(sc[i][j] - mnew[i]);
                rsum[i] += pp[i][j];
            }
            rsum[i] += __shfl_xor_sync(0xffffffffu, rsum[i], 8);
            rsum[i] += __shfl_xor_sync(0xffffffffu, rsum[i], 4);
            rsum[i] += __shfl_xor_sync(0xffffffffu, rsum[i], 2);
            rsum[i] += __shfl_xor_sync(0xffffffffu, rsum[i], 1);
            lrow[i] = lrow[i] * alpha[i] + rsum[i];
#pragma unroll
            for (int j = 0; j < 4; j++) { o2[i][j].x *= alpha[i]; o2[i][j].y *= alpha[i]; }
        }
#pragma unroll
        for (int i = 0; i < 4; i++)
#pragma unroll
            for (int j = 0; j < 4; j++)
                Ps[(ty * 4 + i) * 64 + tx + 16 * j] = pp[i][j];
        __syncthreads();

#pragma unroll 4
        for (int c = 0; c < 64; ++c) {
            float4 v0 = *(const float4*)&Vs[c * 132 + tx * 4];
            float4 v1 = *(const float4*)&Vs[c * 132 + 64 + tx * 4];
            float2 v2[4] = {make_float2(v0.x, v0.y), make_float2(v0.z, v0.w),
                            make_float2(v1.x, v1.y), make_float2(v1.z, v1.w)};
#pragma unroll
            for (int i = 0; i < 4; i++) {
                float pc = Ps[(ty * 4 + i) * 64 + c];
                float2 pd = make_float2(pc, pc);
#pragma unroll
                for (int j = 0; j < 4; j++) ffma2(o2[i][j], pd, v2[j]);
            }
        }
    }

#pragma unroll
    for (int i = 0; i < 4; i++) {
        float inv = 1.0f / lrow[i];
        size_t rowoff = (size_t)(b * SEQ + qi * 64 + ty * 4 + i) * DM + h * DH;
        float4 o0 = make_float4(o2[i][0].x * inv, o2[i][0].y * inv,
                                o2[i][1].x * inv, o2[i][1].y * inv);
        float4 o1 = make_float4(o2[i][2].x * inv, o2[i][2].y * inv,
                                o2[i][3].x * inv, o2[i][3].y * inv);
        *(float4*)&Ap[rowoff + tx * 4] = o0;
        *(float4*)&Ap[rowoff + 64 + tx * 4] = o1;
    }
}

// ---------------------------------------------------------------------------
extern "C" void kernel_launch(void* const* d_in, const int* in_sizes, int n_in,
                              void* d_out, int out_size) {
    const float* x  = (const float*)d_in[0];
    const float* Wq = (const float*)d_in[1];
    const float* Wk = (const float*)d_in[2];
    const float* Wv = (const float*)d_in[3];
    const float* Wo = (const float*)d_in[4];
    float* out = (float*)d_out;

    float *Q, *K, *V, *A;
    cudaGetSymbolAddress((void**)&Q, g_Q);
    cudaGetSymbolAddress((void**)&K, g_K);
    cudaGetSymbolAddress((void**)&V, g_V);
    cudaGetSymbolAddress((void**)&A, g_A);

    rope_tables_kernel<<<(SEQ * 64) / 256, 256>>>();

    cudaFuncSetAttribute(mgemm_nt, cudaFuncAttributeMaxDynamicSharedMemorySize,
                         MG_SMEM_BYTES);
    dim3 gg(DM / 128, ROWS / 128);   // (16, 64)
    mgemm_nt<<<gg, 256, MG_SMEM_BYTES>>>(x, Wq, Q, ROWS, DM, DM);
    mgemm_nt<<<gg, 256, MG_SMEM_BYTES>>>(x, Wk, K, ROWS, DM, DM);
    mgemm_nt<<<gg, 256, MG_SMEM_BYTES>>>(x, Wv, V, ROWS, DM, DM);

    rope_apply_kernel<<<(ROWS * (DM / 2)) / 256, 256>>>(Q, K);

    cudaFuncSetAttribute(flash_kernel, cudaFuncAttributeMaxDynamicSharedMemorySize,
                         FA_SMEM_BYTES);
    flash_kernel<<<dim3(SEQ / 64, BATCH * NH), 256, FA_SMEM_BYTES>>>(Q, K, V, A);

    mgemm_nt<<<gg, 256, MG_SMEM_BYTES>>>(A, Wo, out, ROWS, DM, DM);
}

// round 3
// speedup vs baseline: 1.3702x; 1.2300x over previous
#include <cuda_runtime.h>
#include <cuda_bf16.h>
#include <math.h>

// ---------------------------------------------------------------------------
// Fused causal MHA forward.
//   GEMMs: bf16x3 (hi/lo split both operands, 3 MMAs) on mma.sync.m16n8k16,
//          cp.async double-buffered, ~fp32 accuracy.
//   Attention: fp32 flash kernel with packed f32x2 FMA.
// ---------------------------------------------------------------------------

#define SEQ   4096
#define BATCH 2
#define DM    2048
#define NH    16
#define DH    128
#define ROWS  (BATCH * SEQ)      // 8192

__device__ float g_Q[ROWS * DM];
__device__ float g_K[ROWS * DM];
__device__ float g_V[ROWS * DM];
__device__ float g_A[ROWS * DM];
__device__ float g_cos[SEQ * 64];
__device__ float g_sin[SEQ * 64];

// Split storage: per element-pair (2k,2k+1): uint32 hi(bf16x2), uint32 lo(bf16x2)
// interleaved -> row of K elements occupies K uint32.
__device__ unsigned g_xs[ROWS * DM];   // x split (8192x2048)
__device__ unsigned g_as[ROWS * DM];   // attn-out split
__device__ unsigned g_ws[DM * DM];     // weight split (reused sequentially)

// Packed fp32x2 FMA (PTX-only on sm_103a).
union F2U { float2 f; unsigned long long u; };
__device__ __forceinline__ void ffma2(float2& d, float2 a, float2 b) {
    F2U ud, ua, ub;
    ud.f = d; ua.f = a; ub.f = b;
    asm("fma.rn.f32x2 %0, %1, %2, %0;" : "+l"(ud.u) : "l"(ua.u), "l"(ub.u));
    d = ud.f;
}

__device__ __forceinline__ void mma_bf16(float4& c,
                                         unsigned a0, unsigned a1, unsigned a2, unsigned a3,
                                         unsigned b0, unsigned b1) {
    asm("mma.sync.aligned.m16n8k16.row.col.f32.bf16.bf16.f32 "
        "{%0,%1,%2,%3}, {%4,%5,%6,%7}, {%8,%9}, {%0,%1,%2,%3};"
        : "+f"(c.x), "+f"(c.y), "+f"(c.z), "+f"(c.w)
        : "r"(a0), "r"(a1), "r"(a2), "r"(a3), "r"(b0), "r"(b1));
}

// ---------------------------------------------------------------------------
// Split fp32 -> (bf16 hi, bf16 lo), pairwise packed, interleaved hi/lo.
// ---------------------------------------------------------------------------
__global__ void split_kernel(const float* __restrict__ s, unsigned* __restrict__ d,
                             int npairs) {
    int p = blockIdx.x * blockDim.x + threadIdx.x;
    if (p >= npairs) return;
    float2 v = *(const float2*)&s[2 * p];
    unsigned hi;
    asm("cvt.rn.bf16x2.f32 %0, %1, %2;" : "=r"(hi) : "f"(v.y), "f"(v.x));
    float h0 = __uint_as_float(hi << 16);
    float h1 = __uint_as_float(hi & 0xffff0000u);
    unsigned lo;
    asm("cvt.rn.bf16x2.f32 %0, %1, %2;" : "=r"(lo) : "f"(v.y - h1), "f"(v.x - h0));
    *(uint2*)&d[2 * p] = make_uint2(hi, lo);
}

// ---------------------------------------------------------------------------
// RoPE tables (exact double sincos of the fp32-rounded arg).
// ---------------------------------------------------------------------------
__global__ void rope_tables_kernel() {
    int idx = blockIdx.x * blockDim.x + threadIdx.x;   // [0, 4096*64)
    int s = idx >> 6, i = idx & 63;
    double invd = pow(10000.0, -((double)(2 * i)) / 128.0);
    float arg = (float)s * (float)invd;
    double sv, cv;
    sincos((double)arg, &sv, &cv);
    g_cos[idx] = (float)cv;
    g_sin[idx] = (float)sv;
}

// ---------------------------------------------------------------------------
// C[m,n] = sum_k A[m,k]*B[n,k] from pre-split bf16 hi/lo pairs.
// 128x128x32 tiles, 8 warps (2x4), warp tile 64x32, m16n8k16 bf16, 3 MMAs
// per (tile,k16). cp.async 2-stage pipeline. K = N = 2048 fixed.
//
// smem per stage per matrix: 128 rows x 40 uint32 (32 data + 8 pad); row
// stride 20 x 8B => fragment LDS.64 conflict-free (addr8 = 4*grp + qd).
// ---------------------------------------------------------------------------
#define MG_ROWU   40
#define MG_MATU   (128 * MG_ROWU)          // 5120 uint32
#define MG_STAGEU (2 * MG_MATU)            // 10240 uint32
#define MG_SMEM_BYTES (2 * MG_STAGEU * 4)  // 81920 B
#define MG_KT     (DM / 32)                // 64

__global__ __launch_bounds__(256) void mgemm_bf3(const unsigned* __restrict__ Ag,
                                                 const unsigned* __restrict__ Bg,
                                                 float* __restrict__ C) {
    extern __shared__ unsigned sm[];
    const unsigned sbase = (unsigned)__cvta_generic_to_shared(sm);

    const int tid = threadIdx.x;
    const int wid = tid >> 5, lane = tid & 31;
    const int wm = wid >> 2, wn = wid & 3;
    const int grp = lane >> 3 | ((lane >> 2) & 1) * 0;  // placeholder, fixed below
    const int g8 = lane >> 2;        // 0..7
    const int qd = lane & 3;         // 0..3
    const int bx = blockIdx.x, by = blockIdx.y;

    float4 acc[4][4];
#pragma unroll
    for (int i = 0; i < 4; i++)
#pragma unroll
        for (int j = 0; j < 4; j++) acc[i][j] = make_float4(0.f, 0.f, 0.f, 0.f);

    // cp.async stage loader: 2048 16B-chunks, 8 per thread.
    auto load_stage = [&](int s, int k0u) {
#pragma unroll
        for (int t = 0; t < 8; ++t) {
            int c = tid + (t << 8);
            int mat = c >> 10;
            int rem = c & 1023;
            int r = rem >> 3;
            int ch = rem & 7;
            const unsigned* g = (mat ? Bg + (size_t)(bx * 128 + r) * DM
                                     : Ag + (size_t)(by * 128 + r) * DM)
                                + k0u + ch * 4;
            unsigned dst = sbase + (unsigned)(s * MG_STAGEU + mat * MG_MATU
                                              + r * MG_ROWU + ch * 4) * 4u;
            asm volatile("cp.async.cg.shared.global [%0], [%1], 16;"
                         :: "r"(dst), "l"(g));
        }
        asm volatile("cp.async.commit_group;");
    };

    load_stage(0, 0);

    for (int kt = 0; kt < MG_KT; ++kt) {
        if (kt + 1 < MG_KT) {
            load_stage((kt + 1) & 1, (kt + 1) * 32);
            asm volatile("cp.async.wait_group 1;");
        } else {
            asm volatile("cp.async.wait_group 0;");
        }
        __syncthreads();

        const unsigned* Sa = sm + (kt & 1) * MG_STAGEU;
        const unsigned* Sb = Sa + MG_MATU;

#pragma unroll
        for (int ks = 0; ks < 2; ++ks) {
            // fragment pair positions (uint32 idx): pos = 2*pair, pair = ks*8+qd (+4)
            const int p0 = (ks * 8 + qd) * 2;
            const int p1 = (ks * 8 + qd + 4) * 2;

            uint2 afr[4][4];
#pragma unroll
            for (int mi = 0; mi < 4; ++mi) {
                int row = wm * 64 + mi * 16 + g8;
                afr[mi][0] = *(const uint2*)&Sa[row * MG_ROWU + p0];        // a0 (hi,lo)
                afr[mi][1] = *(const uint2*)&Sa[row * MG_ROWU + p1];        // a2
                afr[mi][2] = *(const uint2*)&Sa[(row + 8) * MG_ROWU + p0];  // a1
                afr[mi][3] = *(const uint2*)&Sa[(row + 8) * MG_ROWU + p1];  // a3
            }
            uint2 bfr[4][2];
#pragma unroll
            for (int ni = 0; ni < 4; ++ni) {
                int col = wn * 32 + ni * 8 + g8;
                bfr[ni][0] = *(const uint2*)&Sb[col * MG_ROWU + p0];        // b0
                bfr[ni][1] = *(const uint2*)&Sb[col * MG_ROWU + p1];        // b1
            }
#pragma unroll
            for (int mi = 0; mi < 4; ++mi)
#pragma unroll
                for (int ni = 0; ni < 4; ++ni) {
                    // hi*hi
                    mma_bf16(acc[mi][ni],
                             afr[mi][0].x, afr[mi][2].x, afr[mi][1].x, afr[mi][3].x,
                             bfr[ni][0].x, bfr[ni][1].x);
                    // hi_a * lo_b
                    mma_bf16(acc[mi][ni],
                             afr[mi][0].x, afr[mi][2].x, afr[mi][1].x, afr[mi][3].x,
                             bfr[ni][0].y, bfr[ni][1].y);
                    // lo_a * hi_b
                    mma_bf16(acc[mi][ni],
                             afr[mi][0].y, afr[mi][2].y, afr[mi][1].y, afr[mi][3].y,
                             bfr[ni][0].x, bfr[ni][1].x);
                }
        }
        __syncthreads();
    }

#pragma unroll
    for (int mi = 0; mi < 4; ++mi)
#pragma unroll
        for (int ni = 0; ni < 4; ++ni) {
            int r0 = by * 128 + wm * 64 + mi * 16 + g8;
            int c0 = bx * 128 + wn * 32 + ni * 8 + 2 * qd;
            *(float2*)&C[(size_t)r0 * DM + c0] = make_float2(acc[mi][ni].x, acc[mi][ni].y);
            *(float2*)&C[(size_t)(r0 + 8) * DM + c0] = make_float2(acc[mi][ni].z, acc[mi][ni].w);
        }
}

// ---------------------------------------------------------------------------
// Interleaved RoPE, in-place on Q and K. Q also absorbs 1/sqrt(DH).
// ---------------------------------------------------------------------------
__global__ void rope_apply_kernel(float* __restrict__ Q, float* __restrict__ K) {
    int idx = blockIdx.x * blockDim.x + threadIdx.x;  // [0, 8192*1024)
    int row = idx >> 10;
    int p = idx & 1023;
    int h = p >> 6, i = p & 63;
    int s = row & (SEQ - 1);
    float c  = g_cos[(s << 6) + i];
    float sn = g_sin[(s << 6) + i];
    size_t off = (size_t)row * DM + h * DH + 2 * i;
    const float SC = 0.08838834764831845f;   // 1/sqrt(128)
    float2 q = *(float2*)&Q[off];
    float2 k = *(float2*)&K[off];
    float2 qo = make_float2((q.x * c - q.y * sn) * SC, (q.y * c + q.x * sn) * SC);
    float2 ko = make_float2(k.x * c - k.y * sn, k.y * c + k.x * sn);
    *(float2*)&Q[off] = qo;
    *(float2*)&K[off] = ko;
}

// ---------------------------------------------------------------------------
// Causal flash attention (fp32, f32x2 FMA). One CTA = 64 q rows of one (b,h).
// ---------------------------------------------------------------------------
#define FA_SMEM_FLOATS (3 * 64 * 132 + 64 * 64)
#define FA_SMEM_BYTES  (FA_SMEM_FLOATS * 4)

__global__ __launch_bounds__(256) void flash_kernel(const float* __restrict__ Q,
                                                    const float* __restrict__ Kp,
                                                    const float* __restrict__ Vp,
                                                    float* __restrict__ Ap) {
    extern __shared__ float smf[];
    float* Qs = smf;                    // [64][132]
    float* Ks = smf + 64 * 132;         // [64][132]
    float* Vs = smf + 2 * 64 * 132;     // [64][132]
    float* Ps = smf + 3 * 64 * 132;     // [64][64]

    int tid = threadIdx.x;
    int tx = tid & 15, ty = tid >> 4;
    int qi = blockIdx.x;
    int bh = blockIdx.y;
    int b = bh >> 4, h = bh & 15;

    const float* Qg = Q + ((size_t)(b * SEQ + qi * 64)) * DM + h * DH;
#pragma unroll
    for (int l = 0; l < 8; ++l) {
        int f = tid + l * 256;
        int r = f >> 5, d4 = (f & 31) << 2;
        *(float4*)&Qs[r * 132 + d4] = *(const float4*)&Qg[(size_t)r * DM + d4];
    }

    float2 o2[4][4];
#pragma unroll
    for (int i = 0; i < 4; i++)
#pragma unroll
        for (int j = 0; j < 4; j++) o2[i][j] = make_float2(0.f, 0.f);
    float mrow[4], lrow[4];
#pragma unroll
    for (int i = 0; i < 4; i++) { mrow[i] = -INFINITY; lrow[i] = 0.f; }

    for (int kt = 0; kt <= qi; ++kt) {
        __syncthreads();
        const float* Kg = Kp + ((size_t)(b * SEQ + kt * 64)) * DM + h * DH;
        const float* Vg = Vp + ((size_t)(b * SEQ + kt * 64)) * DM + h * DH;
#pragma unroll
        for (int l = 0; l < 8; ++l) {
            int f = tid + l * 256;
            int r = f >> 5, d4 = (f & 31) << 2;
            *(float4*)&Ks[r * 132 + d4] = *(const float4*)&Kg[(size_t)r * DM + d4];
            *(float4*)&Vs[r * 132 + d4] = *(const float4*)&Vg[(size_t)r * DM + d4];
        }
        __syncthreads();

        float2 s2[4][4];
#pragma unroll
        for (int i = 0; i < 4; i++)
#pragma unroll
            for (int j = 0; j < 4; j++) s2[i][j] = make_float2(0.f, 0.f);
#pragma unroll 8
        for (int d4 = 0; d4 < 32; ++d4) {
            float4 qv[4], kv[4];
#pragma unroll
            for (int i = 0; i < 4; i++) qv[i] = *(const float4*)&Qs[(ty * 4 + i) * 132 + d4 * 4];
#pragma unroll
            for (int j = 0; j < 4; j++) kv[j] = *(const float4*)&Ks[(tx + 16 * j) * 132 + d4 * 4];
#pragma unroll
            for (int i = 0; i < 4; i++) {
                float2 qlo = make_float2(qv[i].x, qv[i].y);
                float2 qhi = make_float2(qv[i].z, qv[i].w);
#pragma unroll
                for (int j = 0; j < 4; j++) {
                    ffma2(s2[i][j], qlo, make_float2(kv[j].x, kv[j].y));
                    ffma2(s2[i][j], qhi, make_float2(kv[j].z, kv[j].w));
                }
            }
        }
        float sc[4][4];
#pragma unroll
        for (int i = 0; i < 4; i++)
#pragma unroll
            for (int j = 0; j < 4; j++) sc[i][j] = s2[i][j].x + s2[i][j].y;

        if (kt == qi) {
#pragma unroll
            for (int i = 0; i < 4; i++)
#pragma unroll
                for (int j = 0; j < 4; j++)
                    if (tx + 16 * j > ty * 4 + i) sc[i][j] = -INFINITY;
        }

        float mnew[4], alpha[4];
#pragma unroll
        for (int i = 0; i < 4; i++) {
            float mx = fmaxf(fmaxf(sc[i][0], sc[i][1]), fmaxf(sc[i][2], sc[i][3]));
            mx = fmaxf(mx, __shfl_xor_sync(0xffffffffu, mx, 8));
            mx = fmaxf(mx, __shfl_xor_sync(0xffffffffu, mx, 4));
            mx = fmaxf(mx, __shfl_xor_sync(0xffffffffu, mx, 2));
            mx = fmaxf(mx, __shfl_xor_sync(0xffffffffu, mx, 1));
            mnew[i] = fmaxf(mrow[i], mx);
            alpha[i] = __expf(mrow[i] - mnew[i]);
            mrow[i] = mnew[i];
        }
        float pp[4][4], rsum[4];
#pragma unroll
        for (int i = 0; i < 4; i++) {
            rsum[i] = 0.f;
#pragma unroll
            for (int j = 0; j < 4; j++) {
                pp[i][j] = __expf(sc[i][j] - mnew[i]);
                rsum[i] += pp[i][j];
            }
            rsum[i] += __shfl_xor_sync(0xffffffffu, rsum[i], 8);
            rsum[i] += __shfl_xor_sync(0xffffffffu, rsum[i], 4);
            rsum[i] += __shfl_xor_sync(0xffffffffu, rsum[i], 2);
            rsum[i] += __shfl_xor_sync(0xffffffffu, rsum[i], 1);
            lrow[i] = lrow[i] * alpha[i] + rsum[i];
#pragma unroll
            for (int j = 0; j < 4; j++) { o2[i][j].x *= alpha[i]; o2[i][j].y *= alpha[i]; }
        }
#pragma unroll
        for (int i = 0; i < 4; i++)
#pragma unroll
            for (int j = 0; j < 4; j++)
                Ps[(ty * 4 + i) * 64 + tx + 16 * j] = pp[i][j];
        __syncthreads();

#pragma unroll 4
        for (int c = 0; c < 64; ++c) {
            float4 v0 = *(const float4*)&Vs[c * 132 + tx * 4];
            float4 v1 = *(const float4*)&Vs[c * 132 + 64 + tx * 4];
            float2 v2[4] = {make_float2(v0.x, v0.y), make_float2(v0.z, v0.w),
                            make_float2(v1.x, v1.y), make_float2(v1.z, v1.w)};
#pragma unroll
            for (int i = 0; i < 4; i++) {
                float pc = Ps[(ty * 4 + i) * 64 + c];
                float2 pd = make_float2(pc, pc);
#pragma unroll
                for (int j = 0; j < 4; j++) ffma2(o2[i][j], pd, v2[j]);
            }
        }
    }

#pragma unroll
    for (int i = 0; i < 4; i++) {
        float inv = 1.0f / lrow[i];
        size_t rowoff = (size_t)(b * SEQ + qi * 64 + ty * 4 + i) * DM + h * DH;
        float4 o0 = make_float4(o2[i][0].x * inv, o2[i][0].y * inv,
                                o2[i][1].x * inv, o2[i][1].y * inv);
        float4 o1 = make_float4(o2[i][2].x * inv, o2[i][2].y * inv,
                                o2[i][3].x * inv, o2[i][3].y * inv);
        *(float4*)&Ap[rowoff + tx * 4] = o0;
        *(float4*)&Ap[rowoff + 64 + tx * 4] = o1;
    }
}

// ---------------------------------------------------------------------------
extern "C" void kernel_launch(void* const* d_in, const int* in_sizes, int n_in,
                              void* d_out, int out_size) {
    const float* x  = (const float*)d_in[0];
    const float* Wq = (const float*)d_in[1];
    const float* Wk = (const float*)d_in[2];
    const float* Wv = (const float*)d_in[3];
    const float* Wo = (const float*)d_in[4];
    float* out = (float*)d_out;

    float *Q, *K, *V, *A;
    unsigned *xs, *as, *ws;
    cudaGetSymbolAddress((void**)&Q, g_Q);
    cudaGetSymbolAddress((void**)&K, g_K);
    cudaGetSymbolAddress((void**)&V, g_V);
    cudaGetSymbolAddress((void**)&A, g_A);
    cudaGetSymbolAddress((void**)&xs, g_xs);
    cudaGetSymbolAddress((void**)&as, g_as);
    cudaGetSymbolAddress((void**)&ws, g_ws);

    rope_tables_kernel<<<(SEQ * 64) / 256, 256>>>();

    const int XP = ROWS * DM / 2;   // pairs in x / A
    const int WP = DM * DM / 2;     // pairs in a weight
    split_kernel<<<XP / 256, 256>>>(x, xs, XP);

    cudaFuncSetAttribute(mgemm_bf3, cudaFuncAttributeMaxDynamicSharedMemorySize,
                         MG_SMEM_BYTES);
    dim3 gg(DM / 128, ROWS / 128);   // (16, 64)

    split_kernel<<<WP / 256, 256>>>(Wq, ws, WP);
    mgemm_bf3<<<gg, 256, MG_SMEM_BYTES>>>(xs, ws, Q);
    split_kernel<<<WP / 256, 256>>>(Wk, ws, WP);
    mgemm_bf3<<<gg, 256, MG_SMEM_BYTES>>>(xs, ws, K);
    split_kernel<<<WP / 256, 256>>>(Wv, ws, WP);
    mgemm_bf3<<<gg, 256, MG_SMEM_BYTES>>>(xs, ws, V);

    rope_apply_kernel<<<(ROWS * (DM / 2)) / 256, 256>>>(Q, K);

    cudaFuncSetAttribute(flash_kernel, cudaFuncAttributeMaxDynamicSharedMemorySize,
                         FA_SMEM_BYTES);
    flash_kernel<<<dim3(SEQ / 64, BATCH * NH), 256, FA_SMEM_BYTES>>>(Q, K, V, A);

    split_kernel<<<XP / 256, 256>>>(A, as, XP);
    split_kernel<<<WP / 256, 256>>>(Wo, ws, WP);
    mgemm_bf3<<<gg, 256, MG_SMEM_BYTES>>>(as, ws, out);
}

// round 4
// speedup vs baseline: 2.3581x; 1.7209x over previous
#include <cuda_runtime.h>
#include <cuda_bf16.h>
#include <math.h>

// ---------------------------------------------------------------------------
// Fused causal MHA forward.
//   GEMMs: bf16x3 (hi/lo split, 3 MMAs) mma.m16n8k16, cp.async double-buffered.
//   Flash attention: bf16x3 tensor-core MMA, fp32 softmax, ldmatrix.trans V.
// ---------------------------------------------------------------------------

#define SEQ   4096
#define BATCH 2
#define DM    2048
#define NH    16
#define DH    128
#define ROWS  (BATCH * SEQ)      // 8192

__device__ float g_Q[ROWS * DM];
__device__ float g_K[ROWS * DM];
__device__ float g_V[ROWS * DM];
__device__ float g_A[ROWS * DM];
__device__ float g_cos[SEQ * 64];
__device__ float g_sin[SEQ * 64];

// GEMM split operands (interleaved hi/lo u32 per d-pair).
__device__ unsigned g_xs[ROWS * DM];
__device__ unsigned g_as[ROWS * DM];
__device__ unsigned g_ws[DM * DM];

// Flash operands: Q/K split (uint2 = hi,lo per d-pair), V split hi & lo planes.
__device__ uint2    g_qs2[ROWS * (DM / 2)];
__device__ uint2    g_ks2[ROWS * (DM / 2)];
__device__ unsigned g_vh[ROWS * (DM / 2)];
__device__ unsigned g_vl[ROWS * (DM / 2)];

__device__ __forceinline__ void mma_bf16(float4& c,
                                         unsigned a0, unsigned a1, unsigned a2, unsigned a3,
                                         unsigned b0, unsigned b1) {
    asm("mma.sync.aligned.m16n8k16.row.col.f32.bf16.bf16.f32 "
        "{%0,%1,%2,%3}, {%4,%5,%6,%7}, {%8,%9}, {%0,%1,%2,%3};"
        : "+f"(c.x), "+f"(c.y), "+f"(c.z), "+f"(c.w)
        : "r"(a0), "r"(a1), "r"(a2), "r"(a3), "r"(b0), "r"(b1));
}

__device__ __forceinline__ unsigned pack_bf16x2(float lo, float hi) {
    unsigned r;
    asm("cvt.rn.bf16x2.f32 %0, %1, %2;" : "=r"(r) : "f"(hi), "f"(lo));
    return r;
}

// ---------------------------------------------------------------------------
// Split fp32 -> (bf16 hi, bf16 lo), pairwise packed, interleaved hi/lo (GEMM fmt).
// ---------------------------------------------------------------------------
__global__ void split_kernel(const float* __restrict__ s, unsigned* __restrict__ d,
                             int npairs) {
    int p = blockIdx.x * blockDim.x + threadIdx.x;
    if (p >= npairs) return;
    float2 v = *(const float2*)&s[2 * p];
    unsigned hi = pack_bf16x2(v.x, v.y);
    float h0 = __uint_as_float(hi << 16);
    float h1 = __uint_as_float(hi & 0xffff0000u);
    unsigned lo = pack_bf16x2(v.x - h0, v.y - h1);
    *(uint2*)&d[2 * p] = make_uint2(hi, lo);
}

// V split into separate hi / lo planes (u32 per pair).
__global__ void vsplit_kernel(const float* __restrict__ s,
                              unsigned* __restrict__ dh, unsigned* __restrict__ dl,
                              int npairs) {
    int p = blockIdx.x * blockDim.x + threadIdx.x;
    if (p >= npairs) return;
    float2 v = *(const float2*)&s[2 * p];
    unsigned hi = pack_bf16x2(v.x, v.y);
    float h0 = __uint_as_float(hi << 16);
    float h1 = __uint_as_float(hi & 0xffff0000u);
    dh[p] = hi;
    dl[p] = pack_bf16x2(v.x - h0, v.y - h1);
}

// ---------------------------------------------------------------------------
// RoPE tables (exact double sincos of the fp32-rounded arg).
// ---------------------------------------------------------------------------
__global__ void rope_tables_kernel() {
    int idx = blockIdx.x * blockDim.x + threadIdx.x;   // [0, 4096*64)
    int s = idx >> 6, i = idx & 63;
    double invd = pow(10000.0, -((double)(2 * i)) / 128.0);
    float arg = (float)s * (float)invd;
    double sv, cv;
    sincos((double)arg, &sv, &cv);
    g_cos[idx] = (float)cv;
    g_sin[idx] = (float)sv;
}

// ---------------------------------------------------------------------------
// RoPE + bf16 hi/lo split, Q absorbs 1/sqrt(DH). Emits flash-format Q/K.
// ---------------------------------------------------------------------------
__global__ void rope_split_kernel(const float* __restrict__ Qf,
                                  const float* __restrict__ Kf,
                                  uint2* __restrict__ qs, uint2* __restrict__ ks) {
    int idx = blockIdx.x * blockDim.x + threadIdx.x;  // [0, ROWS*1024)
    int row = idx >> 10;
    int p = idx & 1023;
    int h = p >> 6, i = p & 63;
    int s = row & (SEQ - 1);
    float c  = g_cos[(s << 6) + i];
    float sn = g_sin[(s << 6) + i];
    size_t off = (size_t)row * DM + h * DH + 2 * i;
    const float SC = 0.08838834764831845f;   // 1/sqrt(128)
    float2 q = *(const float2*)&Qf[off];
    float2 k = *(const float2*)&Kf[off];
    float qx = (q.x * c - q.y * sn) * SC, qy = (q.y * c + q.x * sn) * SC;
    float kx = k.x * c - k.y * sn,        ky = k.y * c + k.x * sn;

    unsigned qhi = pack_bf16x2(qx, qy);
    unsigned qlo = pack_bf16x2(qx - __uint_as_float(qhi << 16),
                               qy - __uint_as_float(qhi & 0xffff0000u));
    qs[idx] = make_uint2(qhi, qlo);
    unsigned khi = pack_bf16x2(kx, ky);
    unsigned klo = pack_bf16x2(kx - __uint_as_float(khi << 16),
                               ky - __uint_as_float(khi & 0xffff0000u));
    ks[idx] = make_uint2(khi, klo);
}

// ---------------------------------------------------------------------------
// GEMM: C[m,n] = sum_k A[m,k]*B[n,k] from pre-split bf16 hi/lo pairs (round-3).
// ---------------------------------------------------------------------------
#define MG_ROWU   40
#define MG_MATU   (128 * MG_ROWU)
#define MG_STAGEU (2 * MG_MATU)
#define MG_SMEM_BYTES (2 * MG_STAGEU * 4)
#define MG_KT     (DM / 32)

__global__ __launch_bounds__(256) void mgemm_bf3(const unsigned* __restrict__ Ag,
                                                 const unsigned* __restrict__ Bg,
                                                 float* __restrict__ C) {
    extern __shared__ unsigned sm[];
    const unsigned sbase = (unsigned)__cvta_generic_to_shared(sm);

    const int tid = threadIdx.x;
    const int wid = tid >> 5, lane = tid & 31;
    const int wm = wid >> 2, wn = wid & 3;
    const int g8 = lane >> 2;
    const int qd = lane & 3;
    const int bx = blockIdx.x, by = blockIdx.y;

    float4 acc[4][4];
#pragma unroll
    for (int i = 0; i < 4; i++)
#pragma unroll
        for (int j = 0; j < 4; j++) acc[i][j] = make_float4(0.f, 0.f, 0.f, 0.f);

    auto load_stage = [&](int s, int k0u) {
#pragma unroll
        for (int t = 0; t < 8; ++t) {
            int c = tid + (t << 8);
            int mat = c >> 10;
            int rem = c & 1023;
            int r = rem >> 3;
            int ch = rem & 7;
            const unsigned* g = (mat ? Bg + (size_t)(bx * 128 + r) * DM
                                     : Ag + (size_t)(by * 128 + r) * DM)
                                + k0u + ch * 4;
            unsigned dst = sbase + (unsigned)(s * MG_STAGEU + mat * MG_MATU
                                              + r * MG_ROWU + ch * 4) * 4u;
            asm volatile("cp.async.cg.shared.global [%0], [%1], 16;"
                         :: "r"(dst), "l"(g));
        }
        asm volatile("cp.async.commit_group;");
    };

    load_stage(0, 0);

    for (int kt = 0; kt < MG_KT; ++kt) {
        if (kt + 1 < MG_KT) {
            load_stage((kt + 1) & 1, (kt + 1) * 32);
            asm volatile("cp.async.wait_group 1;");
        } else {
            asm volatile("cp.async.wait_group 0;");
        }
        __syncthreads();

        const unsigned* Sa = sm + (kt & 1) * MG_STAGEU;
        const unsigned* Sb = Sa + MG_MATU;

#pragma unroll
        for (int ks = 0; ks < 2; ++ks) {
            const int p0 = (ks * 8 + qd) * 2;
            const int p1 = (ks * 8 + qd + 4) * 2;

            uint2 afr[4][4];
#pragma unroll
            for (int mi = 0; mi < 4; ++mi) {
                int row = wm * 64 + mi * 16 + g8;
                afr[mi][0] = *(const uint2*)&Sa[row * MG_ROWU + p0];
                afr[mi][1] = *(const uint2*)&Sa[row * MG_ROWU + p1];
                afr[mi][2] = *(const uint2*)&Sa[(row + 8) * MG_ROWU + p0];
                afr[mi][3] = *(const uint2*)&Sa[(row + 8) * MG_ROWU + p1];
            }
            uint2 bfr[4][2];
#pragma unroll
            for (int ni = 0; ni < 4; ++ni) {
                int col = wn * 32 + ni * 8 + g8;
                bfr[ni][0] = *(const uint2*)&Sb[col * MG_ROWU + p0];
                bfr[ni][1] = *(const uint2*)&Sb[col * MG_ROWU + p1];
            }
#pragma unroll
            for (int mi = 0; mi < 4; ++mi)
#pragma unroll
                for (int ni = 0; ni < 4; ++ni) {
                    mma_bf16(acc[mi][ni],
                             afr[mi][0].x, afr[mi][2].x, afr[mi][1].x, afr[mi][3].x,
                             bfr[ni][0].x, bfr[ni][1].x);
                    mma_bf16(acc[mi][ni],
                             afr[mi][0].x, afr[mi][2].x, afr[mi][1].x, afr[mi][3].x,
                             bfr[ni][0].y, bfr[ni][1].y);
                    mma_bf16(acc[mi][ni],
                             afr[mi][0].y, afr[mi][2].y, afr[mi][1].y, afr[mi][3].y,
                             bfr[ni][0].x, bfr[ni][1].x);
                }
        }
        __syncthreads();
    }

#pragma unroll
    for (int mi = 0; mi < 4; ++mi)
#pragma unroll
        for (int ni = 0; ni < 4; ++ni) {
            int r0 = by * 128 + wm * 64 + mi * 16 + g8;
            int c0 = bx * 128 + wn * 32 + ni * 8 + 2 * qd;
            *(float2*)&C[(size_t)r0 * DM + c0] = make_float2(acc[mi][ni].x, acc[mi][ni].y);
            *(float2*)&C[(size_t)(r0 + 8) * DM + c0] = make_float2(acc[mi][ni].z, acc[mi][ni].w);
        }
}

// ---------------------------------------------------------------------------
// Flash attention, bf16x3 tensor-core. CTA = 64 q-rows x one (b,h); 4 warps,
// each warp owns 16 q-rows x full 64-key tile (no cross-warp softmax).
// smem: Qs/Ks as uint2-interleaved pairs (stride 136 u32, conflict-free
// fragment LDS.64); V hi/lo bf16 row-major with xor-swizzle for ldmatrix.trans.
// ---------------------------------------------------------------------------
#define FL_QS_U   (64 * 136)
#define FL_V_U    (64 * 64)
#define FL_SMEM_U (2 * FL_QS_U + 2 * FL_V_U)
#define FL_SMEM_BYTES (FL_SMEM_U * 4)   // 102,400

__global__ __launch_bounds__(128) void flash_mma(const uint2* __restrict__ qs,
                                                 const uint2* __restrict__ ks,
                                                 const unsigned* __restrict__ vh,
                                                 const unsigned* __restrict__ vl,
                                                 float* __restrict__ Ap) {
    extern __shared__ unsigned su[];
    unsigned* Qs = su;                       // [64][136]
    unsigned* Ks = su + FL_QS_U;             // [64][136]
    const unsigned sb  = (unsigned)__cvta_generic_to_shared(su);
    const unsigned QsB = sb;
    const unsigned KsB = sb + FL_QS_U * 4;
    const unsigned VhB = KsB + FL_QS_U * 4;
    const unsigned VlB = VhB + FL_V_U * 4;

    const int tid = threadIdx.x, lane = tid & 31, w = tid >> 5;
    const int gr = lane >> 2, q4 = lane & 3;
    const int qi = (int)gridDim.x - 1 - (int)blockIdx.x;   // longest first
    const int bh = blockIdx.y;
    const int b = bh >> 4, h = bh & 15;
    const size_t qrow0 = (size_t)(b * SEQ + qi * 64);

    // ---- Q tile: 64 rows x 64 uint2 (512B) = 32 x 16B chunks per row ----
#pragma unroll
    for (int it = 0; it < 16; ++it) {
        int c = tid + it * 128;             // 0..2047
        int r = c >> 5, ch = c & 31;
        const char* src = (const char*)(qs + (qrow0 + r) * 1024 + h * 64) + ch * 16;
        unsigned dst = QsB + (unsigned)(r * 136 + ch * 4) * 4u;
        asm volatile("cp.async.cg.shared.global [%0], [%1], 16;" :: "r"(dst), "l"(src));
    }

    float4 O[16];
#pragma unroll
    for (int j = 0; j < 16; ++j) O[j] = make_float4(0.f, 0.f, 0.f, 0.f);
    float m0 = -INFINITY, m1 = -INFINITY, l0 = 0.f, l1 = 0.f;

    for (int kt = 0; kt <= qi; ++kt) {
        __syncthreads();   // previous iteration's smem reads complete
        const size_t krow0 = (size_t)(b * SEQ + kt * 64);
        // K tile
#pragma unroll
        for (int it = 0; it < 16; ++it) {
            int c = tid + it * 128;
            int r = c >> 5, ch = c & 31;
            const char* src = (const char*)(ks + (krow0 + r) * 1024 + h * 64) + ch * 16;
            unsigned dst = KsB + (unsigned)(r * 136 + ch * 4) * 4u;
            asm volatile("cp.async.cg.shared.global [%0], [%1], 16;" :: "r"(dst), "l"(src));
        }
        // V hi/lo tiles: rows 64 x 64 u32 (16 chunks), xor-swizzled dst
#pragma unroll
        for (int it = 0; it < 8; ++it) {
            int c = tid + it * 128;          // 0..1023
            int s = c >> 4, cb = c & 15;
            unsigned soff = (unsigned)(s * 64 + ((cb ^ (s & 7)) << 2)) * 4u;
            const unsigned* srch = vh + (krow0 + s) * 1024 + h * 64 + cb * 4;
            asm volatile("cp.async.cg.shared.global [%0], [%1], 16;"
                         :: "r"(VhB + soff), "l"(srch));
            const unsigned* srcl = vl + (krow0 + s) * 1024 + h * 64 + cb * 4;
            asm volatile("cp.async.cg.shared.global [%0], [%1], 16;"
                         :: "r"(VlB + soff), "l"(srcl));
        }
        asm volatile("cp.async.commit_group;");
        asm volatile("cp.async.wait_group 0;");
        __syncthreads();

        // ---- S = Q K^T (bf16x3) ----
        float4 s4[8];
#pragma unroll
        for (int nt = 0; nt < 8; ++nt) s4[nt] = make_float4(0.f, 0.f, 0.f, 0.f);

        const int prow = w * 16 + gr;
#pragma unroll
        for (int t = 0; t < 8; ++t) {
            uint2 a0 = *(const uint2*)&Qs[prow * 136 + (8 * t + q4) * 2];
            uint2 a1 = *(const uint2*)&Qs[(prow + 8) * 136 + (8 * t + q4) * 2];
            uint2 a2 = *(const uint2*)&Qs[prow * 136 + (8 * t + q4 + 4) * 2];
            uint2 a3 = *(const uint2*)&Qs[(prow + 8) * 136 + (8 * t + q4 + 4) * 2];
#pragma unroll
            for (int nt = 0; nt < 8; ++nt) {
                int key = nt * 8 + gr;
                uint2 b0 = *(const uint2*)&Ks[key * 136 + (8 * t + q4) * 2];
                uint2 b1 = *(const uint2*)&Ks[key * 136 + (8 * t + q4 + 4) * 2];
                mma_bf16(s4[nt], a0.x, a1.x, a2.x, a3.x, b0.x, b1.x);
                mma_bf16(s4[nt], a0.x, a1.x, a2.x, a3.x, b0.y, b1.y);
                mma_bf16(s4[nt], a0.y, a1.y, a2.y, a3.y, b0.x, b1.x);
            }
        }

        if (kt == qi) {   // causal mask inside diagonal tile (local coords)
            int r0 = w * 16 + gr, r1 = r0 + 8;
#pragma unroll
            for (int nt = 0; nt < 8; ++nt) {
                int c0 = nt * 8 + 2 * q4;
                if (c0 > r0)     s4[nt].x = -INFINITY;
                if (c0 + 1 > r0) s4[nt].y = -INFINITY;
                if (c0 > r1)     s4[nt].z = -INFINITY;
                if (c0 + 1 > r1) s4[nt].w = -INFINITY;
            }
        }

        // ---- online softmax (fp32) ----
        float mx0 = -INFINITY, mx1 = -INFINITY;
#pragma unroll
        for (int nt = 0; nt < 8; ++nt) {
            mx0 = fmaxf(mx0, fmaxf(s4[nt].x, s4[nt].y));
            mx1 = fmaxf(mx1, fmaxf(s4[nt].z, s4[nt].w));
        }
        mx0 = fmaxf(mx0, __shfl_xor_sync(0xffffffffu, mx0, 1));
        mx0 = fmaxf(mx0, __shfl_xor_sync(0xffffffffu, mx0, 2));
        mx1 = fmaxf(mx1, __shfl_xor_sync(0xffffffffu, mx1, 1));
        mx1 = fmaxf(mx1, __shfl_xor_sync(0xffffffffu, mx1, 2));
        float nm0 = fmaxf(m0, mx0), nm1 = fmaxf(m1, mx1);
        float al0 = __expf(m0 - nm0), al1 = __expf(m1 - nm1);
        m0 = nm0; m1 = nm1;

        float sum0 = 0.f, sum1 = 0.f;
#pragma unroll
        for (int nt = 0; nt < 8; ++nt) {
            s4[nt].x = __expf(s4[nt].x - nm0);
            s4[nt].y = __expf(s4[nt].y - nm0);
            s4[nt].z = __expf(s4[nt].z - nm1);
            s4[nt].w = __expf(s4[nt].w - nm1);
            sum0 += s4[nt].x + s4[nt].y;
            sum1 += s4[nt].z + s4[nt].w;
        }
        sum0 += __shfl_xor_sync(0xffffffffu, sum0, 1);
        sum0 += __shfl_xor_sync(0xffffffffu, sum0, 2);
        sum1 += __shfl_xor_sync(0xffffffffu, sum1, 1);
        sum1 += __shfl_xor_sync(0xffffffffu, sum1, 2);
        l0 = l0 * al0 + sum0;
        l1 = l1 * al1 + sum1;
#pragma unroll
        for (int j = 0; j < 16; ++j) {
            O[j].x *= al0; O[j].y *= al0; O[j].z *= al1; O[j].w *= al1;
        }

        // ---- pack P to bf16 hi/lo A-fragments ----
        unsigned phi[16], plo[16];
#pragma unroll
        for (int nt = 0; nt < 8; ++nt) {
            unsigned h01 = pack_bf16x2(s4[nt].x, s4[nt].y);
            unsigned h23 = pack_bf16x2(s4[nt].z, s4[nt].w);
            phi[2 * nt] = h01;
            phi[2 * nt + 1] = h23;
            plo[2 * nt] = pack_bf16x2(s4[nt].x - __uint_as_float(h01 << 16),
                                      s4[nt].y - __uint_as_float(h01 & 0xffff0000u));
            plo[2 * nt + 1] = pack_bf16x2(s4[nt].z - __uint_as_float(h23 << 16),
                                          s4[nt].w - __uint_as_float(h23 & 0xffff0000u));
        }

        // ---- O += P V  (bf16x3; V via ldmatrix.x4.trans) ----
        const int mgrp = lane >> 3, lr = lane & 7;
#pragma unroll
        for (int t2 = 0; t2 < 4; ++t2) {
            unsigned pa0 = phi[4 * t2], pa1 = phi[4 * t2 + 1];
            unsigned pa2 = phi[4 * t2 + 2], pa3 = phi[4 * t2 + 3];
            unsigned pb0 = plo[4 * t2], pb1 = plo[4 * t2 + 1];
            unsigned pb2 = plo[4 * t2 + 2], pb3 = plo[4 * t2 + 3];
#pragma unroll
            for (int nb = 0; nb < 8; ++nb) {
                int s = 16 * t2 + ((mgrp & 1) << 3) + lr;
                int cb = 2 * nb + (mgrp >> 1);
                unsigned off = (unsigned)(s * 64 + ((cb ^ (s & 7)) << 2)) * 4u;
                unsigned h0, h1, h2, h3, v0, v1, v2, v3;
                asm volatile("ldmatrix.sync.aligned.m8n8.x4.trans.shared.b16 "
                             "{%0,%1,%2,%3}, [%4];"
                             : "=r"(h0), "=r"(h1), "=r"(h2), "=r"(h3)
                             : "r"(VhB + off));
                asm volatile("ldmatrix.sync.aligned.m8n8.x4.trans.shared.b16 "
                             "{%0,%1,%2,%3}, [%4];"
                             : "=r"(v0), "=r"(v1), "=r"(v2), "=r"(v3)
                             : "r"(VlB + off));
                mma_bf16(O[2 * nb], pa0, pa1, pa2, pa3, h0, h1);
                mma_bf16(O[2 * nb], pa0, pa1, pa2, pa3, v0, v1);
                mma_bf16(O[2 * nb], pb0, pb1, pb2, pb3, h0, h1);
                mma_bf16(O[2 * nb + 1], pa0, pa1, pa2, pa3, h2, h3);
                mma_bf16(O[2 * nb + 1], pa0, pa1, pa2, pa3, v2, v3);
                mma_bf16(O[2 * nb + 1], pb0, pb1, pb2, pb3, h2, h3);
            }
        }
    }

    // ---- epilogue ----
    float inv0 = 1.0f / l0, inv1 = 1.0f / l1;
    size_t ro0 = (qrow0 + w * 16 + gr) * DM + h * DH;
    size_t ro1 = ro0 + (size_t)8 * DM;
#pragma unroll
    for (int j = 0; j < 16; ++j) {
        int col = j * 8 + 2 * q4;
        *(float2*)&Ap[ro0 + col] = make_float2(O[j].x * inv0, O[j].y * inv0);
        *(float2*)&Ap[ro1 + col] = make_float2(O[j].z * inv1, O[j].w * inv1);
    }
}

// ---------------------------------------------------------------------------
extern "C" void kernel_launch(void* const* d_in, const int* in_sizes, int n_in,
                              void* d_out, int out_size) {
    const float* x  = (const float*)d_in[0];
    const float* Wq = (const float*)d_in[1];
    const float* Wk = (const float*)d_in[2];
    const float* Wv = (const float*)d_in[3];
    const float* Wo = (const float*)d_in[4];
    float* out = (float*)d_out;

    float *Q, *K, *V, *A;
    unsigned *xs, *as, *ws, *vh, *vl;
    uint2 *qs2, *ks2;
    cudaGetSymbolAddress((void**)&Q, g_Q);
    cudaGetSymbolAddress((void**)&K, g_K);
    cudaGetSymbolAddress((void**)&V, g_V);
    cudaGetSymbolAddress((void**)&A, g_A);
    cudaGetSymbolAddress((void**)&xs, g_xs);
    cudaGetSymbolAddress((void**)&as, g_as);
    cudaGetSymbolAddress((void**)&ws, g_ws);
    cudaGetSymbolAddress((void**)&vh, g_vh);
    cudaGetSymbolAddress((void**)&vl, g_vl);
    cudaGetSymbolAddress((void**)&qs2, g_qs2);
    cudaGetSymbolAddress((void**)&ks2, g_ks2);

    rope_tables_kernel<<<(SEQ * 64) / 256, 256>>>();

    const int XP = ROWS * DM / 2;
    const int WP = DM * DM / 2;
    split_kernel<<<XP / 256, 256>>>(x, xs, XP);

    cudaFuncSetAttribute(mgemm_bf3, cudaFuncAttributeMaxDynamicSharedMemorySize,
                         MG_SMEM_BYTES);
    dim3 gg(DM / 128, ROWS / 128);

    split_kernel<<<WP / 256, 256>>>(Wq, ws, WP);
    mgemm_bf3<<<gg, 256, MG_SMEM_BYTES>>>(xs, ws, Q);
    split_kernel<<<WP / 256, 256>>>(Wk, ws, WP);
    mgemm_bf3<<<gg, 256, MG_SMEM_BYTES>>>(xs, ws, K);
    split_kernel<<<WP / 256, 256>>>(Wv, ws, WP);
    mgemm_bf3<<<gg, 256, MG_SMEM_BYTES>>>(xs, ws, V);

    rope_split_kernel<<<(ROWS * 1024) / 256, 256>>>(Q, K, qs2, ks2);
    vsplit_kernel<<<XP / 256, 256>>>(V, vh, vl, XP);

    cudaFuncSetAttribute(flash_mma, cudaFuncAttributeMaxDynamicSharedMemorySize,
                         FL_SMEM_BYTES);
    flash_mma<<<dim3(SEQ / 64, BATCH * NH), 128, FL_SMEM_BYTES>>>(qs2, ks2, vh, vl, A);

    split_kernel<<<XP / 256, 256>>>(A, as, XP);
    split_kernel<<<WP / 256, 256>>>(Wo, ws, WP);
    mgemm_bf3<<<gg, 256, MG_SMEM_BYTES>>>(as, ws, out);
}

// round 6
// speedup vs baseline: 2.4136x; 1.0235x over previous
#include <cuda_runtime.h>
#include <cuda_bf16.h>
#include <math.h>

// ---------------------------------------------------------------------------
// Fused causal MHA forward — all heavy math on mma.sync bf16x3 (~fp32 acc).
//   One QKV mega-GEMM (N=6144) with fused RoPE/split epilogues.
//   Flash attention: round-4 validated mainloop, epilogue writes split A.
//   Final GEMM consumes split A, writes fp32 out.
// ---------------------------------------------------------------------------

#define SEQ   4096
#define BATCH 2
#define DM    2048
#define NH    16
#define DH    128
#define ROWS  (BATCH * SEQ)      // 8192

__device__ float    g_cos[SEQ * 64];
__device__ float    g_sin[SEQ * 64];
__device__ unsigned g_xs[ROWS * DM];        // x split, interleaved hi/lo per pair
__device__ unsigned g_as[ROWS * DM];        // attn-out split, interleaved
__device__ unsigned g_ws[3 * DM * DM];      // Wq|Wk|Wv split rows (Wo reuses [0])
__device__ uint2    g_qs2[ROWS * 1024];     // Q rope+split (hi,lo per d-pair)
__device__ uint2    g_ks2[ROWS * 1024];     // K rope+split
__device__ unsigned g_vh[ROWS * 1024];      // V hi plane
__device__ unsigned g_vl[ROWS * 1024];      // V lo plane

// ---------------------------------------------------------------------------
__device__ __forceinline__ void mma_bf16(float4& c,
                                         unsigned a0, unsigned a1, unsigned a2, unsigned a3,
                                         unsigned b0, unsigned b1) {
    asm("mma.sync.aligned.m16n8k16.row.col.f32.bf16.bf16.f32 "
        "{%0,%1,%2,%3}, {%4,%5,%6,%7}, {%8,%9}, {%0,%1,%2,%3};"
        : "+f"(c.x), "+f"(c.y), "+f"(c.z), "+f"(c.w)
        : "r"(a0), "r"(a1), "r"(a2), "r"(a3), "r"(b0), "r"(b1));
}

__device__ __forceinline__ unsigned pack_bf16x2(float lo, float hi) {
    unsigned r;
    asm("cvt.rn.bf16x2.f32 %0, %1, %2;" : "=r"(r) : "f"(hi), "f"(lo));
    return r;
}

// (hi, lo) bf16x2 split of a float pair.
__device__ __forceinline__ uint2 split2(float x, float y) {
    unsigned hi = pack_bf16x2(x, y);
    unsigned lo = pack_bf16x2(x - __uint_as_float(hi << 16),
                              y - __uint_as_float(hi & 0xffff0000u));
    return make_uint2(hi, lo);
}

// ---------------------------------------------------------------------------
__global__ void rope_tables_kernel() {
    int idx = blockIdx.x * blockDim.x + threadIdx.x;
    int s = idx >> 6, i = idx & 63;
    double invd = pow(10000.0, -((double)(2 * i)) / 128.0);
    float arg = (float)s * (float)invd;
    double sv, cv;
    sincos((double)arg, &sv, &cv);
    g_cos[idx] = (float)cv;
    g_sin[idx] = (float)sv;
}

// fp32 -> interleaved (hi,lo) bf16x2 pairs.
__global__ void split_kernel(const float* __restrict__ s, unsigned* __restrict__ d,
                             int npairs) {
    int p = blockIdx.x * blockDim.x + threadIdx.x;
    if (p >= npairs) return;
    float2 v = *(const float2*)&s[2 * p];
    uint2 t = split2(v.x, v.y);
    *(uint2*)&d[2 * p] = t;
}

// ---------------------------------------------------------------------------
// GEMM C[m,n] = sum_k A[m,k]*B[n,k], bf16x3 from interleaved splits.
// 128x128 CTA tile, 8 warps (2x4), warp 64x32, k32 double-buffered cp.async,
// kt-loop unrolled x2 so all smem offsets are immediates.
// modes: 0 = fp32 C; -1 = derive per bx>>4: 0->Q(rope+scale+split),
//        1->K(rope+split), 2->V(split planes).
// ---------------------------------------------------------------------------
#define MG_ROWU   40
#define MG_MATU   (128 * MG_ROWU)            // 5120 u32
#define MG_STAGEU (2 * MG_MATU)              // 10240 u32
#define MG_SMEM_BYTES (2 * MG_STAGEU * 4)    // 81920
#define MG_KT     (DM / 32)                  // 64

__global__ __launch_bounds__(256, 2) void mgemm_bf3(
        const unsigned* __restrict__ Ag, const unsigned* __restrict__ Bg,
        int modes, float* __restrict__ Cf,
        unsigned* __restrict__ Ph, unsigned* __restrict__ Pl,
        uint2* __restrict__ Pq, uint2* __restrict__ Pk) {
    extern __shared__ unsigned sm[];
    const unsigned sbase = (unsigned)__cvta_generic_to_shared(sm);
    const int tid = threadIdx.x, wid = tid >> 5, lane = tid & 31;
    const int wm = wid >> 2, wn = wid & 3, g8 = lane >> 2, qd = lane & 3;
    const int bx = blockIdx.x, by = blockIdx.y;

    // loader bases (each thread: 4 A-chunks + 4 B-chunks, rows lr+{0,32,64,96})
    const int lr = tid >> 3, lc = (tid & 7) << 2;
    const unsigned* sA = Ag + (size_t)(by * 128 + lr) * DM + lc;
    const unsigned* sB = Bg + (size_t)(bx * 128 + lr) * DM + lc;
    const unsigned dA0 = sbase + (unsigned)(lr * MG_ROWU + lc) * 4u;
    const unsigned dB0 = dA0 + MG_MATU * 4;

    auto load_stage = [&](unsigned bufB, int kt) {
        const unsigned* a = sA + kt * 32;
        const unsigned* b = sB + kt * 32;
#pragma unroll
        for (int l = 0; l < 4; ++l) {
            asm volatile("cp.async.cg.shared.global [%0], [%1], 16;"
                         :: "r"(dA0 + bufB + (unsigned)(l * 5120)),
                            "l"(a + (size_t)l * 32 * DM));
            asm volatile("cp.async.cg.shared.global [%0], [%1], 16;"
                         :: "r"(dB0 + bufB + (unsigned)(l * 5120)),
                            "l"(b + (size_t)l * 32 * DM));
        }
        asm volatile("cp.async.commit_group;");
    };

    float4 acc[4][4];
#pragma unroll
    for (int i = 0; i < 4; i++)
#pragma unroll
        for (int j = 0; j < 4; j++) acc[i][j] = make_float4(0.f, 0.f, 0.f, 0.f);

    // per-warp fragment base pointers (all further offsets are immediates)
    const unsigned* Aw0 = sm + (wm * 64 + g8) * MG_ROWU + qd * 2;
    const unsigned* Bw0 = sm + MG_MATU + (wn * 32 + g8) * MG_ROWU + qd * 2;

    auto compute = [&](const unsigned* Aw, const unsigned* Bw) {
#pragma unroll
        for (int ks = 0; ks < 2; ++ks) {
            uint2 af[4][4];
#pragma unroll
            for (int mi = 0; mi < 4; ++mi) {
                const unsigned* p = Aw + mi * 640 + ks * 16;
                af[mi][0] = *(const uint2*)(p);        // row,   p0
                af[mi][1] = *(const uint2*)(p + 8);    // row,   p1
                af[mi][2] = *(const uint2*)(p + 320);  // row+8, p0
                af[mi][3] = *(const uint2*)(p + 328);  // row+8, p1
            }
            uint2 bf[4][2];
#pragma unroll
            for (int ni = 0; ni < 4; ++ni) {
                const unsigned* p = Bw + ni * 320 + ks * 16;
                bf[ni][0] = *(const uint2*)(p);
                bf[ni][1] = *(const uint2*)(p + 8);
            }
#pragma unroll
            for (int mi = 0; mi < 4; ++mi)
#pragma unroll
                for (int ni = 0; ni < 4; ++ni) {
                    mma_bf16(acc[mi][ni],
                             af[mi][0].x, af[mi][2].x, af[mi][1].x, af[mi][3].x,
                             bf[ni][0].x, bf[ni][1].x);
                    mma_bf16(acc[mi][ni],
                             af[mi][0].x, af[mi][2].x, af[mi][1].x, af[mi][3].x,
                             bf[ni][0].y, bf[ni][1].y);
                    mma_bf16(acc[mi][ni],
                             af[mi][0].y, af[mi][2].y, af[mi][1].y, af[mi][3].y,
                             bf[ni][0].x, bf[ni][1].x);
                }
        }
    };

    const unsigned BUFB = MG_STAGEU * 4;
    load_stage(0, 0);

#pragma unroll 1
    for (int ktb = 0; ktb < MG_KT; ktb += 2) {
        load_stage(BUFB, ktb + 1);
        asm volatile("cp.async.wait_group 1;");
        __syncthreads();
        compute(Aw0, Bw0);
        __syncthreads();
        if (ktb + 2 < MG_KT) {
            load_stage(0, ktb + 2);
            asm volatile("cp.async.wait_group 1;");
        } else {
            asm volatile("cp.async.wait_group 0;");
        }
        __syncthreads();
        compute(Aw0 + MG_STAGEU, Bw0 + MG_STAGEU);
        __syncthreads();
    }

    // ---- epilogue with fused post-ops ----
    int mode, bxl;
    if (modes >= 0) { mode = modes; bxl = bx; }
    else { int r = bx >> 4; mode = (r == 0) ? 2 : (r == 1 ? 3 : 1); bxl = bx & 15; }
    const float SC = 0.08838834764831845f;   // 1/sqrt(128)

#pragma unroll
    for (int mi = 0; mi < 4; ++mi)
#pragma unroll
        for (int ni = 0; ni < 4; ++ni) {
            int r0 = by * 128 + wm * 64 + mi * 16 + g8;
            int c0 = bxl * 128 + wn * 32 + ni * 8 + 2 * qd;
            float4 v = acc[mi][ni];
            if (mode == 0) {
                *(float2*)&Cf[(size_t)r0 * DM + c0] = make_float2(v.x, v.y);
                *(float2*)&Cf[(size_t)(r0 + 8) * DM + c0] = make_float2(v.z, v.w);
            } else if (mode == 1) {        // V: split planes
                int pA = r0 * 1024 + (c0 >> 1);
                uint2 t0 = split2(v.x, v.y);
                Ph[pA] = t0.x; Pl[pA] = t0.y;
                uint2 t1 = split2(v.z, v.w);
                Ph[pA + 8192] = t1.x; Pl[pA + 8192] = t1.y;
            } else {                        // Q/K: rope (+scale) + split
                int i = (c0 & 127) >> 1;
                int s0 = r0 & (SEQ - 1);
                float c_ = g_cos[(s0 << 6) + i], sn = g_sin[(s0 << 6) + i];
                float c1 = g_cos[((s0 + 8) << 6) + i], s1 = g_sin[((s0 + 8) << 6) + i];
                float x0 = v.x * c_ - v.y * sn, y0 = v.y * c_ + v.x * sn;
                float x1 = v.z * c1 - v.w * s1, y1 = v.w * c1 + v.z * s1;
                int pA = r0 * 1024 + (c0 >> 1);
                if (mode == 2) {
                    x0 *= SC; y0 *= SC; x1 *= SC; y1 *= SC;
                    Pq[pA] = split2(x0, y0);
                    Pq[pA + 8192] = split2(x1, y1);
                } else {
                    Pk[pA] = split2(x0, y0);
                    Pk[pA + 8192] = split2(x1, y1);
                }
            }
        }
}

// ---------------------------------------------------------------------------
// Flash attention, bf16x3 mma.sync (round-4 mainloop). Epilogue writes the
// attention output pre-split (interleaved hi/lo) for the final GEMM.
// ---------------------------------------------------------------------------
#define FL_QS_U   (64 * 136)
#define FL_V_U    (64 * 64)
#define FL_SMEM_U (2 * FL_QS_U + 2 * FL_V_U)
#define FL_SMEM_BYTES (FL_SMEM_U * 4)

__global__ __launch_bounds__(128) void flash_mma(const uint2* __restrict__ qs,
                                                 const uint2* __restrict__ ks,
                                                 const unsigned* __restrict__ vh,
                                                 const unsigned* __restrict__ vl,
                                                 uint2* __restrict__ As2) {
    extern __shared__ unsigned su[];
    unsigned* Qs = su;
    unsigned* Ks = su + FL_QS_U;
    const unsigned sb  = (unsigned)__cvta_generic_to_shared(su);
    const unsigned QsB = sb;
    const unsigned KsB = sb + FL_QS_U * 4;
    const unsigned VhB = KsB + FL_QS_U * 4;
    const unsigned VlB = VhB + FL_V_U * 4;

    const int tid = threadIdx.x, lane = tid & 31, w = tid >> 5;
    const int gr = lane >> 2, q4 = lane & 3;
    const int qi = (int)gridDim.x - 1 - (int)blockIdx.x;
    const int bh = blockIdx.y;
    const int b = bh >> 4, h = bh & 15;
    const size_t qrow0 = (size_t)(b * SEQ + qi * 64);

#pragma unroll
    for (int it = 0; it < 16; ++it) {
        int c = tid + it * 128;
        int r = c >> 5, ch = c & 31;
        const char* src = (const char*)(qs + (qrow0 + r) * 1024 + h * 64) + ch * 16;
        unsigned dst = QsB + (unsigned)(r * 136 + ch * 4) * 4u;
        asm volatile("cp.async.cg.shared.global [%0], [%1], 16;" :: "r"(dst), "l"(src));
    }

    float4 O[16];
#pragma unroll
    for (int j = 0; j < 16; ++j) O[j] = make_float4(0.f, 0.f, 0.f, 0.f);
    float m0 = -INFINITY, m1 = -INFINITY, l0 = 0.f, l1 = 0.f;

    for (int kt = 0; kt <= qi; ++kt) {
        __syncthreads();
        const size_t krow0 = (size_t)(b * SEQ + kt * 64);
#pragma unroll
        for (int it = 0; it < 16; ++it) {
            int c = tid + it * 128;
            int r = c >> 5, ch = c & 31;
            const char* src = (const char*)(ks + (krow0 + r) * 1024 + h * 64) + ch * 16;
            unsigned dst = KsB + (unsigned)(r * 136 + ch * 4) * 4u;
            asm volatile("cp.async.cg.shared.global [%0], [%1], 16;" :: "r"(dst), "l"(src));
        }
#pragma unroll
        for (int it = 0; it < 8; ++it) {
            int c = tid + it * 128;
            int s = c >> 4, cb = c & 15;
            unsigned soff = (unsigned)(s * 64 + ((cb ^ (s & 7)) << 2)) * 4u;
            const unsigned* srch = vh + (krow0 + s) * 1024 + h * 64 + cb * 4;
            asm volatile("cp.async.cg.shared.global [%0], [%1], 16;"
                         :: "r"(VhB + soff), "l"(srch));
            const unsigned* srcl = vl + (krow0 + s) * 1024 + h * 64 + cb * 4;
            asm volatile("cp.async.cg.shared.global [%0], [%1], 16;"
                         :: "r"(VlB + soff), "l"(srcl));
        }
        asm volatile("cp.async.commit_group;");
        asm volatile("cp.async.wait_group 0;");
        __syncthreads();

        float4 s4[8];
#pragma unroll
        for (int nt = 0; nt < 8; ++nt) s4[nt] = make_float4(0.f, 0.f, 0.f, 0.f);

        const int prow = w * 16 + gr;
#pragma unroll
        for (int t = 0; t < 8; ++t) {
            uint2 a0 = *(const uint2*)&Qs[prow * 136 + (8 * t + q4) * 2];
            uint2 a1 = *(const uint2*)&Qs[(prow + 8) * 136 + (8 * t + q4) * 2];
            uint2 a2 = *(const uint2*)&Qs[prow * 136 + (8 * t + q4 + 4) * 2];
            uint2 a3 = *(const uint2*)&Qs[(prow + 8) * 136 + (8 * t + q4 + 4) * 2];
#pragma unroll
            for (int nt = 0; nt < 8; ++nt) {
                int key = nt * 8 + gr;
                uint2 b0 = *(const uint2*)&Ks[key * 136 + (8 * t + q4) * 2];
                uint2 b1 = *(const uint2*)&Ks[key * 136 + (8 * t + q4 + 4) * 2];
                mma_bf16(s4[nt], a0.x, a1.x, a2.x, a3.x, b0.x, b1.x);
                mma_bf16(s4[nt], a0.x, a1.x, a2.x, a3.x, b0.y, b1.y);
                mma_bf16(s4[nt], a0.y, a1.y, a2.y, a3.y, b0.x, b1.x);
            }
        }

        if (kt == qi) {
            int r0 = w * 16 + gr, r1 = r0 + 8;
#pragma unroll
            for (int nt = 0; nt < 8; ++nt) {
                int c0 = nt * 8 + 2 * q4;
                if (c0 > r0)     s4[nt].x = -INFINITY;
                if (c0 + 1 > r0) s4[nt].y = -INFINITY;
                if (c0 > r1)     s4[nt].z = -INFINITY;
                if (c0 + 1 > r1) s4[nt].w = -INFINITY;
            }
        }

        float mx0 = -INFINITY, mx1 = -INFINITY;
#pragma unroll
        for (int nt = 0; nt < 8; ++nt) {
            mx0 = fmaxf(mx0, fmaxf(s4[nt].x, s4[nt].y));
            mx1 = fmaxf(mx1, fmaxf(s4[nt].z, s4[nt].w));
        }
        mx0 = fmaxf(mx0, __shfl_xor_sync(0xffffffffu, mx0, 1));
        mx0 = fmaxf(mx0, __shfl_xor_sync(0xffffffffu, mx0, 2));
        mx1 = fmaxf(mx1, __shfl_xor_sync(0xffffffffu, mx1, 1));
        mx1 = fmaxf(mx1, __shfl_xor_sync(0xffffffffu, mx1, 2));
        float nm0 = fmaxf(m0, mx0), nm1 = fmaxf(m1, mx1);
        float al0 = __expf(m0 - nm0), al1 = __expf(m1 - nm1);
        m0 = nm0; m1 = nm1;

        float sum0 = 0.f, sum1 = 0.f;
#pragma unroll
        for (int nt = 0; nt < 8; ++nt) {
            s4[nt].x = __expf(s4[nt].x - nm0);
            s4[nt].y = __expf(s4[nt].y - nm0);
            s4[nt].z = __expf(s4[nt].z - nm1);
            s4[nt].w = __expf(s4[nt].w - nm1);
            sum0 += s4[nt].x + s4[nt].y;
            sum1 += s4[nt].z + s4[nt].w;
        }
        sum0 += __shfl_xor_sync(0xffffffffu, sum0, 1);
        sum0 += __shfl_xor_sync(0xffffffffu, sum0, 2);
        sum1 += __shfl_xor_sync(0xffffffffu, sum1, 1);
        sum1 += __shfl_xor_sync(0xffffffffu, sum1, 2);
        l0 = l0 * al0 + sum0;
        l1 = l1 * al1 + sum1;
#pragma unroll
        for (int j = 0; j < 16; ++j) {
            O[j].x *= al0; O[j].y *= al0; O[j].z *= al1; O[j].w *= al1;
        }

        unsigned phi[16], plo[16];
#pragma unroll
        for (int nt = 0; nt < 8; ++nt) {
            uint2 t01 = split2(s4[nt].x, s4[nt].y);
            uint2 t23 = split2(s4[nt].z, s4[nt].w);
            phi[2 * nt] = t01.x;  plo[2 * nt] = t01.y;
            phi[2 * nt + 1] = t23.x;  plo[2 * nt + 1] = t23.y;
        }

        const int mgrp = lane >> 3, lr2 = lane & 7;
#pragma unroll
        for (int t2 = 0; t2 < 4; ++t2) {
            unsigned pa0 = phi[4 * t2], pa1 = phi[4 * t2 + 1];
            unsigned pa2 = phi[4 * t2 + 2], pa3 = phi[4 * t2 + 3];
            unsigned pb0 = plo[4 * t2], pb1 = plo[4 * t2 + 1];
            unsigned pb2 = plo[4 * t2 + 2], pb3 = plo[4 * t2 + 3];
#pragma unroll
            for (int nb = 0; nb < 8; ++nb) {
                int s = 16 * t2 + ((mgrp & 1) << 3) + lr2;
                int cb = 2 * nb + (mgrp >> 1);
                unsigned off = (unsigned)(s * 64 + ((cb ^ (s & 7)) << 2)) * 4u;
                unsigned h0, h1, h2, h3, v0, v1, v2, v3;
                asm volatile("ldmatrix.sync.aligned.m8n8.x4.trans.shared.b16 "
                             "{%0,%1,%2,%3}, [%4];"
                             : "=r"(h0), "=r"(h1), "=r"(h2), "=r"(h3)
                             : "r"(VhB + off));
                asm volatile("ldmatrix.sync.aligned.m8n8.x4.trans.shared.b16 "
                             "{%0,%1,%2,%3}, [%4];"
                             : "=r"(v0), "=r"(v1), "=r"(v2), "=r"(v3)
                             : "r"(VlB + off));
                mma_bf16(O[2 * nb], pa0, pa1, pa2, pa3, h0, h1);
                mma_bf16(O[2 * nb], pa0, pa1, pa2, pa3, v0, v1);
                mma_bf16(O[2 * nb], pb0, pb1, pb2, pb3, h0, h1);
                mma_bf16(O[2 * nb + 1], pa0, pa1, pa2, pa3, h2, h3);
                mma_bf16(O[2 * nb + 1], pa0, pa1, pa2, pa3, v2, v3);
                mma_bf16(O[2 * nb + 1], pb0, pb1, pb2, pb3, h2, h3);
            }
        }
    }

    // epilogue: normalize + bf16 hi/lo split, interleaved pairs for next GEMM
    float inv0 = 1.0f / l0, inv1 = 1.0f / l1;
    size_t p0 = (qrow0 + w * 16 + gr) * 1024 + h * 64;
    size_t p1 = p0 + (size_t)8 * 1024;
#pragma unroll
    for (int j = 0; j < 16; ++j) {
        int pc = j * 4 + q4;
        As2[p0 + pc] = split2(O[j].x * inv0, O[j].y * inv0);
        As2[p1 + pc] = split2(O[j].z * inv1, O[j].w * inv1);
    }
}

// ---------------------------------------------------------------------------
extern "C" void kernel_launch(void* const* d_in, const int* in_sizes, int n_in,
                              void* d_out, int out_size) {
    const float* x  = (const float*)d_in[0];
    const float* Wq = (const float*)d_in[1];
    const float* Wk = (const float*)d_in[2];
    const float* Wv = (const float*)d_in[3];
    const float* Wo = (const float*)d_in[4];
    float* out = (float*)d_out;

    unsigned *xs, *as, *ws, *vh, *vl;
    uint2 *qs2, *ks2;
    cudaGetSymbolAddress((void**)&xs, g_xs);
    cudaGetSymbolAddress((void**)&as, g_as);
    cudaGetSymbolAddress((void**)&ws, g_ws);
    cudaGetSymbolAddress((void**)&vh, g_vh);
    cudaGetSymbolAddress((void**)&vl, g_vl);
    cudaGetSymbolAddress((void**)&qs2, g_qs2);
    cudaGetSymbolAddress((void**)&ks2, g_ks2);

    rope_tables_kernel<<<(SEQ * 64) / 256, 256>>>();

    const int XP = ROWS * DM / 2;   // pairs in x / A
    const int WP = DM * DM / 2;     // pairs per weight
    split_kernel<<<XP / 256, 256>>>(x, xs, XP);
    split_kernel<<<WP / 256, 256>>>(Wq, ws, WP);
    split_kernel<<<WP / 256, 256>>>(Wk, ws + DM * DM, WP);
    split_kernel<<<WP / 256, 256>>>(Wv, ws + 2 * DM * DM, WP);

    cudaFuncSetAttribute(mgemm_bf3, cudaFuncAttributeMaxDynamicSharedMemorySize,
                         MG_SMEM_BYTES);
    // QKV mega-GEMM: bx 0-15 -> Q (rope+scale+split), 16-31 -> K (rope+split),
    // 32-47 -> V (split planes)
    mgemm_bf3<<<dim3(48, 64), 256, MG_SMEM_BYTES>>>(xs, ws, -1, nullptr,
                                                    vh, vl, qs2, ks2);

    cudaFuncSetAttribute(flash_mma, cudaFuncAttributeMaxDynamicSharedMemorySize,
                         FL_SMEM_BYTES);
    flash_mma<<<dim3(SEQ / 64, BATCH * NH), 128, FL_SMEM_BYTES>>>(
        qs2, ks2, vh, vl, (uint2*)as);

    // Wo split reuses ws[0] region (stream-ordered after QKV GEMM)
    split_kernel<<<WP / 256, 256>>>(Wo, ws, WP);
    mgemm_bf3<<<dim3(16, 64), 256, MG_SMEM_BYTES>>>(as, ws, 0, out,
                                                    nullptr, nullptr, nullptr, nullptr);
}

// round 7
// speedup vs baseline: 3.1365x; 1.2995x over previous
#include <cuda_runtime.h>
#include <cuda_fp16.h>
#include <cuda_bf16.h>
#include <math.h>

// ---------------------------------------------------------------------------
// Fused causal MHA forward — mma.sync fp16x2 GEMMs (A split hi/lo, B plain),
// flash attention with fp16 QK (Q split, K plain) + bf16x3 PV.
// ---------------------------------------------------------------------------

#define SEQ   4096
#define BATCH 2
#define DM    2048
#define NH    16
#define DH    128
#define ROWS  (BATCH * SEQ)      // 8192
#define WU    (DM * DM / 2)      // u32 per packed weight plane

__device__ float    g_cos[SEQ * 64];
__device__ float    g_sin[SEQ * 64];
__device__ unsigned g_xs[ROWS * DM];        // x: fp16 split, interleaved (hi,lo)/pair
__device__ unsigned g_as[ROWS * DM];        // attn out: fp16 split interleaved
__device__ unsigned g_ws[3 * WU];           // Wq|Wk|Wv plain fp16 (Wo reuses [0])
__device__ uint2    g_qs2[ROWS * 1024];     // Q rope+fp16 split (hi,lo per pair)
__device__ unsigned g_ks1[ROWS * 1024];     // K rope, plain fp16
__device__ unsigned g_vh[ROWS * 1024];      // V bf16 hi plane
__device__ unsigned g_vl[ROWS * 1024];      // V bf16 lo plane

// ---------------------------------------------------------------------------
__device__ __forceinline__ void mma_f16(float4& c,
                                        unsigned a0, unsigned a1, unsigned a2, unsigned a3,
                                        unsigned b0, unsigned b1) {
    asm("mma.sync.aligned.m16n8k16.row.col.f32.f16.f16.f32 "
        "{%0,%1,%2,%3}, {%4,%5,%6,%7}, {%8,%9}, {%0,%1,%2,%3};"
        : "+f"(c.x), "+f"(c.y), "+f"(c.z), "+f"(c.w)
        : "r"(a0), "r"(a1), "r"(a2), "r"(a3), "r"(b0), "r"(b1));
}

__device__ __forceinline__ void mma_bf16(float4& c,
                                         unsigned a0, unsigned a1, unsigned a2, unsigned a3,
                                         unsigned b0, unsigned b1) {
    asm("mma.sync.aligned.m16n8k16.row.col.f32.bf16.bf16.f32 "
        "{%0,%1,%2,%3}, {%4,%5,%6,%7}, {%8,%9}, {%0,%1,%2,%3};"
        : "+f"(c.x), "+f"(c.y), "+f"(c.z), "+f"(c.w)
        : "r"(a0), "r"(a1), "r"(a2), "r"(a3), "r"(b0), "r"(b1));
}

__device__ __forceinline__ unsigned pack_bf16x2(float lo, float hi) {
    unsigned r;
    asm("cvt.rn.bf16x2.f32 %0, %1, %2;" : "=r"(r) : "f"(hi), "f"(lo));
    return r;
}
__device__ __forceinline__ uint2 split2_bf(float x, float y) {
    unsigned hi = pack_bf16x2(x, y);
    unsigned lo = pack_bf16x2(x - __uint_as_float(hi << 16),
                              y - __uint_as_float(hi & 0xffff0000u));
    return make_uint2(hi, lo);
}
__device__ __forceinline__ unsigned pack_f16x2(float x, float y) {
    __half2 h = __floats2half2_rn(x, y);
    return *(unsigned*)&h;
}
__device__ __forceinline__ uint2 split2_h(float x, float y) {
    __half2 h = __floats2half2_rn(x, y);
    float2 f = __half22float2(h);
    __half2 l = __floats2half2_rn(x - f.x, y - f.y);
    return make_uint2(*(unsigned*)&h, *(unsigned*)&l);
}

// ---------------------------------------------------------------------------
__global__ void rope_tables_kernel() {
    int idx = blockIdx.x * blockDim.x + threadIdx.x;
    int s = idx >> 6, i = idx & 63;
    double invd = pow(10000.0, -((double)(2 * i)) / 128.0);
    float arg = (float)s * (float)invd;
    double sv, cv;
    sincos((double)arg, &sv, &cv);
    g_cos[idx] = (float)cv;
    g_sin[idx] = (float)sv;
}

// fp32 -> interleaved fp16 (hi,lo) pairs (GEMM A-side format).
__global__ void splith_kernel(const float* __restrict__ s, unsigned* __restrict__ d,
                              int npairs) {
    int p = blockIdx.x * blockDim.x + threadIdx.x;
    if (p >= npairs) return;
    float2 v = *(const float2*)&s[2 * p];
    *(uint2*)&d[2 * p] = split2_h(v.x, v.y);
}

// fp32 -> plain fp16 plane (GEMM B-side / weights).
__global__ void wpack_kernel(const float* __restrict__ s, unsigned* __restrict__ d,
                             int npairs) {
    int p = blockIdx.x * blockDim.x + threadIdx.x;
    if (p >= npairs) return;
    float2 v = *(const float2*)&s[2 * p];
    d[p] = pack_f16x2(v.x, v.y);
}

// ---------------------------------------------------------------------------
// GEMM C[m,n] = sum_k A[m,k]*B[n,k]. A: fp16 split interleaved; B: plain fp16.
// 128x128 CTA tile, 8 warps (2x4), warp 64x32, k32 double-buffered cp.async,
// 2 MMAs per tile per k16 (Ah*B + Al*B).
// modes: 0 = fp32 C; -1 = per bx>>4: 0->Q(rope+scale+fp16split),
//        1->K(rope+plain fp16), 2->V(bf16 split planes).
// ---------------------------------------------------------------------------
#define MG_A_U    5120                        // 128 rows x 40 u32 (32 data + 8 pad)
#define MG_B_U    2560                        // 128 rows x 20 u32 (16 data + 4 pad)
#define MG_STAGEU (MG_A_U + MG_B_U)           // 7680 u32
#define MG_SMEM_BYTES (2 * MG_STAGEU * 4)     // 61440
#define MG_KT     (DM / 32)                   // 64

__global__ __launch_bounds__(256, 2) void mgemm_h2(
        const unsigned* __restrict__ Ag, const unsigned* __restrict__ Bg,
        int modes, float* __restrict__ Cf,
        unsigned* __restrict__ Ph, unsigned* __restrict__ Pl,
        uint2* __restrict__ Pq, unsigned* __restrict__ Pk) {
    extern __shared__ unsigned sm[];
    const unsigned sbase = (unsigned)__cvta_generic_to_shared(sm);
    const int tid = threadIdx.x, wid = tid >> 5, lane = tid & 31;
    const int wm = wid >> 2, wn = wid & 3, g8 = lane >> 2, qd = lane & 3;
    const int bx = blockIdx.x, by = blockIdx.y;

    // A loader: 1024 chunks (128 rows x 8), rows lr+{0,32,64,96}
    const int lr = tid >> 3, lc = (tid & 7) << 2;
    const unsigned* sA = Ag + (size_t)(by * 128 + lr) * DM + lc;
    const unsigned dA0 = sbase + (unsigned)(lr * 40 + lc) * 4u;
    // B loader: 512 chunks (128 rows x 4)
    const int br0 = tid >> 2, bc0 = (tid & 3) << 2;
    const unsigned* sB0 = Bg + (size_t)(bx * 128 + br0) * (DM / 2) + bc0;
    const unsigned dB0 = sbase + (unsigned)(MG_A_U + br0 * 20 + bc0) * 4u;

    auto load_stage = [&](unsigned bufB, int kt) {
        const unsigned* a = sA + kt * 32;
#pragma unroll
        for (int l = 0; l < 4; ++l)
            asm volatile("cp.async.cg.shared.global [%0], [%1], 16;"
                         :: "r"(dA0 + bufB + (unsigned)(l * 5120)),
                            "l"(a + (size_t)l * 32 * DM));
        const unsigned* b = sB0 + kt * 16;
#pragma unroll
        for (int l = 0; l < 2; ++l)
            asm volatile("cp.async.cg.shared.global [%0], [%1], 16;"
                         :: "r"(dB0 + bufB + (unsigned)(l * 5120)),
                            "l"(b + (size_t)l * 64 * (DM / 2)));
        asm volatile("cp.async.commit_group;");
    };

    float4 acc[4][4];
#pragma unroll
    for (int i = 0; i < 4; i++)
#pragma unroll
        for (int j = 0; j < 4; j++) acc[i][j] = make_float4(0.f, 0.f, 0.f, 0.f);

    const unsigned* Aw0 = sm + (wm * 64 + g8) * 40 + qd * 2;
    const unsigned* Bw0 = sm + MG_A_U + (wn * 32 + g8) * 20 + qd;

    auto compute = [&](const unsigned* Aw, const unsigned* Bw) {
#pragma unroll
        for (int ks = 0; ks < 2; ++ks) {
            uint2 af[4][4];
#pragma unroll
            for (int mi = 0; mi < 4; ++mi) {
                const unsigned* p = Aw + mi * 640 + ks * 16;
                af[mi][0] = *(const uint2*)(p);        // row,   k[0:8)
                af[mi][1] = *(const uint2*)(p + 8);    // row,   k[8:16)
                af[mi][2] = *(const uint2*)(p + 320);  // row+8, k[0:8)
                af[mi][3] = *(const uint2*)(p + 328);  // row+8, k[8:16)
            }
            unsigned b0[4], b1[4];
#pragma unroll
            for (int ni = 0; ni < 4; ++ni) {
                const unsigned* q = Bw + ni * 160 + ks * 8;
                b0[ni] = q[0];
                b1[ni] = q[4];
            }
#pragma unroll
            for (int mi = 0; mi < 4; ++mi)
#pragma unroll
                for (int ni = 0; ni < 4; ++ni) {
                    mma_f16(acc[mi][ni],
                            af[mi][0].x, af[mi][2].x, af[mi][1].x, af[mi][3].x,
                            b0[ni], b1[ni]);
                    mma_f16(acc[mi][ni],
                            af[mi][0].y, af[mi][2].y, af[mi][1].y, af[mi][3].y,
                            b0[ni], b1[ni]);
                }
        }
    };

    const unsigned BUFB = MG_STAGEU * 4;
    load_stage(0, 0);

#pragma unroll 1
    for (int ktb = 0; ktb < MG_KT; ktb += 2) {
        load_stage(BUFB, ktb + 1);
        asm volatile("cp.async.wait_group 1;");
        __syncthreads();
        compute(Aw0, Bw0);
        __syncthreads();
        if (ktb + 2 < MG_KT) {
            load_stage(0, ktb + 2);
            asm volatile("cp.async.wait_group 1;");
        } else {
            asm volatile("cp.async.wait_group 0;");
        }
        __syncthreads();
        compute(Aw0 + MG_STAGEU, Bw0 + MG_STAGEU);
        __syncthreads();
    }

    // ---- epilogue with fused post-ops ----
    int mode, bxl;
    if (modes >= 0) { mode = modes; bxl = bx; }
    else { int r = bx >> 4; mode = (r == 0) ? 2 : (r == 1 ? 3 : 1); bxl = bx & 15; }
    const float SC = 0.08838834764831845f;   // 1/sqrt(128)

#pragma unroll
    for (int mi = 0; mi < 4; ++mi)
#pragma unroll
        for (int ni = 0; ni < 4; ++ni) {
            int r0 = by * 128 + wm * 64 + mi * 16 + g8;
            int c0 = bxl * 128 + wn * 32 + ni * 8 + 2 * qd;
            float4 v = acc[mi][ni];
            if (mode == 0) {
                *(float2*)&Cf[(size_t)r0 * DM + c0] = make_float2(v.x, v.y);
                *(float2*)&Cf[(size_t)(r0 + 8) * DM + c0] = make_float2(v.z, v.w);
            } else if (mode == 1) {        // V: bf16 split planes
                int pA = r0 * 1024 + (c0 >> 1);
                uint2 t0 = split2_bf(v.x, v.y);
                Ph[pA] = t0.x; Pl[pA] = t0.y;
                uint2 t1 = split2_bf(v.z, v.w);
                Ph[pA + 8192] = t1.x; Pl[pA + 8192] = t1.y;
            } else {                        // Q/K: rope (+scale)
                int i = (c0 & 127) >> 1;
                int s0 = r0 & (SEQ - 1);
                float c_ = g_cos[(s0 << 6) + i], sn = g_sin[(s0 << 6) + i];
                float c1 = g_cos[((s0 + 8) << 6) + i], s1 = g_sin[((s0 + 8) << 6) + i];
                float x0 = v.x * c_ - v.y * sn, y0 = v.y * c_ + v.x * sn;
                float x1 = v.z * c1 - v.w * s1, y1 = v.w * c1 + v.z * s1;
                int pA = r0 * 1024 + (c0 >> 1);
                if (mode == 2) {            // Q: fp16 split, scaled
                    x0 *= SC; y0 *= SC; x1 *= SC; y1 *= SC;
                    Pq[pA] = split2_h(x0, y0);
                    Pq[pA + 8192] = split2_h(x1, y1);
                } else {                    // K: plain fp16
                    Pk[pA] = pack_f16x2(x0, y0);
                    Pk[pA + 8192] = pack_f16x2(x1, y1);
                }
            }
        }
}

// ---------------------------------------------------------------------------
// Flash attention: fp16 QK (Q split 2 MMAs, K plain), bf16x3 PV (validated).
// Q smem 64x136 u32 (uint2 pairs); K plane 64x68 u32; V bf16 planes 64x64.
// ---------------------------------------------------------------------------
#define FL_Q_U   (64 * 136)
#define FL_K_U   (64 * 68)
#define FL_V_U   (64 * 64)
#define FL_SMEM_U (FL_Q_U + FL_K_U + 2 * FL_V_U)
#define FL_SMEM_BYTES (FL_SMEM_U * 4)    // 84992

__global__ __launch_bounds__(128) void flash_mma(const uint2* __restrict__ qs,
                                                 const unsigned* __restrict__ ks1,
                                                 const unsigned* __restrict__ vh,
                                                 const unsigned* __restrict__ vl,
                                                 uint2* __restrict__ As2) {
    extern __shared__ unsigned su[];
    unsigned* Qs = su;                       // [64][136]
    unsigned* Ks = su + FL_Q_U;              // [64][68]
    const unsigned sb  = (unsigned)__cvta_generic_to_shared(su);
    const unsigned QsB = sb;
    const unsigned KsB = sb + FL_Q_U * 4;
    const unsigned VhB = KsB + FL_K_U * 4;
    const unsigned VlB = VhB + FL_V_U * 4;

    const int tid = threadIdx.x, lane = tid & 31, w = tid >> 5;
    const int gr = lane >> 2, q4 = lane & 3;
    const int qi = (int)gridDim.x - 1 - (int)blockIdx.x;
    const int bh = blockIdx.y;
    const int b = bh >> 4, h = bh & 15;
    const size_t qrow0 = (size_t)(b * SEQ + qi * 64);

    // Q tile: 2048 chunks
#pragma unroll
    for (int it = 0; it < 16; ++it) {
        int c = tid + it * 128;
        int r = c >> 5, ch = c & 31;
        const char* src = (const char*)(qs + (qrow0 + r) * 1024 + h * 64) + ch * 16;
        unsigned dst = QsB + (unsigned)(r * 136 + ch * 4) * 4u;
        asm volatile("cp.async.cg.shared.global [%0], [%1], 16;" :: "r"(dst), "l"(src));
    }

    float4 O[16];
#pragma unroll
    for (int j = 0; j < 16; ++j) O[j] = make_float4(0.f, 0.f, 0.f, 0.f);
    float m0 = -INFINITY, m1 = -INFINITY, l0 = 0.f, l1 = 0.f;

    for (int kt = 0; kt <= qi; ++kt) {
        __syncthreads();
        const size_t krow0 = (size_t)(b * SEQ + kt * 64);
        // K plane: 1024 chunks
#pragma unroll
        for (int it = 0; it < 8; ++it) {
            int c = tid + it * 128;
            int r = c >> 4, ch = c & 15;
            const unsigned* src = ks1 + (krow0 + r) * 1024 + h * 64 + ch * 4;
            unsigned dst = KsB + (unsigned)(r * 68 + ch * 4) * 4u;
            asm volatile("cp.async.cg.shared.global [%0], [%1], 16;" :: "r"(dst), "l"(src));
        }
        // V hi/lo planes, xor-swizzled
#pragma unroll
        for (int it = 0; it < 8; ++it) {
            int c = tid + it * 128;
            int s = c >> 4, cb = c & 15;
            unsigned soff = (unsigned)(s * 64 + ((cb ^ (s & 7)) << 2)) * 4u;
            const unsigned* srch = vh + (krow0 + s) * 1024 + h * 64 + cb * 4;
            asm volatile("cp.async.cg.shared.global [%0], [%1], 16;"
                         :: "r"(VhB + soff), "l"(srch));
            const unsigned* srcl = vl + (krow0 + s) * 1024 + h * 64 + cb * 4;
            asm volatile("cp.async.cg.shared.global [%0], [%1], 16;"
                         :: "r"(VlB + soff), "l"(srcl));
        }
        asm volatile("cp.async.commit_group;");
        asm volatile("cp.async.wait_group 0;");
        __syncthreads();

        // ---- S = Q K^T (fp16: Qhi*K + Qlo*K) ----
        float4 s4[8];
#pragma unroll
        for (int nt = 0; nt < 8; ++nt) s4[nt] = make_float4(0.f, 0.f, 0.f, 0.f);

        const int prow = w * 16 + gr;
#pragma unroll
        for (int t = 0; t < 8; ++t) {
            uint2 a0 = *(const uint2*)&Qs[prow * 136 + (8 * t + q4) * 2];
            uint2 a1 = *(const uint2*)&Qs[(prow + 8) * 136 + (8 * t + q4) * 2];
            uint2 a2 = *(const uint2*)&Qs[prow * 136 + (8 * t + q4 + 4) * 2];
            uint2 a3 = *(const uint2*)&Qs[(prow + 8) * 136 + (8 * t + q4 + 4) * 2];
#pragma unroll
            for (int nt = 0; nt < 8; ++nt) {
                int key = nt * 8 + gr;
                unsigned b0 = Ks[key * 68 + 8 * t + q4];
                unsigned b1 = Ks[key * 68 + 8 * t + q4 + 4];
                mma_f16(s4[nt], a0.x, a1.x, a2.x, a3.x, b0, b1);
                mma_f16(s4[nt], a0.y, a1.y, a2.y, a3.y, b0, b1);
            }
        }

        if (kt == qi) {
            int r0 = w * 16 + gr, r1 = r0 + 8;
#pragma unroll
            for (int nt = 0; nt < 8; ++nt) {
                int c0 = nt * 8 + 2 * q4;
                if (c0 > r0)     s4[nt].x = -INFINITY;
                if (c0 + 1 > r0) s4[nt].y = -INFINITY;
                if (c0 > r1)     s4[nt].z = -INFINITY;
                if (c0 + 1 > r1) s4[nt].w = -INFINITY;
            }
        }

        float mx0 = -INFINITY, mx1 = -INFINITY;
#pragma unroll
        for (int nt = 0; nt < 8; ++nt) {
            mx0 = fmaxf(mx0, fmaxf(s4[nt].x, s4[nt].y));
            mx1 = fmaxf(mx1, fmaxf(s4[nt].z, s4[nt].w));
        }
        mx0 = fmaxf(mx0, __shfl_xor_sync(0xffffffffu, mx0, 1));
        mx0 = fmaxf(mx0, __shfl_xor_sync(0xffffffffu, mx0, 2));
        mx1 = fmaxf(mx1, __shfl_xor_sync(0xffffffffu, mx1, 1));
        mx1 = fmaxf(mx1, __shfl_xor_sync(0xffffffffu, mx1, 2));
        float nm0 = fmaxf(m0, mx0), nm1 = fmaxf(m1, mx1);
        float al0 = __expf(m0 - nm0), al1 = __expf(m1 - nm1);
        m0 = nm0; m1 = nm1;

        float sum0 = 0.f, sum1 = 0.f;
#pragma unroll
        for (int nt = 0; nt < 8; ++nt) {
            s4[nt].x = __expf(s4[nt].x - nm0);
            s4[nt].y = __expf(s4[nt].y - nm0);
            s4[nt].z = __expf(s4[nt].z - nm1);
            s4[nt].w = __expf(s4[nt].w - nm1);
            sum0 += s4[nt].x + s4[nt].y;
            sum1 += s4[nt].z + s4[nt].w;
        }
        sum0 += __shfl_xor_sync(0xffffffffu, sum0, 1);
        sum0 += __shfl_xor_sync(0xffffffffu, sum0, 2);
        sum1 += __shfl_xor_sync(0xffffffffu, sum1, 1);
        sum1 += __shfl_xor_sync(0xffffffffu, sum1, 2);
        l0 = l0 * al0 + sum0;
        l1 = l1 * al1 + sum1;
#pragma unroll
        for (int j = 0; j < 16; ++j) {
            O[j].x *= al0; O[j].y *= al0; O[j].z *= al1; O[j].w *= al1;
        }

        // ---- P bf16 split, PV bf16x3 (validated path) ----
        unsigned phi[16], plo[16];
#pragma unroll
        for (int nt = 0; nt < 8; ++nt) {
            uint2 t01 = split2_bf(s4[nt].x, s4[nt].y);
            uint2 t23 = split2_bf(s4[nt].z, s4[nt].w);
            phi[2 * nt] = t01.x;  plo[2 * nt] = t01.y;
            phi[2 * nt + 1] = t23.x;  plo[2 * nt + 1] = t23.y;
        }

        const int mgrp = lane >> 3, lr2 = lane & 7;
#pragma unroll
        for (int t2 = 0; t2 < 4; ++t2) {
            unsigned pa0 = phi[4 * t2], pa1 = phi[4 * t2 + 1];
            unsigned pa2 = phi[4 * t2 + 2], pa3 = phi[4 * t2 + 3];
            unsigned pb0 = plo[4 * t2], pb1 = plo[4 * t2 + 1];
            unsigned pb2 = plo[4 * t2 + 2], pb3 = plo[4 * t2 + 3];
#pragma unroll
            for (int nb = 0; nb < 8; ++nb) {
                int s = 16 * t2 + ((mgrp & 1) << 3) + lr2;
                int cb = 2 * nb + (mgrp >> 1);
                unsigned off = (unsigned)(s * 64 + ((cb ^ (s & 7)) << 2)) * 4u;
                unsigned h0, h1, h2, h3, v0, v1, v2, v3;
                asm volatile("ldmatrix.sync.aligned.m8n8.x4.trans.shared.b16 "
                             "{%0,%1,%2,%3}, [%4];"
                             : "=r"(h0), "=r"(h1), "=r"(h2), "=r"(h3)
                             : "r"(VhB + off));
                asm volatile("ldmatrix.sync.aligned.m8n8.x4.trans.shared.b16 "
                             "{%0,%1,%2,%3}, [%4];"
                             : "=r"(v0), "=r"(v1), "=r"(v2), "=r"(v3)
                             : "r"(VlB + off));
                mma_bf16(O[2 * nb], pa0, pa1, pa2, pa3, h0, h1);
                mma_bf16(O[2 * nb], pa0, pa1, pa2, pa3, v0, v1);
                mma_bf16(O[2 * nb], pb0, pb1, pb2, pb3, h0, h1);
                mma_bf16(O[2 * nb + 1], pa0, pa1, pa2, pa3, h2, h3);
                mma_bf16(O[2 * nb + 1], pa0, pa1, pa2, pa3, v2, v3);
                mma_bf16(O[2 * nb + 1], pb0, pb1, pb2, pb3, h2, h3);
            }
        }
    }

    // epilogue: normalize + fp16 split (A-side of final GEMM)
    float inv0 = 1.0f / l0, inv1 = 1.0f / l1;
    size_t p0 = (qrow0 + w * 16 + gr) * 1024 + h * 64;
    size_t p1 = p0 + (size_t)8 * 1024;
#pragma unroll
    for (int j = 0; j < 16; ++j) {
        int pc = j * 4 + q4;
        As2[p0 + pc] = split2_h(O[j].x * inv0, O[j].y * inv0);
        As2[p1 + pc] = split2_h(O[j].z * inv1, O[j].w * inv1);
    }
}

// ---------------------------------------------------------------------------
extern "C" void kernel_launch(void* const* d_in, const int* in_sizes, int n_in,
                              void* d_out, int out_size) {
    const float* x  = (const float*)d_in[0];
    const float* Wq = (const float*)d_in[1];
    const float* Wk = (const float*)d_in[2];
    const float* Wv = (const float*)d_in[3];
    const float* Wo = (const float*)d_in[4];
    float* out = (float*)d_out;

    unsigned *xs, *as, *ws, *vh, *vl, *ks1;
    uint2 *qs2;
    cudaGetSymbolAddress((void**)&xs, g_xs);
    cudaGetSymbolAddress((void**)&as, g_as);
    cudaGetSymbolAddress((void**)&ws, g_ws);
    cudaGetSymbolAddress((void**)&vh, g_vh);
    cudaGetSymbolAddress((void**)&vl, g_vl);
    cudaGetSymbolAddress((void**)&ks1, g_ks1);
    cudaGetSymbolAddress((void**)&qs2, g_qs2);

    rope_tables_kernel<<<(SEQ * 64) / 256, 256>>>();

    const int XP = ROWS * DM / 2;   // pairs in x / A
    const int WP = DM * DM / 2;     // pairs per weight
    splith_kernel<<<XP / 256, 256>>>(x, xs, XP);
    wpack_kernel<<<WP / 256, 256>>>(Wq, ws, WP);
    wpack_kernel<<<WP / 256, 256>>>(Wk, ws + WU, WP);
    wpack_kernel<<<WP / 256, 256>>>(Wv, ws + 2 * WU, WP);

    cudaFuncSetAttribute(mgemm_h2, cudaFuncAttributeMaxDynamicSharedMemorySize,
                         MG_SMEM_BYTES);
    // QKV mega-GEMM: bx 0-15 -> Q (rope+scale+fp16split), 16-31 -> K (rope+fp16),
    // 32-47 -> V (bf16 split planes)
    mgemm_h2<<<dim3(48, 64), 256, MG_SMEM_BYTES>>>(xs, ws, -1, nullptr,
                                                   vh, vl, qs2, ks1);

    cudaFuncSetAttribute(flash_mma, cudaFuncAttributeMaxDynamicSharedMemorySize,
                         FL_SMEM_BYTES);
    flash_mma<<<dim3(SEQ / 64, BATCH * NH), 128, FL_SMEM_BYTES>>>(
        qs2, ks1, vh, vl, (uint2*)as);

    // Wo reuses ws[0] (stream-ordered after QKV GEMM)
    wpack_kernel<<<WP / 256, 256>>>(Wo, ws, WP);
    mgemm_h2<<<dim3(16, 64), 256, MG_SMEM_BYTES>>>(as, ws, 0, out,
                                                   nullptr, nullptr, nullptr, nullptr);
}

// round 8
// speedup vs baseline: 3.4178x; 1.0897x over previous
#include <cuda_runtime.h>
#include <cuda_fp16.h>
#include <math.h>

// ---------------------------------------------------------------------------
// Fused causal MHA forward — fp16x2 mma.sync everywhere it can afford it.
//   GEMMs: A fp16-split (2 MMAs), B plain fp16, 3-stage cp.async pipeline.
//   Flash: fp16 QK (Q split) + fp16 PV (P split, V plain), K/V double-buffered.
// ---------------------------------------------------------------------------

#define SEQ   4096
#define BATCH 2
#define DM    2048
#define NH    16
#define DH    128
#define ROWS  (BATCH * SEQ)      // 8192
#define WU    (DM * DM / 2)      // u32 per packed weight plane

__device__ float    g_cos[SEQ * 64];
__device__ float    g_sin[SEQ * 64];
__device__ unsigned g_xs[ROWS * DM];        // x: fp16 split, interleaved (hi,lo)/pair
__device__ unsigned g_as[ROWS * DM];        // attn out: fp16 split interleaved
__device__ unsigned g_ws[3 * WU];           // Wq|Wk|Wv plain fp16 (Wo reuses [0])
__device__ uint2    g_qs2[ROWS * 1024];     // Q rope+fp16 split
__device__ unsigned g_ks1[ROWS * 1024];     // K rope, plain fp16
__device__ unsigned g_v1[ROWS * 1024];      // V plain fp16 plane

// ---------------------------------------------------------------------------
__device__ __forceinline__ void mma_f16(float4& c,
                                        unsigned a0, unsigned a1, unsigned a2, unsigned a3,
                                        unsigned b0, unsigned b1) {
    asm("mma.sync.aligned.m16n8k16.row.col.f32.f16.f16.f32 "
        "{%0,%1,%2,%3}, {%4,%5,%6,%7}, {%8,%9}, {%0,%1,%2,%3};"
        : "+f"(c.x), "+f"(c.y), "+f"(c.z), "+f"(c.w)
        : "r"(a0), "r"(a1), "r"(a2), "r"(a3), "r"(b0), "r"(b1));
}

__device__ __forceinline__ unsigned pack_f16x2(float x, float y) {
    __half2 h = __floats2half2_rn(x, y);
    return *(unsigned*)&h;
}
__device__ __forceinline__ uint2 split2_h(float x, float y) {
    __half2 h = __floats2half2_rn(x, y);
    float2 f = __half22float2(h);
    __half2 l = __floats2half2_rn(x - f.x, y - f.y);
    return make_uint2(*(unsigned*)&h, *(unsigned*)&l);
}

// ---------------------------------------------------------------------------
__global__ void rope_tables_kernel() {
    int idx = blockIdx.x * blockDim.x + threadIdx.x;
    int s = idx >> 6, i = idx & 63;
    double invd = pow(10000.0, -((double)(2 * i)) / 128.0);
    float arg = (float)s * (float)invd;
    double sv, cv;
    sincos((double)arg, &sv, &cv);
    g_cos[idx] = (float)cv;
    g_sin[idx] = (float)sv;
}

__global__ void splith_kernel(const float* __restrict__ s, unsigned* __restrict__ d,
                              int npairs) {
    int p = blockIdx.x * blockDim.x + threadIdx.x;
    if (p >= npairs) return;
    float2 v = *(const float2*)&s[2 * p];
    *(uint2*)&d[2 * p] = split2_h(v.x, v.y);
}

__global__ void wpack_kernel(const float* __restrict__ s, unsigned* __restrict__ d,
                             int npairs) {
    int p = blockIdx.x * blockDim.x + threadIdx.x;
    if (p >= npairs) return;
    float2 v = *(const float2*)&s[2 * p];
    d[p] = pack_f16x2(v.x, v.y);
}

// ---------------------------------------------------------------------------
// GEMM C[m,n] = sum_k A[m,k]*B[n,k]. A fp16-split interleaved; B plain fp16.
// 128x128 CTA tile, 8 warps, warp 64x32, k32 stages, 3-stage cp.async ring,
// ONE __syncthreads per stage. 2 MMAs per tile per k16.
// modes: 0 = fp32 C; -1 = per bx>>4: 0->Q(rope+scale+split),
//        1->K(rope+fp16), 2->V(plain fp16 plane).
// ---------------------------------------------------------------------------
#define MG_A_U    5120                        // 128 rows x 40 u32
#define MG_B_U    2560                        // 128 rows x 20 u32
#define MG_STAGEU (MG_A_U + MG_B_U)           // 7680 u32 = 30720 B
#define MG_SMEM_BYTES (3 * MG_STAGEU * 4)     // 92160
#define MG_KT     (DM / 32)                   // 64

__global__ __launch_bounds__(256, 2) void mgemm_h2(
        const unsigned* __restrict__ Ag, const unsigned* __restrict__ Bg,
        int modes, float* __restrict__ Cf,
        unsigned* __restrict__ Pv,
        uint2* __restrict__ Pq, unsigned* __restrict__ Pk) {
    extern __shared__ unsigned sm[];
    const unsigned sbase = (unsigned)__cvta_generic_to_shared(sm);
    const int tid = threadIdx.x, wid = tid >> 5, lane = tid & 31;
    const int wm = wid >> 2, wn = wid & 3, g8 = lane >> 2, qd = lane & 3;
    const int bx = blockIdx.x, by = blockIdx.y;

    const int lr = tid >> 3, lc = (tid & 7) << 2;
    const unsigned* sA = Ag + (size_t)(by * 128 + lr) * DM + lc;
    const unsigned dA0 = sbase + (unsigned)(lr * 40 + lc) * 4u;
    const int br0 = tid >> 2, bc0 = (tid & 3) << 2;
    const unsigned* sB0 = Bg + (size_t)(bx * 128 + br0) * (DM / 2) + bc0;
    const unsigned dB0 = sbase + (unsigned)(MG_A_U + br0 * 20 + bc0) * 4u;

    auto load_stage = [&](unsigned bufB, int kt) {
        const unsigned* a = sA + kt * 32;
#pragma unroll
        for (int l = 0; l < 4; ++l)
            asm volatile("cp.async.cg.shared.global [%0], [%1], 16;"
                         :: "r"(dA0 + bufB + (unsigned)(l * 5120)),
                            "l"(a + (size_t)l * 32 * DM));
        const unsigned* b = sB0 + kt * 16;
#pragma unroll
        for (int l = 0; l < 2; ++l)
            asm volatile("cp.async.cg.shared.global [%0], [%1], 16;"
                         :: "r"(dB0 + bufB + (unsigned)(l * 5120)),
                            "l"(b + (size_t)l * 64 * (DM / 2)));
        asm volatile("cp.async.commit_group;");
    };

    float4 acc[4][4];
#pragma unroll
    for (int i = 0; i < 4; i++)
#pragma unroll
        for (int j = 0; j < 4; j++) acc[i][j] = make_float4(0.f, 0.f, 0.f, 0.f);

    const unsigned* Aw0 = sm + (wm * 64 + g8) * 40 + qd * 2;
    const unsigned* Bw0 = sm + MG_A_U + (wn * 32 + g8) * 20 + qd;

    auto compute = [&](const unsigned* Aw, const unsigned* Bw) {
#pragma unroll
        for (int ks = 0; ks < 2; ++ks) {
            uint2 af[4][4];
#pragma unroll
            for (int mi = 0; mi < 4; ++mi) {
                const unsigned* p = Aw + mi * 640 + ks * 16;
                af[mi][0] = *(const uint2*)(p);
                af[mi][1] = *(const uint2*)(p + 8);
                af[mi][2] = *(const uint2*)(p + 320);
                af[mi][3] = *(const uint2*)(p + 328);
            }
            unsigned b0[4], b1[4];
#pragma unroll
            for (int ni = 0; ni < 4; ++ni) {
                const unsigned* q = Bw + ni * 160 + ks * 8;
                b0[ni] = q[0];
                b1[ni] = q[4];
            }
#pragma unroll
            for (int mi = 0; mi < 4; ++mi)
#pragma unroll
                for (int ni = 0; ni < 4; ++ni) {
                    mma_f16(acc[mi][ni],
                            af[mi][0].x, af[mi][2].x, af[mi][1].x, af[mi][3].x,
                            b0[ni], b1[ni]);
                    mma_f16(acc[mi][ni],
                            af[mi][0].y, af[mi][2].y, af[mi][1].y, af[mi][3].y,
                            b0[ni], b1[ni]);
                }
        }
    };

    // 3-stage ring: wait(stage kt) -> sync -> issue load(kt+2) -> compute(kt)
    load_stage(0, 0);
    load_stage(MG_STAGEU * 4u, 1);
    int cs = 0, ls = 2;
#pragma unroll 1
    for (int kt = 0; kt < MG_KT; ++kt) {
        if (kt + 1 < MG_KT) asm volatile("cp.async.wait_group 1;");
        else                asm volatile("cp.async.wait_group 0;");
        __syncthreads();
        if (kt + 2 < MG_KT) {
            load_stage((unsigned)(ls * MG_STAGEU) * 4u, kt + 2);
            ls = (ls == 2) ? 0 : ls + 1;
        }
        compute(Aw0 + cs * MG_STAGEU, Bw0 + cs * MG_STAGEU);
        cs = (cs == 2) ? 0 : cs + 1;
    }

    // ---- epilogue with fused post-ops ----
    int mode, bxl;
    if (modes >= 0) { mode = modes; bxl = bx; }
    else { int r = bx >> 4; mode = (r == 0) ? 2 : (r == 1 ? 3 : 1); bxl = bx & 15; }
    const float SC = 0.08838834764831845f;   // 1/sqrt(128)

#pragma unroll
    for (int mi = 0; mi < 4; ++mi)
#pragma unroll
        for (int ni = 0; ni < 4; ++ni) {
            int r0 = by * 128 + wm * 64 + mi * 16 + g8;
            int c0 = bxl * 128 + wn * 32 + ni * 8 + 2 * qd;
            float4 v = acc[mi][ni];
            if (mode == 0) {
                *(float2*)&Cf[(size_t)r0 * DM + c0] = make_float2(v.x, v.y);
                *(float2*)&Cf[(size_t)(r0 + 8) * DM + c0] = make_float2(v.z, v.w);
            } else if (mode == 1) {        // V: plain fp16 plane
                int pA = r0 * 1024 + (c0 >> 1);
                Pv[pA] = pack_f16x2(v.x, v.y);
                Pv[pA + 8192] = pack_f16x2(v.z, v.w);
            } else {                        // Q/K: rope (+scale)
                int i = (c0 & 127) >> 1;
                int s0 = r0 & (SEQ - 1);
                float c_ = g_cos[(s0 << 6) + i], sn = g_sin[(s0 << 6) + i];
                float c1 = g_cos[((s0 + 8) << 6) + i], s1 = g_sin[((s0 + 8) << 6) + i];
                float x0 = v.x * c_ - v.y * sn, y0 = v.y * c_ + v.x * sn;
                float x1 = v.z * c1 - v.w * s1, y1 = v.w * c1 + v.z * s1;
                int pA = r0 * 1024 + (c0 >> 1);
                if (mode == 2) {            // Q: fp16 split, scaled
                    x0 *= SC; y0 *= SC; x1 *= SC; y1 *= SC;
                    Pq[pA] = split2_h(x0, y0);
                    Pq[pA + 8192] = split2_h(x1, y1);
                } else {                    // K: plain fp16
                    Pk[pA] = pack_f16x2(x0, y0);
                    Pk[pA + 8192] = pack_f16x2(x1, y1);
                }
            }
        }
}

// ---------------------------------------------------------------------------
// Flash attention: fp16 QK (Q split), fp16 PV (P split, V plain).
// K/V tiles double-buffered via cp.async groups.
// ---------------------------------------------------------------------------
#define FL_Q_U     (64 * 136)                 // 8704 u32
#define FLK_U      (64 * 68)                  // 4352 u32
#define FLV_U      (64 * 64)                  // 4096 u32
#define FL_STAGE_U (FLK_U + FLV_U)            // 8448 u32
#define FL_SMEM_BYTES ((FL_Q_U + 2 * FL_STAGE_U) * 4)   // 102400

__global__ __launch_bounds__(128) void flash_mma(const uint2* __restrict__ qs,
                                                 const unsigned* __restrict__ ks1,
                                                 const unsigned* __restrict__ v1,
                                                 uint2* __restrict__ As2) {
    extern __shared__ unsigned su[];
    unsigned* Qs = su;                        // [64][136]
    const unsigned sb  = (unsigned)__cvta_generic_to_shared(su);
    const unsigned QsB = sb;
    const unsigned St0 = sb + FL_Q_U * 4;     // stage0: K then V

    const int tid = threadIdx.x, lane = tid & 31, w = tid >> 5;
    const int gr = lane >> 2, q4 = lane & 3;
    const int qi = (int)gridDim.x - 1 - (int)blockIdx.x;
    const int bh = blockIdx.y;
    const int b = bh >> 4, h = bh & 15;
    const size_t qrow0 = (size_t)(b * SEQ + qi * 64);

    // Q tile (group 0)
#pragma unroll
    for (int it = 0; it < 16; ++it) {
        int c = tid + it * 128;
        int r = c >> 5, ch = c & 31;
        const char* src = (const char*)(qs + (qrow0 + r) * 1024 + h * 64) + ch * 16;
        unsigned dst = QsB + (unsigned)(r * 136 + ch * 4) * 4u;
        asm volatile("cp.async.cg.shared.global [%0], [%1], 16;" :: "r"(dst), "l"(src));
    }
    asm volatile("cp.async.commit_group;");

    auto load_kv = [&](int s, int kt) {
        const size_t krow0 = (size_t)(b * SEQ + kt * 64);
        const unsigned KB = St0 + (unsigned)(s * FL_STAGE_U) * 4u;
        const unsigned VB = KB + FLK_U * 4u;
#pragma unroll
        for (int it = 0; it < 8; ++it) {
            int c = tid + it * 128;
            int r = c >> 4, ch = c & 15;
            const unsigned* src = ks1 + (krow0 + r) * 1024 + h * 64 + ch * 4;
            asm volatile("cp.async.cg.shared.global [%0], [%1], 16;"
                         :: "r"(KB + (unsigned)(r * 68 + ch * 4) * 4u), "l"(src));
        }
#pragma unroll
        for (int it = 0; it < 8; ++it) {
            int c = tid + it * 128;
            int s_ = c >> 4, cb = c & 15;
            unsigned soff = (unsigned)(s_ * 64 + ((cb ^ (s_ & 7)) << 2)) * 4u;
            const unsigned* src = v1 + (krow0 + s_) * 1024 + h * 64 + cb * 4;
            asm volatile("cp.async.cg.shared.global [%0], [%1], 16;"
                         :: "r"(VB + soff), "l"(src));
        }
        asm volatile("cp.async.commit_group;");
    };

    load_kv(0, 0);

    float4 O[16];
#pragma unroll
    for (int j = 0; j < 16; ++j) O[j] = make_float4(0.f, 0.f, 0.f, 0.f);
    float m0 = -INFINITY, m1 = -INFINITY, l0 = 0.f, l1 = 0.f;

    for (int kt = 0; kt <= qi; ++kt) {
        if (kt + 1 <= qi) {
            load_kv((kt + 1) & 1, kt + 1);
            asm volatile("cp.async.wait_group 1;");
        } else {
            asm volatile("cp.async.wait_group 0;");
        }
        __syncthreads();

        const int st = kt & 1;
        const unsigned* Ks = su + FL_Q_U + st * FL_STAGE_U;
        const unsigned VB = St0 + (unsigned)(st * FL_STAGE_U + FLK_U) * 4u;

        // ---- S = Q K^T (Qhi*K + Qlo*K) ----
        float4 s4[8];
#pragma unroll
        for (int nt = 0; nt < 8; ++nt) s4[nt] = make_float4(0.f, 0.f, 0.f, 0.f);

        const int prow = w * 16 + gr;
#pragma unroll
        for (int t = 0; t < 8; ++t) {
            uint2 a0 = *(const uint2*)&Qs[prow * 136 + (8 * t + q4) * 2];
            uint2 a1 = *(const uint2*)&Qs[(prow + 8) * 136 + (8 * t + q4) * 2];
            uint2 a2 = *(const uint2*)&Qs[prow * 136 + (8 * t + q4 + 4) * 2];
            uint2 a3 = *(const uint2*)&Qs[(prow + 8) * 136 + (8 * t + q4 + 4) * 2];
#pragma unroll
            for (int nt = 0; nt < 8; ++nt) {
                int key = nt * 8 + gr;
                unsigned b0 = Ks[key * 68 + 8 * t + q4];
                unsigned b1 = Ks[key * 68 + 8 * t + q4 + 4];
                mma_f16(s4[nt], a0.x, a1.x, a2.x, a3.x, b0, b1);
                mma_f16(s4[nt], a0.y, a1.y, a2.y, a3.y, b0, b1);
            }
        }

        if (kt == qi) {
            int r0 = w * 16 + gr, r1 = r0 + 8;
#pragma unroll
            for (int nt = 0; nt < 8; ++nt) {
                int c0 = nt * 8 + 2 * q4;
                if (c0 > r0)     s4[nt].x = -INFINITY;
                if (c0 + 1 > r0) s4[nt].y = -INFINITY;
                if (c0 > r1)     s4[nt].z = -INFINITY;
                if (c0 + 1 > r1) s4[nt].w = -INFINITY;
            }
        }

        float mx0 = -INFINITY, mx1 = -INFINITY;
#pragma unroll
        for (int nt = 0; nt < 8; ++nt) {
            mx0 = fmaxf(mx0, fmaxf(s4[nt].x, s4[nt].y));
            mx1 = fmaxf(mx1, fmaxf(s4[nt].z, s4[nt].w));
        }
        mx0 = fmaxf(mx0, __shfl_xor_sync(0xffffffffu, mx0, 1));
        mx0 = fmaxf(mx0, __shfl_xor_sync(0xffffffffu, mx0, 2));
        mx1 = fmaxf(mx1, __shfl_xor_sync(0xffffffffu, mx1, 1));
        mx1 = fmaxf(mx1, __shfl_xor_sync(0xffffffffu, mx1, 2));
        float nm0 = fmaxf(m0, mx0), nm1 = fmaxf(m1, mx1);
        float al0 = __expf(m0 - nm0), al1 = __expf(m1 - nm1);
        m0 = nm0; m1 = nm1;

        float sum0 = 0.f, sum1 = 0.f;
#pragma unroll
        for (int nt = 0; nt < 8; ++nt) {
            s4[nt].x = __expf(s4[nt].x - nm0);
            s4[nt].y = __expf(s4[nt].y - nm0);
            s4[nt].z = __expf(s4[nt].z - nm1);
            s4[nt].w = __expf(s4[nt].w - nm1);
            sum0 += s4[nt].x + s4[nt].y;
            sum1 += s4[nt].z + s4[nt].w;
        }
        sum0 += __shfl_xor_sync(0xffffffffu, sum0, 1);
        sum0 += __shfl_xor_sync(0xffffffffu, sum0, 2);
        sum1 += __shfl_xor_sync(0xffffffffu, sum1, 1);
        sum1 += __shfl_xor_sync(0xffffffffu, sum1, 2);
        l0 = l0 * al0 + sum0;
        l1 = l1 * al1 + sum1;
#pragma unroll
        for (int j = 0; j < 16; ++j) {
            O[j].x *= al0; O[j].y *= al0; O[j].z *= al1; O[j].w *= al1;
        }

        // ---- P fp16 split; O += Ph*V + Pl*V ----
        unsigned phi[16], plo[16];
#pragma unroll
        for (int nt = 0; nt < 8; ++nt) {
            uint2 t01 = split2_h(s4[nt].x, s4[nt].y);
            uint2 t23 = split2_h(s4[nt].z, s4[nt].w);
            phi[2 * nt] = t01.x;  plo[2 * nt] = t01.y;
            phi[2 * nt + 1] = t23.x;  plo[2 * nt + 1] = t23.y;
        }

        const int mgrp = lane >> 3, lr2 = lane & 7;
#pragma unroll
        for (int t2 = 0; t2 < 4; ++t2) {
            unsigned pa0 = phi[4 * t2], pa1 = phi[4 * t2 + 1];
            unsigned pa2 = phi[4 * t2 + 2], pa3 = phi[4 * t2 + 3];
            unsigned pb0 = plo[4 * t2], pb1 = plo[4 * t2 + 1];
            unsigned pb2 = plo[4 * t2 + 2], pb3 = plo[4 * t2 + 3];
#pragma unroll
            for (int nb = 0; nb < 8; ++nb) {
                int s = 16 * t2 + ((mgrp & 1) << 3) + lr2;
                int cb = 2 * nb + (mgrp >> 1);
                unsigned off = (unsigned)(s * 64 + ((cb ^ (s & 7)) << 2)) * 4u;
                unsigned h0, h1, h2, h3;
                asm volatile("ldmatrix.sync.aligned.m8n8.x4.trans.shared.b16 "
                             "{%0,%1,%2,%3}, [%4];"
                             : "=r"(h0), "=r"(h1), "=r"(h2), "=r"(h3)
                             : "r"(VB + off));
                mma_f16(O[2 * nb], pa0, pa1, pa2, pa3, h0, h1);
                mma_f16(O[2 * nb], pb0, pb1, pb2, pb3, h0, h1);
                mma_f16(O[2 * nb + 1], pa0, pa1, pa2, pa3, h2, h3);
                mma_f16(O[2 * nb + 1], pb0, pb1, pb2, pb3, h2, h3);
            }
        }
        __syncthreads();   // protect stage kt before load(kt+2) overwrites it
    }

    // epilogue: normalize + fp16 split (A-side of final GEMM)
    float inv0 = 1.0f / l0, inv1 = 1.0f / l1;
    size_t p0 = (qrow0 + w * 16 + gr) * 1024 + h * 64;
    size_t p1 = p0 + (size_t)8 * 1024;
#pragma unroll
    for (int j = 0; j < 16; ++j) {
        int pc = j * 4 + q4;
        As2[p0 + pc] = split2_h(O[j].x * inv0, O[j].y * inv0);
        As2[p1 + pc] = split2_h(O[j].z * inv1, O[j].w * inv1);
    }
}

// ---------------------------------------------------------------------------
extern "C" void kernel_launch(void* const* d_in, const int* in_sizes, int n_in,
                              void* d_out, int out_size) {
    const float* x  = (const float*)d_in[0];
    const float* Wq = (const float*)d_in[1];
    const float* Wk = (const float*)d_in[2];
    const float* Wv = (const float*)d_in[3];
    const float* Wo = (const float*)d_in[4];
    float* out = (float*)d_out;

    unsigned *xs, *as, *ws, *v1, *ks1;
    uint2 *qs2;
    cudaGetSymbolAddress((void**)&xs, g_xs);
    cudaGetSymbolAddress((void**)&as, g_as);
    cudaGetSymbolAddress((void**)&ws, g_ws);
    cudaGetSymbolAddress((void**)&v1, g_v1);
    cudaGetSymbolAddress((void**)&ks1, g_ks1);
    cudaGetSymbolAddress((void**)&qs2, g_qs2);

    rope_tables_kernel<<<(SEQ * 64) / 256, 256>>>();

    const int XP = ROWS * DM / 2;
    const int WP = DM * DM / 2;
    splith_kernel<<<XP / 256, 256>>>(x, xs, XP);
    wpack_kernel<<<WP / 256, 256>>>(Wq, ws, WP);
    wpack_kernel<<<WP / 256, 256>>>(Wk, ws + WU, WP);
    wpack_kernel<<<WP / 256, 256>>>(Wv, ws + 2 * WU, WP);

    cudaFuncSetAttribute(mgemm_h2, cudaFuncAttributeMaxDynamicSharedMemorySize,
                         MG_SMEM_BYTES);
    // QKV mega-GEMM: bx 0-15 -> Q, 16-31 -> K, 32-47 -> V
    mgemm_h2<<<dim3(48, 64), 256, MG_SMEM_BYTES>>>(xs, ws, -1, nullptr,
                                                   v1, qs2, ks1);

    cudaFuncSetAttribute(flash_mma, cudaFuncAttributeMaxDynamicSharedMemorySize,
                         FL_SMEM_BYTES);
    flash_mma<<<dim3(SEQ / 64, BATCH * NH), 128, FL_SMEM_BYTES>>>(
        qs2, ks1, v1, (uint2*)as);

    wpack_kernel<<<WP / 256, 256>>>(Wo, ws, WP);
    mgemm_h2<<<dim3(16, 64), 256, MG_SMEM_BYTES>>>(as, ws, 0, out,
                                                   nullptr, nullptr, nullptr);
}

// round 9
// speedup vs baseline: 3.5453x; 1.0373x over previous
#include <cuda_runtime.h>
#include <cuda_fp16.h>
#include <math.h>

// ---------------------------------------------------------------------------
// Fused causal MHA forward — fp16x2 mma.sync.
//   GEMMs: A fp16-split (2 MMAs), B plain fp16, 3-stage cp.async pipeline.
//   Flash: 128 q-rows/CTA, fp16 QK (Q split) + fp16 PV (P split), K/V dbuf.
// ---------------------------------------------------------------------------

#define SEQ   4096
#define BATCH 2
#define DM    2048
#define NH    16
#define DH    128
#define ROWS  (BATCH * SEQ)      // 8192
#define WU    (DM * DM / 2)      // u32 per packed weight plane

__device__ float    g_cos[SEQ * 64];
__device__ float    g_sin[SEQ * 64];
__device__ unsigned g_xs[ROWS * DM];        // x: fp16 split, interleaved (hi,lo)/pair
__device__ unsigned g_as[ROWS * DM];        // attn out: fp16 split interleaved
__device__ unsigned g_ws[3 * WU];           // Wq|Wk|Wv plain fp16 (Wo reuses [0])
__device__ uint2    g_qs2[ROWS * 1024];     // Q rope+fp16 split
__device__ unsigned g_ks1[ROWS * 1024];     // K rope, plain fp16
__device__ unsigned g_v1[ROWS * 1024];      // V plain fp16 plane

// ---------------------------------------------------------------------------
__device__ __forceinline__ void mma_f16(float4& c,
                                        unsigned a0, unsigned a1, unsigned a2, unsigned a3,
                                        unsigned b0, unsigned b1) {
    asm("mma.sync.aligned.m16n8k16.row.col.f32.f16.f16.f32 "
        "{%0,%1,%2,%3}, {%4,%5,%6,%7}, {%8,%9}, {%0,%1,%2,%3};"
        : "+f"(c.x), "+f"(c.y), "+f"(c.z), "+f"(c.w)
        : "r"(a0), "r"(a1), "r"(a2), "r"(a3), "r"(b0), "r"(b1));
}

__device__ __forceinline__ unsigned pack_f16x2(float x, float y) {
    __half2 h = __floats2half2_rn(x, y);
    return *(unsigned*)&h;
}
__device__ __forceinline__ uint2 split2_h(float x, float y) {
    __half2 h = __floats2half2_rn(x, y);
    float2 f = __half22float2(h);
    __half2 l = __floats2half2_rn(x - f.x, y - f.y);
    return make_uint2(*(unsigned*)&h, *(unsigned*)&l);
}

// ---------------------------------------------------------------------------
__global__ void rope_tables_kernel() {
    int idx = blockIdx.x * blockDim.x + threadIdx.x;
    int s = idx >> 6, i = idx & 63;
    double invd = pow(10000.0, -((double)(2 * i)) / 128.0);
    float arg = (float)s * (float)invd;
    double sv, cv;
    sincos((double)arg, &sv, &cv);
    g_cos[idx] = (float)cv;
    g_sin[idx] = (float)sv;
}

__global__ void splith_kernel(const float* __restrict__ s, unsigned* __restrict__ d,
                              int npairs) {
    int p = blockIdx.x * blockDim.x + threadIdx.x;
    if (p >= npairs) return;
    float2 v = *(const float2*)&s[2 * p];
    *(uint2*)&d[2 * p] = split2_h(v.x, v.y);
}

__global__ void wpack_kernel(const float* __restrict__ s, unsigned* __restrict__ d,
                             int npairs) {
    int p = blockIdx.x * blockDim.x + threadIdx.x;
    if (p >= npairs) return;
    float2 v = *(const float2*)&s[2 * p];
    d[p] = pack_f16x2(v.x, v.y);
}

// ---------------------------------------------------------------------------
// GEMM C[m,n] = sum_k A[m,k]*B[n,k]. A fp16-split interleaved; B plain fp16.
// 128x128 CTA tile, 8 warps, warp 64x32, k32 stages, 3-stage cp.async ring.
// modes: 0 = fp32 C; -1 = per bx>>4: 0->Q(rope+scale+split),
//        1->K(rope+fp16), 2->V(plain fp16 plane).
// ---------------------------------------------------------------------------
#define MG_A_U    5120
#define MG_B_U    2560
#define MG_STAGEU (MG_A_U + MG_B_U)           // 7680 u32
#define MG_SMEM_BYTES (3 * MG_STAGEU * 4)     // 92160
#define MG_KT     (DM / 32)                   // 64

__global__ __launch_bounds__(256, 2) void mgemm_h2(
        const unsigned* __restrict__ Ag, const unsigned* __restrict__ Bg,
        int modes, float* __restrict__ Cf,
        unsigned* __restrict__ Pv,
        uint2* __restrict__ Pq, unsigned* __restrict__ Pk) {
    extern __shared__ unsigned sm[];
    const unsigned sbase = (unsigned)__cvta_generic_to_shared(sm);
    const int tid = threadIdx.x, wid = tid >> 5, lane = tid & 31;
    const int wm = wid >> 2, wn = wid & 3, g8 = lane >> 2, qd = lane & 3;
    const int bx = blockIdx.x, by = blockIdx.y;

    const int lr = tid >> 3, lc = (tid & 7) << 2;
    const unsigned* sA = Ag + (size_t)(by * 128 + lr) * DM + lc;
    const unsigned dA0 = sbase + (unsigned)(lr * 40 + lc) * 4u;
    const int br0 = tid >> 2, bc0 = (tid & 3) << 2;
    const unsigned* sB0 = Bg + (size_t)(bx * 128 + br0) * (DM / 2) + bc0;
    const unsigned dB0 = sbase + (unsigned)(MG_A_U + br0 * 20 + bc0) * 4u;

    auto load_stage = [&](unsigned bufB, int kt) {
        const unsigned* a = sA + kt * 32;
#pragma unroll
        for (int l = 0; l < 4; ++l)
            asm volatile("cp.async.cg.shared.global [%0], [%1], 16;"
                         :: "r"(dA0 + bufB + (unsigned)(l * 5120)),
                            "l"(a + (size_t)l * 32 * DM));
        const unsigned* b = sB0 + kt * 16;
#pragma unroll
        for (int l = 0; l < 2; ++l)
            asm volatile("cp.async.cg.shared.global [%0], [%1], 16;"
                         :: "r"(dB0 + bufB + (unsigned)(l * 5120)),
                            "l"(b + (size_t)l * 64 * (DM / 2)));
        asm volatile("cp.async.commit_group;");
    };

    float4 acc[4][4];
#pragma unroll
    for (int i = 0; i < 4; i++)
#pragma unroll
        for (int j = 0; j < 4; j++) acc[i][j] = make_float4(0.f, 0.f, 0.f, 0.f);

    const unsigned* Aw0 = sm + (wm * 64 + g8) * 40 + qd * 2;
    const unsigned* Bw0 = sm + MG_A_U + (wn * 32 + g8) * 20 + qd;

    auto compute = [&](const unsigned* Aw, const unsigned* Bw) {
#pragma unroll
        for (int ks = 0; ks < 2; ++ks) {
            uint2 af[4][4];
#pragma unroll
            for (int mi = 0; mi < 4; ++mi) {
                const unsigned* p = Aw + mi * 640 + ks * 16;
                af[mi][0] = *(const uint2*)(p);
                af[mi][1] = *(const uint2*)(p + 8);
                af[mi][2] = *(const uint2*)(p + 320);
                af[mi][3] = *(const uint2*)(p + 328);
            }
            unsigned b0[4], b1[4];
#pragma unroll
            for (int ni = 0; ni < 4; ++ni) {
                const unsigned* q = Bw + ni * 160 + ks * 8;
                b0[ni] = q[0];
                b1[ni] = q[4];
            }
#pragma unroll
            for (int mi = 0; mi < 4; ++mi)
#pragma unroll
                for (int ni = 0; ni < 4; ++ni) {
                    mma_f16(acc[mi][ni],
                            af[mi][0].x, af[mi][2].x, af[mi][1].x, af[mi][3].x,
                            b0[ni], b1[ni]);
                    mma_f16(acc[mi][ni],
                            af[mi][0].y, af[mi][2].y, af[mi][1].y, af[mi][3].y,
                            b0[ni], b1[ni]);
                }
        }
    };

    load_stage(0, 0);
    load_stage(MG_STAGEU * 4u, 1);
    int cs = 0, ls = 2;
#pragma unroll 1
    for (int kt = 0; kt < MG_KT; ++kt) {
        if (kt + 1 < MG_KT) asm volatile("cp.async.wait_group 1;");
        else                asm volatile("cp.async.wait_group 0;");
        __syncthreads();
        if (kt + 2 < MG_KT) {
            load_stage((unsigned)(ls * MG_STAGEU) * 4u, kt + 2);
            ls = (ls == 2) ? 0 : ls + 1;
        }
        compute(Aw0 + cs * MG_STAGEU, Bw0 + cs * MG_STAGEU);
        cs = (cs == 2) ? 0 : cs + 1;
    }

    int mode, bxl;
    if (modes >= 0) { mode = modes; bxl = bx; }
    else { int r = bx >> 4; mode = (r == 0) ? 2 : (r == 1 ? 3 : 1); bxl = bx & 15; }
    const float SC = 0.08838834764831845f;

#pragma unroll
    for (int mi = 0; mi < 4; ++mi)
#pragma unroll
        for (int ni = 0; ni < 4; ++ni) {
            int r0 = by * 128 + wm * 64 + mi * 16 + g8;
            int c0 = bxl * 128 + wn * 32 + ni * 8 + 2 * qd;
            float4 v = acc[mi][ni];
            if (mode == 0) {
                *(float2*)&Cf[(size_t)r0 * DM + c0] = make_float2(v.x, v.y);
                *(float2*)&Cf[(size_t)(r0 + 8) * DM + c0] = make_float2(v.z, v.w);
            } else if (mode == 1) {
                int pA = r0 * 1024 + (c0 >> 1);
                Pv[pA] = pack_f16x2(v.x, v.y);
                Pv[pA + 8192] = pack_f16x2(v.z, v.w);
            } else {
                int i = (c0 & 127) >> 1;
                int s0 = r0 & (SEQ - 1);
                float c_ = g_cos[(s0 << 6) + i], sn = g_sin[(s0 << 6) + i];
                float c1 = g_cos[((s0 + 8) << 6) + i], s1 = g_sin[((s0 + 8) << 6) + i];
                float x0 = v.x * c_ - v.y * sn, y0 = v.y * c_ + v.x * sn;
                float x1 = v.z * c1 - v.w * s1, y1 = v.w * c1 + v.z * s1;
                int pA = r0 * 1024 + (c0 >> 1);
                if (mode == 2) {
                    x0 *= SC; y0 *= SC; x1 *= SC; y1 *= SC;
                    Pq[pA] = split2_h(x0, y0);
                    Pq[pA + 8192] = split2_h(x1, y1);
                } else {
                    Pk[pA] = pack_f16x2(x0, y0);
                    Pk[pA + 8192] = pack_f16x2(x1, y1);
                }
            }
        }
}

// ---------------------------------------------------------------------------
// Flash attention: 128 q-rows per CTA (256 thr, 8 warps, 16 rows/warp),
// 64-key tiles, fp16 QK (Q split) + fp16 PV (P split), K/V double-buffered.
// ---------------------------------------------------------------------------
#define FL_Q_U     (128 * 136)                // 17408 u32
#define FLK_U      (64 * 68)                  // 4352 u32
#define FLV_U      (64 * 64)                  // 4096 u32
#define FL_STAGE_U (FLK_U + FLV_U)            // 8448 u32
#define FL_SMEM_BYTES ((FL_Q_U + 2 * FL_STAGE_U) * 4)   // 137216

__global__ __launch_bounds__(256) void flash_mma(const uint2* __restrict__ qs,
                                                 const unsigned* __restrict__ ks1,
                                                 const unsigned* __restrict__ v1,
                                                 uint2* __restrict__ As2) {
    extern __shared__ unsigned su[];
    unsigned* Qs = su;                        // [128][136]
    const unsigned sb  = (unsigned)__cvta_generic_to_shared(su);
    const unsigned QsB = sb;
    const unsigned St0 = sb + FL_Q_U * 4;     // stage0: K then V

    const int tid = threadIdx.x, lane = tid & 31, w = tid >> 5;
    const int gr = lane >> 2, q4 = lane & 3;
    const int qi = (int)gridDim.x - 1 - (int)blockIdx.x;   // longest first
    const int bh = blockIdx.y;
    const int b = bh >> 4, h = bh & 15;
    const size_t qrow0 = (size_t)(b * SEQ + qi * 128);
    const int ktmax = 2 * qi + 1;

    // Q tile: 128 rows x 32 chunks = 4096
#pragma unroll
    for (int it = 0; it < 16; ++it) {
        int c = tid + it * 256;
        int r = c >> 5, ch = c & 31;
        const char* src = (const char*)(qs + (qrow0 + r) * 1024 + h * 64) + ch * 16;
        unsigned dst = QsB + (unsigned)(r * 136 + ch * 4) * 4u;
        asm volatile("cp.async.cg.shared.global [%0], [%1], 16;" :: "r"(dst), "l"(src));
    }
    asm volatile("cp.async.commit_group;");

    auto load_kv = [&](int s, int kt) {
        const size_t krow0 = (size_t)(b * SEQ + kt * 64);
        const unsigned KB = St0 + (unsigned)(s * FL_STAGE_U) * 4u;
        const unsigned VB = KB + FLK_U * 4u;
#pragma unroll
        for (int it = 0; it < 4; ++it) {
            int c = tid + it * 256;
            int r = c >> 4, ch = c & 15;
            const unsigned* src = ks1 + (krow0 + r) * 1024 + h * 64 + ch * 4;
            asm volatile("cp.async.cg.shared.global [%0], [%1], 16;"
                         :: "r"(KB + (unsigned)(r * 68 + ch * 4) * 4u), "l"(src));
        }
#pragma unroll
        for (int it = 0; it < 4; ++it) {
            int c = tid + it * 256;
            int s_ = c >> 4, cb = c & 15;
            unsigned soff = (unsigned)(s_ * 64 + ((cb ^ (s_ & 7)) << 2)) * 4u;
            const unsigned* src = v1 + (krow0 + s_) * 1024 + h * 64 + cb * 4;
            asm volatile("cp.async.cg.shared.global [%0], [%1], 16;"
                         :: "r"(VB + soff), "l"(src));
        }
        asm volatile("cp.async.commit_group;");
    };

    load_kv(0, 0);

    float4 O[16];
#pragma unroll
    for (int j = 0; j < 16; ++j) O[j] = make_float4(0.f, 0.f, 0.f, 0.f);
    float m0 = -INFINITY, m1 = -INFINITY, l0 = 0.f, l1 = 0.f;

    for (int kt = 0; kt <= ktmax; ++kt) {
        if (kt + 1 <= ktmax) {
            load_kv((kt + 1) & 1, kt + 1);
            asm volatile("cp.async.wait_group 1;");
        } else {
            asm volatile("cp.async.wait_group 0;");
        }
        __syncthreads();

        const int st = kt & 1;
        const unsigned* Ks = su + FL_Q_U + st * FL_STAGE_U;
        const unsigned VB = St0 + (unsigned)(st * FL_STAGE_U + FLK_U) * 4u;

        // ---- S = Q K^T (Qhi*K + Qlo*K) ----
        float4 s4[8];
#pragma unroll
        for (int nt = 0; nt < 8; ++nt) s4[nt] = make_float4(0.f, 0.f, 0.f, 0.f);

        const int prow = w * 16 + gr;
#pragma unroll
        for (int t = 0; t < 8; ++t) {
            uint2 a0 = *(const uint2*)&Qs[prow * 136 + (8 * t + q4) * 2];
            uint2 a1 = *(const uint2*)&Qs[(prow + 8) * 136 + (8 * t + q4) * 2];
            uint2 a2 = *(const uint2*)&Qs[prow * 136 + (8 * t + q4 + 4) * 2];
            uint2 a3 = *(const uint2*)&Qs[(prow + 8) * 136 + (8 * t + q4 + 4) * 2];
#pragma unroll
            for (int nt = 0; nt < 8; ++nt) {
                int key = nt * 8 + gr;
                unsigned b0 = Ks[key * 68 + 8 * t + q4];
                unsigned b1 = Ks[key * 68 + 8 * t + q4 + 4];
                mma_f16(s4[nt], a0.x, a1.x, a2.x, a3.x, b0, b1);
                mma_f16(s4[nt], a0.y, a1.y, a2.y, a3.y, b0, b1);
            }
        }

        // causal mask: only the last two tiles need it
        if (kt >= 2 * qi) {
            int off = (kt - 2 * qi) * 64;
            int r0 = w * 16 + gr, r1 = r0 + 8;
#pragma unroll
            for (int nt = 0; nt < 8; ++nt) {
                int c0 = nt * 8 + 2 * q4 + off;
                if (c0 > r0)     s4[nt].x = -INFINITY;
                if (c0 + 1 > r0) s4[nt].y = -INFINITY;
                if (c0 > r1)     s4[nt].z = -INFINITY;
                if (c0 + 1 > r1) s4[nt].w = -INFINITY;
            }
        }

        float mx0 = -INFINITY, mx1 = -INFINITY;
#pragma unroll
        for (int nt = 0; nt < 8; ++nt) {
            mx0 = fmaxf(mx0, fmaxf(s4[nt].x, s4[nt].y));
            mx1 = fmaxf(mx1, fmaxf(s4[nt].z, s4[nt].w));
        }
        mx0 = fmaxf(mx0, __shfl_xor_sync(0xffffffffu, mx0, 1));
        mx0 = fmaxf(mx0, __shfl_xor_sync(0xffffffffu, mx0, 2));
        mx1 = fmaxf(mx1, __shfl_xor_sync(0xffffffffu, mx1, 1));
        mx1 = fmaxf(mx1, __shfl_xor_sync(0xffffffffu, mx1, 2));
        float nm0 = fmaxf(m0, mx0), nm1 = fmaxf(m1, mx1);
        float al0 = __expf(m0 - nm0), al1 = __expf(m1 - nm1);
        m0 = nm0; m1 = nm1;

        float sum0 = 0.f, sum1 = 0.f;
#pragma unroll
        for (int nt = 0; nt < 8; ++nt) {
            s4[nt].x = __expf(s4[nt].x - nm0);
            s4[nt].y = __expf(s4[nt].y - nm0);
            s4[nt].z = __expf(s4[nt].z - nm1);
            s4[nt].w = __expf(s4[nt].w - nm1);
            sum0 += s4[nt].x + s4[nt].y;
            sum1 += s4[nt].z + s4[nt].w;
        }
        sum0 += __shfl_xor_sync(0xffffffffu, sum0, 1);
        sum0 += __shfl_xor_sync(0xffffffffu, sum0, 2);
        sum1 += __shfl_xor_sync(0xffffffffu, sum1, 1);
        sum1 += __shfl_xor_sync(0xffffffffu, sum1, 2);
        l0 = l0 * al0 + sum0;
        l1 = l1 * al1 + sum1;
#pragma unroll
        for (int j = 0; j < 16; ++j) {
            O[j].x *= al0; O[j].y *= al0; O[j].z *= al1; O[j].w *= al1;
        }

        unsigned phi[16], plo[16];
#pragma unroll
        for (int nt = 0; nt < 8; ++nt) {
            uint2 t01 = split2_h(s4[nt].x, s4[nt].y);
            uint2 t23 = split2_h(s4[nt].z, s4[nt].w);
            phi[2 * nt] = t01.x;  plo[2 * nt] = t01.y;
            phi[2 * nt + 1] = t23.x;  plo[2 * nt + 1] = t23.y;
        }

        const int mgrp = lane >> 3, lr2 = lane & 7;
#pragma unroll
        for (int t2 = 0; t2 < 4; ++t2) {
            unsigned pa0 = phi[4 * t2], pa1 = phi[4 * t2 + 1];
            unsigned pa2 = phi[4 * t2 + 2], pa3 = phi[4 * t2 + 3];
            unsigned pb0 = plo[4 * t2], pb1 = plo[4 * t2 + 1];
            unsigned pb2 = plo[4 * t2 + 2], pb3 = plo[4 * t2 + 3];
#pragma unroll
            for (int nb = 0; nb < 8; ++nb) {
                int s = 16 * t2 + ((mgrp & 1) << 3) + lr2;
                int cb = 2 * nb + (mgrp >> 1);
                unsigned off = (unsigned)(s * 64 + ((cb ^ (s & 7)) << 2)) * 4u;
                unsigned h0, h1, h2, h3;
                asm volatile("ldmatrix.sync.aligned.m8n8.x4.trans.shared.b16 "
                             "{%0,%1,%2,%3}, [%4];"
                             : "=r"(h0), "=r"(h1), "=r"(h2), "=r"(h3)
                             : "r"(VB + off));
                mma_f16(O[2 * nb], pa0, pa1, pa2, pa3, h0, h1);
                mma_f16(O[2 * nb], pb0, pb1, pb2, pb3, h0, h1);
                mma_f16(O[2 * nb + 1], pa0, pa1, pa2, pa3, h2, h3);
                mma_f16(O[2 * nb + 1], pb0, pb1, pb2, pb3, h2, h3);
            }
        }
        __syncthreads();
    }

    float inv0 = 1.0f / l0, inv1 = 1.0f / l1;
    size_t p0 = (qrow0 + w * 16 + gr) * 1024 + h * 64;
    size_t p1 = p0 + (size_t)8 * 1024;
#pragma unroll
    for (int j = 0; j < 16; ++j) {
        int pc = j * 4 + q4;
        As2[p0 + pc] = split2_h(O[j].x * inv0, O[j].y * inv0);
        As2[p1 + pc] = split2_h(O[j].z * inv1, O[j].w * inv1);
    }
}

// ---------------------------------------------------------------------------
extern "C" void kernel_launch(void* const* d_in, const int* in_sizes, int n_in,
                              void* d_out, int out_size) {
    const float* x  = (const float*)d_in[0];
    const float* Wq = (const float*)d_in[1];
    const float* Wk = (const float*)d_in[2];
    const float* Wv = (const float*)d_in[3];
    const float* Wo = (const float*)d_in[4];
    float* out = (float*)d_out;

    unsigned *xs, *as, *ws, *v1, *ks1;
    uint2 *qs2;
    cudaGetSymbolAddress((void**)&xs, g_xs);
    cudaGetSymbolAddress((void**)&as, g_as);
    cudaGetSymbolAddress((void**)&ws, g_ws);
    cudaGetSymbolAddress((void**)&v1, g_v1);
    cudaGetSymbolAddress((void**)&ks1, g_ks1);
    cudaGetSymbolAddress((void**)&qs2, g_qs2);

    rope_tables_kernel<<<(SEQ * 64) / 256, 256>>>();

    const int XP = ROWS * DM / 2;
    const int WP = DM * DM / 2;
    splith_kernel<<<XP / 256, 256>>>(x, xs, XP);
    wpack_kernel<<<WP / 256, 256>>>(Wq, ws, WP);
    wpack_kernel<<<WP / 256, 256>>>(Wk, ws + WU, WP);
    wpack_kernel<<<WP / 256, 256>>>(Wv, ws + 2 * WU, WP);

    cudaFuncSetAttribute(mgemm_h2, cudaFuncAttributeMaxDynamicSharedMemorySize,
                         MG_SMEM_BYTES);
    mgemm_h2<<<dim3(48, 64), 256, MG_SMEM_BYTES>>>(xs, ws, -1, nullptr,
                                                   v1, qs2, ks1);

    cudaFuncSetAttribute(flash_mma, cudaFuncAttributeMaxDynamicSharedMemorySize,
                         FL_SMEM_BYTES);
    flash_mma<<<dim3(SEQ / 128, BATCH * NH), 256, FL_SMEM_BYTES>>>(
        qs2, ks1, v1, (uint2*)as);

    wpack_kernel<<<WP / 256, 256>>>(Wo, ws, WP);
    mgemm_h2<<<dim3(16, 64), 256, MG_SMEM_BYTES>>>(as, ws, 0, out,
                                                   nullptr, nullptr, nullptr);
}

// round 10
// speedup vs baseline: 4.6620x; 1.3150x over previous
#include <cuda_runtime.h>
#include <cuda_fp16.h>
#include <math.h>

// ---------------------------------------------------------------------------
// Fused causal MHA forward — fp16 mma.sync.
//   GEMMs: A plain fp16, B plain fp16 (1 MMA/tile), 3-stage cp.async ring.
//   Flash: 128 q-rows/CTA, fp16 QK (Q split hi/lo) + fp16 PV (P split hi/lo).
// ---------------------------------------------------------------------------

#define SEQ   4096
#define BATCH 2
#define DM    2048
#define NH    16
#define DH    128
#define ROWS  (BATCH * SEQ)      // 8192
#define WU    (DM * DM / 2)      // u32 per packed weight plane
#define RWU   (DM / 2)           // u32 per packed activation row

__device__ float    g_cos[SEQ * 64];
__device__ float    g_sin[SEQ * 64];
__device__ unsigned g_xs[ROWS * RWU];       // x plain fp16
__device__ unsigned g_as[ROWS * RWU];       // attn out plain fp16
__device__ unsigned g_ws[3 * WU];           // Wq|Wk|Wv plain fp16 (Wo reuses [0])
__device__ uint2    g_qs2[ROWS * 1024];     // Q rope+fp16 split (hi,lo per pair)
__device__ unsigned g_ks1[ROWS * 1024];     // K rope, plain fp16
__device__ unsigned g_v1[ROWS * 1024];      // V plain fp16 plane

// ---------------------------------------------------------------------------
__device__ __forceinline__ void mma_f16(float4& c,
                                        unsigned a0, unsigned a1, unsigned a2, unsigned a3,
                                        unsigned b0, unsigned b1) {
    asm("mma.sync.aligned.m16n8k16.row.col.f32.f16.f16.f32 "
        "{%0,%1,%2,%3}, {%4,%5,%6,%7}, {%8,%9}, {%0,%1,%2,%3};"
        : "+f"(c.x), "+f"(c.y), "+f"(c.z), "+f"(c.w)
        : "r"(a0), "r"(a1), "r"(a2), "r"(a3), "r"(b0), "r"(b1));
}

__device__ __forceinline__ unsigned pack_f16x2(float x, float y) {
    __half2 h = __floats2half2_rn(x, y);
    return *(unsigned*)&h;
}
__device__ __forceinline__ uint2 split2_h(float x, float y) {
    __half2 h = __floats2half2_rn(x, y);
    float2 f = __half22float2(h);
    __half2 l = __floats2half2_rn(x - f.x, y - f.y);
    return make_uint2(*(unsigned*)&h, *(unsigned*)&l);
}

// ---------------------------------------------------------------------------
__global__ void rope_tables_kernel() {
    int idx = blockIdx.x * blockDim.x + threadIdx.x;
    int s = idx >> 6, i = idx & 63;
    double invd = pow(10000.0, -((double)(2 * i)) / 128.0);
    float arg = (float)s * (float)invd;
    double sv, cv;
    sincos((double)arg, &sv, &cv);
    g_cos[idx] = (float)cv;
    g_sin[idx] = (float)sv;
}

// fp32 -> plain fp16 packed pairs.
__global__ void wpack_kernel(const float* __restrict__ s, unsigned* __restrict__ d,
                             int npairs) {
    int p = blockIdx.x * blockDim.x + threadIdx.x;
    if (p >= npairs) return;
    float2 v = *(const float2*)&s[2 * p];
    d[p] = pack_f16x2(v.x, v.y);
}

// ---------------------------------------------------------------------------
// GEMM C[m,n] = sum_k A[m,k]*B[n,k]. Both operands plain fp16 -> 1 MMA/tile.
// 128x128 CTA tile, 8 warps (2x4), warp 64x32, k32 stages, 3-stage ring.
// modes: 0 = fp32 C; -1 = per bx>>4: 0->Q(rope+scale+split),
//        1->K(rope+fp16), 2->V(plain fp16 plane).
// ---------------------------------------------------------------------------
#define MG_P_U    2560                        // 128 rows x 20 u32 (16 data + 4 pad)
#define MG_STAGEU (2 * MG_P_U)                // 5120 u32 = 20480 B
#define MG_SMEM_BYTES (3 * MG_STAGEU * 4)     // 61440
#define MG_KT     (DM / 32)                   // 64

__global__ __launch_bounds__(256, 2) void mgemm_h1(
        const unsigned* __restrict__ Ag, const unsigned* __restrict__ Bg,
        int modes, float* __restrict__ Cf,
        unsigned* __restrict__ Pv,
        uint2* __restrict__ Pq, unsigned* __restrict__ Pk) {
    extern __shared__ unsigned sm[];
    const unsigned sbase = (unsigned)__cvta_generic_to_shared(sm);
    const int tid = threadIdx.x, wid = tid >> 5, lane = tid & 31;
    const int wm = wid >> 2, wn = wid & 3, g8 = lane >> 2, qd = lane & 3;
    const int bx = blockIdx.x, by = blockIdx.y;

    // loaders: 512 chunks each (128 rows x 4), rows br0+{0,64}
    const int br0 = tid >> 2, bc0 = (tid & 3) << 2;
    const unsigned* sA = Ag + (size_t)(by * 128 + br0) * RWU + bc0;
    const unsigned* sB = Bg + (size_t)(bx * 128 + br0) * RWU + bc0;
    const unsigned dA0 = sbase + (unsigned)(br0 * 20 + bc0) * 4u;
    const unsigned dB0 = dA0 + MG_P_U * 4u;

    auto load_stage = [&](unsigned bufB, int kt) {
        const unsigned* a = sA + kt * 16;
        const unsigned* b = sB + kt * 16;
#pragma unroll
        for (int l = 0; l < 2; ++l) {
            asm volatile("cp.async.cg.shared.global [%0], [%1], 16;"
                         :: "r"(dA0 + bufB + (unsigned)(l * 5120)),
                            "l"(a + (size_t)l * 64 * RWU));
            asm volatile("cp.async.cg.shared.global [%0], [%1], 16;"
                         :: "r"(dB0 + bufB + (unsigned)(l * 5120)),
                            "l"(b + (size_t)l * 64 * RWU));
        }
        asm volatile("cp.async.commit_group;");
    };

    float4 acc[4][4];
#pragma unroll
    for (int i = 0; i < 4; i++)
#pragma unroll
        for (int j = 0; j < 4; j++) acc[i][j] = make_float4(0.f, 0.f, 0.f, 0.f);

    const unsigned* Aw0 = sm + (wm * 64 + g8) * 20 + qd;
    const unsigned* Bw0 = sm + MG_P_U + (wn * 32 + g8) * 20 + qd;

    auto compute = [&](const unsigned* Aw, const unsigned* Bw) {
#pragma unroll
        for (int ks = 0; ks < 2; ++ks) {
            unsigned a0[4], a1[4], a2[4], a3[4];
#pragma unroll
            for (int mi = 0; mi < 4; ++mi) {
                const unsigned* p = Aw + mi * 320 + ks * 8;
                a0[mi] = p[0];      // row,   k[0:8)
                a2[mi] = p[4];      // row,   k[8:16)
                a1[mi] = p[160];    // row+8, k[0:8)
                a3[mi] = p[164];    // row+8, k[8:16)
            }
            unsigned b0[4], b1[4];
#pragma unroll
            for (int ni = 0; ni < 4; ++ni) {
                const unsigned* q = Bw + ni * 160 + ks * 8;
                b0[ni] = q[0];
                b1[ni] = q[4];
            }
#pragma unroll
            for (int mi = 0; mi < 4; ++mi)
#pragma unroll
                for (int ni = 0; ni < 4; ++ni)
                    mma_f16(acc[mi][ni], a0[mi], a1[mi], a2[mi], a3[mi],
                            b0[ni], b1[ni]);
        }
    };

    load_stage(0, 0);
    load_stage(MG_STAGEU * 4u, 1);
    int cs = 0, ls = 2;
#pragma unroll 1
    for (int kt = 0; kt < MG_KT; ++kt) {
        if (kt + 1 < MG_KT) asm volatile("cp.async.wait_group 1;");
        else                asm volatile("cp.async.wait_group 0;");
        __syncthreads();
        if (kt + 2 < MG_KT) {
            load_stage((unsigned)(ls * MG_STAGEU) * 4u, kt + 2);
            ls = (ls == 2) ? 0 : ls + 1;
        }
        compute(Aw0 + cs * MG_STAGEU, Bw0 + cs * MG_STAGEU);
        cs = (cs == 2) ? 0 : cs + 1;
    }

    int mode, bxl;
    if (modes >= 0) { mode = modes; bxl = bx; }
    else { int r = bx >> 4; mode = (r == 0) ? 2 : (r == 1 ? 3 : 1); bxl = bx & 15; }
    const float SC = 0.08838834764831845f;   // 1/sqrt(128)

#pragma unroll
    for (int mi = 0; mi < 4; ++mi)
#pragma unroll
        for (int ni = 0; ni < 4; ++ni) {
            int r0 = by * 128 + wm * 64 + mi * 16 + g8;
            int c0 = bxl * 128 + wn * 32 + ni * 8 + 2 * qd;
            float4 v = acc[mi][ni];
            if (mode == 0) {
                *(float2*)&Cf[(size_t)r0 * DM + c0] = make_float2(v.x, v.y);
                *(float2*)&Cf[(size_t)(r0 + 8) * DM + c0] = make_float2(v.z, v.w);
            } else if (mode == 1) {        // V plain fp16 plane
                int pA = r0 * 1024 + (c0 >> 1);
                Pv[pA] = pack_f16x2(v.x, v.y);
                Pv[pA + 8192] = pack_f16x2(v.z, v.w);
            } else {                        // Q/K: rope (+scale)
                int i = (c0 & 127) >> 1;
                int s0 = r0 & (SEQ - 1);
                float c_ = g_cos[(s0 << 6) + i], sn = g_sin[(s0 << 6) + i];
                float c1 = g_cos[((s0 + 8) << 6) + i], s1 = g_sin[((s0 + 8) << 6) + i];
                float x0 = v.x * c_ - v.y * sn, y0 = v.y * c_ + v.x * sn;
                float x1 = v.z * c1 - v.w * s1, y1 = v.w * c1 + v.z * s1;
                int pA = r0 * 1024 + (c0 >> 1);
                if (mode == 2) {            // Q: fp16 split, scaled
                    x0 *= SC; y0 *= SC; x1 *= SC; y1 *= SC;
                    Pq[pA] = split2_h(x0, y0);
                    Pq[pA + 8192] = split2_h(x1, y1);
                } else {                    // K plain fp16
                    Pk[pA] = pack_f16x2(x0, y0);
                    Pk[pA + 8192] = pack_f16x2(x1, y1);
                }
            }
        }
}

// ---------------------------------------------------------------------------
// Flash attention: 128 q-rows per CTA (256 thr, 8 warps, 16 rows/warp),
// 64-key tiles, fp16 QK (Q split) + fp16 PV (P split), K/V double-buffered.
// Epilogue writes plain-fp16 attn-out for the Wo GEMM.
// ---------------------------------------------------------------------------
#define FL_Q_U     (128 * 136)                // 17408 u32
#define FLK_U      (64 * 68)
#define FLV_U      (64 * 64)
#define FL_STAGE_U (FLK_U + FLV_U)            // 8448 u32
#define FL_SMEM_BYTES ((FL_Q_U + 2 * FL_STAGE_U) * 4)   // 137216

__global__ __launch_bounds__(256) void flash_mma(const uint2* __restrict__ qs,
                                                 const unsigned* __restrict__ ks1,
                                                 const unsigned* __restrict__ v1,
                                                 unsigned* __restrict__ As1) {
    extern __shared__ unsigned su[];
    unsigned* Qs = su;                        // [128][136]
    const unsigned sb  = (unsigned)__cvta_generic_to_shared(su);
    const unsigned QsB = sb;
    const unsigned St0 = sb + FL_Q_U * 4;

    const int tid = threadIdx.x, lane = tid & 31, w = tid >> 5;
    const int gr = lane >> 2, q4 = lane & 3;
    const int qi = (int)gridDim.x - 1 - (int)blockIdx.x;   // longest first
    const int bh = blockIdx.y;
    const int b = bh >> 4, h = bh & 15;
    const size_t qrow0 = (size_t)(b * SEQ + qi * 128);
    const int ktmax = 2 * qi + 1;

#pragma unroll
    for (int it = 0; it < 16; ++it) {
        int c = tid + it * 256;
        int r = c >> 5, ch = c & 31;
        const char* src = (const char*)(qs + (qrow0 + r) * 1024 + h * 64) + ch * 16;
        unsigned dst = QsB + (unsigned)(r * 136 + ch * 4) * 4u;
        asm volatile("cp.async.cg.shared.global [%0], [%1], 16;" :: "r"(dst), "l"(src));
    }
    asm volatile("cp.async.commit_group;");

    auto load_kv = [&](int s, int kt) {
        const size_t krow0 = (size_t)(b * SEQ + kt * 64);
        const unsigned KB = St0 + (unsigned)(s * FL_STAGE_U) * 4u;
        const unsigned VB = KB + FLK_U * 4u;
#pragma unroll
        for (int it = 0; it < 4; ++it) {
            int c = tid + it * 256;
            int r = c >> 4, ch = c & 15;
            const unsigned* src = ks1 + (krow0 + r) * 1024 + h * 64 + ch * 4;
            asm volatile("cp.async.cg.shared.global [%0], [%1], 16;"
                         :: "r"(KB + (unsigned)(r * 68 + ch * 4) * 4u), "l"(src));
        }
#pragma unroll
        for (int it = 0; it < 4; ++it) {
            int c = tid + it * 256;
            int s_ = c >> 4, cb = c & 15;
            unsigned soff = (unsigned)(s_ * 64 + ((cb ^ (s_ & 7)) << 2)) * 4u;
            const unsigned* src = v1 + (krow0 + s_) * 1024 + h * 64 + cb * 4;
            asm volatile("cp.async.cg.shared.global [%0], [%1], 16;"
                         :: "r"(VB + soff), "l"(src));
        }
        asm volatile("cp.async.commit_group;");
    };

    load_kv(0, 0);

    float4 O[16];
#pragma unroll
    for (int j = 0; j < 16; ++j) O[j] = make_float4(0.f, 0.f, 0.f, 0.f);
    float m0 = -INFINITY, m1 = -INFINITY, l0 = 0.f, l1 = 0.f;

    for (int kt = 0; kt <= ktmax; ++kt) {
        if (kt + 1 <= ktmax) {
            load_kv((kt + 1) & 1, kt + 1);
            asm volatile("cp.async.wait_group 1;");
        } else {
            asm volatile("cp.async.wait_group 0;");
        }
        __syncthreads();

        const int st = kt & 1;
        const unsigned* Ks = su + FL_Q_U + st * FL_STAGE_U;
        const unsigned VB = St0 + (unsigned)(st * FL_STAGE_U + FLK_U) * 4u;

        float4 s4[8];
#pragma unroll
        for (int nt = 0; nt < 8; ++nt) s4[nt] = make_float4(0.f, 0.f, 0.f, 0.f);

        const int prow = w * 16 + gr;
#pragma unroll
        for (int t = 0; t < 8; ++t) {
            uint2 a0 = *(const uint2*)&Qs[prow * 136 + (8 * t + q4) * 2];
            uint2 a1 = *(const uint2*)&Qs[(prow + 8) * 136 + (8 * t + q4) * 2];
            uint2 a2 = *(const uint2*)&Qs[prow * 136 + (8 * t + q4 + 4) * 2];
            uint2 a3 = *(const uint2*)&Qs[(prow + 8) * 136 + (8 * t + q4 + 4) * 2];
#pragma unroll
            for (int nt = 0; nt < 8; ++nt) {
                int key = nt * 8 + gr;
                unsigned b0 = Ks[key * 68 + 8 * t + q4];
                unsigned b1 = Ks[key * 68 + 8 * t + q4 + 4];
                mma_f16(s4[nt], a0.x, a1.x, a2.x, a3.x, b0, b1);
                mma_f16(s4[nt], a0.y, a1.y, a2.y, a3.y, b0, b1);
            }
        }

        if (kt >= 2 * qi) {
            int off = (kt - 2 * qi) * 64;
            int r0 = w * 16 + gr, r1 = r0 + 8;
#pragma unroll
            for (int nt = 0; nt < 8; ++nt) {
                int c0 = nt * 8 + 2 * q4 + off;
                if (c0 > r0)     s4[nt].x = -INFINITY;
                if (c0 + 1 > r0) s4[nt].y = -INFINITY;
                if (c0 > r1)     s4[nt].z = -INFINITY;
                if (c0 + 1 > r1) s4[nt].w = -INFINITY;
            }
        }

        float mx0 = -INFINITY, mx1 = -INFINITY;
#pragma unroll
        for (int nt = 0; nt < 8; ++nt) {
            mx0 = fmaxf(mx0, fmaxf(s4[nt].x, s4[nt].y));
            mx1 = fmaxf(mx1, fmaxf(s4[nt].z, s4[nt].w));
        }
        mx0 = fmaxf(mx0, __shfl_xor_sync(0xffffffffu, mx0, 1));
        mx0 = fmaxf(mx0, __shfl_xor_sync(0xffffffffu, mx0, 2));
        mx1 = fmaxf(mx1, __shfl_xor_sync(0xffffffffu, mx1, 1));
        mx1 = fmaxf(mx1, __shfl_xor_sync(0xffffffffu, mx1, 2));
        float nm0 = fmaxf(m0, mx0), nm1 = fmaxf(m1, mx1);
        float al0 = __expf(m0 - nm0), al1 = __expf(m1 - nm1);
        m0 = nm0; m1 = nm1;

        float sum0 = 0.f, sum1 = 0.f;
#pragma unroll
        for (int nt = 0; nt < 8; ++nt) {
            s4[nt].x = __expf(s4[nt].x - nm0);
            s4[nt].y = __expf(s4[nt].y - nm0);
            s4[nt].z = __expf(s4[nt].z - nm1);
            s4[nt].w = __expf(s4[nt].w - nm1);
            sum0 += s4[nt].x + s4[nt].y;
            sum1 += s4[nt].z + s4[nt].w;
        }
        sum0 += __shfl_xor_sync(0xffffffffu, sum0, 1);
        sum0 += __shfl_xor_sync(0xffffffffu, sum0, 2);
        sum1 += __shfl_xor_sync(0xffffffffu, sum1, 1);
        sum1 += __shfl_xor_sync(0xffffffffu, sum1, 2);
        l0 = l0 * al0 + sum0;
        l1 = l1 * al1 + sum1;
#pragma unroll
        for (int j = 0; j < 16; ++j) {
            O[j].x *= al0; O[j].y *= al0; O[j].z *= al1; O[j].w *= al1;
        }

        unsigned phi[16], plo[16];
#pragma unroll
        for (int nt = 0; nt < 8; ++nt) {
            uint2 t01 = split2_h(s4[nt].x, s4[nt].y);
            uint2 t23 = split2_h(s4[nt].z, s4[nt].w);
            phi[2 * nt] = t01.x;  plo[2 * nt] = t01.y;
            phi[2 * nt + 1] = t23.x;  plo[2 * nt + 1] = t23.y;
        }

        const int mgrp = lane >> 3, lr2 = lane & 7;
#pragma unroll
        for (int t2 = 0; t2 < 4; ++t2) {
            unsigned pa0 = phi[4 * t2], pa1 = phi[4 * t2 + 1];
            unsigned pa2 = phi[4 * t2 + 2], pa3 = phi[4 * t2 + 3];
            unsigned pb0 = plo[4 * t2], pb1 = plo[4 * t2 + 1];
            unsigned pb2 = plo[4 * t2 + 2], pb3 = plo[4 * t2 + 3];
#pragma unroll
            for (int nb = 0; nb < 8; ++nb) {
                int s = 16 * t2 + ((mgrp & 1) << 3) + lr2;
                int cb = 2 * nb + (mgrp >> 1);
                unsigned off = (unsigned)(s * 64 + ((cb ^ (s & 7)) << 2)) * 4u;
                unsigned h0, h1, h2, h3;
                asm volatile("ldmatrix.sync.aligned.m8n8.x4.trans.shared.b16 "
                             "{%0,%1,%2,%3}, [%4];"
                             : "=r"(h0), "=r"(h1), "=r"(h2), "=r"(h3)
                             : "r"(VB + off));
                mma_f16(O[2 * nb], pa0, pa1, pa2, pa3, h0, h1);
                mma_f16(O[2 * nb], pb0, pb1, pb2, pb3, h0, h1);
                mma_f16(O[2 * nb + 1], pa0, pa1, pa2, pa3, h2, h3);
                mma_f16(O[2 * nb + 1], pb0, pb1, pb2, pb3, h2, h3);
            }
        }
        __syncthreads();
    }

    // epilogue: normalize + plain fp16 pack (A-side of Wo GEMM)
    float inv0 = 1.0f / l0, inv1 = 1.0f / l1;
    size_t p0 = (qrow0 + w * 16 + gr) * RWU + h * 64;
    size_t p1 = p0 + (size_t)8 * RWU;
#pragma unroll
    for (int j = 0; j < 16; ++j) {
        int pc = j * 4 + q4;
        As1[p0 + pc] = pack_f16x2(O[j].x * inv0, O[j].y * inv0);
        As1[p1 + pc] = pack_f16x2(O[j].z * inv1, O[j].w * inv1);
    }
}

// ---------------------------------------------------------------------------
extern "C" void kernel_launch(void* const* d_in, const int* in_sizes, int n_in,
                              void* d_out, int out_size) {
    const float* x  = (const float*)d_in[0];
    const float* Wq = (const float*)d_in[1];
    const float* Wk = (const float*)d_in[2];
    const float* Wv = (const float*)d_in[3];
    const float* Wo = (const float*)d_in[4];
    float* out = (float*)d_out;

    unsigned *xs, *as, *ws, *v1, *ks1;
    uint2 *qs2;
    cudaGetSymbolAddress((void**)&xs, g_xs);
    cudaGetSymbolAddress((void**)&as, g_as);
    cudaGetSymbolAddress((void**)&ws, g_ws);
    cudaGetSymbolAddress((void**)&v1, g_v1);
    cudaGetSymbolAddress((void**)&ks1, g_ks1);
    cudaGetSymbolAddress((void**)&qs2, g_qs2);

    rope_tables_kernel<<<(SEQ * 64) / 256, 256>>>();

    const int XP = ROWS * DM / 2;
    const int WP = DM * DM / 2;
    wpack_kernel<<<XP / 256, 256>>>(x, xs, XP);
    wpack_kernel<<<WP / 256, 256>>>(Wq, ws, WP);
    wpack_kernel<<<WP / 256, 256>>>(Wk, ws + WU, WP);
    wpack_kernel<<<WP / 256, 256>>>(Wv, ws + 2 * WU, WP);

    cudaFuncSetAttribute(mgemm_h1, cudaFuncAttributeMaxDynamicSharedMemorySize,
                         MG_SMEM_BYTES);
    // QKV mega-GEMM: bx 0-15 -> Q, 16-31 -> K, 32-47 -> V
    mgemm_h1<<<dim3(48, 64), 256, MG_SMEM_BYTES>>>(xs, ws, -1, nullptr,
                                                   v1, qs2, ks1);

    cudaFuncSetAttribute(flash_mma, cudaFuncAttributeMaxDynamicSharedMemorySize,
                         FL_SMEM_BYTES);
    flash_mma<<<dim3(SEQ / 128, BATCH * NH), 256, FL_SMEM_BYTES>>>(
        qs2, ks1, v1, as);

    wpack_kernel<<<WP / 256, 256>>>(Wo, ws, WP);
    mgemm_h1<<<dim3(16, 64), 256, MG_SMEM_BYTES>>>(as, ws, 0, out,
                                                   nullptr, nullptr, nullptr);
}

// round 11
// speedup vs baseline: 5.3681x; 1.1514x over previous
#include <cuda_runtime.h>
#include <cuda_fp16.h>
#include <math.h>

// ---------------------------------------------------------------------------
// Fused causal MHA forward — plain-fp16 mma.sync everywhere.
//   GEMMs: A,B plain fp16 (1 MMA/tile), 3-stage cp.async ring, fused epilogues.
//   Flash: 128 q-rows/CTA, plain fp16 QK and PV, K/V double-buffered, 2 CTA/SM.
// ---------------------------------------------------------------------------

#define SEQ   4096
#define BATCH 2
#define DM    2048
#define NH    16
#define DH    128
#define ROWS  (BATCH * SEQ)      // 8192
#define WU    (DM * DM / 2)      // u32 per packed weight plane
#define RWU   (DM / 2)           // u32 per packed activation row

__device__ float    g_cos[SEQ * 64];
__device__ float    g_sin[SEQ * 64];
__device__ unsigned g_xs[ROWS * RWU];       // x plain fp16
__device__ unsigned g_as[ROWS * RWU];       // attn out plain fp16
__device__ unsigned g_ws[3 * WU];           // Wq|Wk|Wv plain fp16 (Wo reuses [0])
__device__ unsigned g_qs1[ROWS * 1024];     // Q rope+scale, plain fp16
__device__ unsigned g_ks1[ROWS * 1024];     // K rope, plain fp16
__device__ unsigned g_v1[ROWS * 1024];      // V plain fp16 plane

// ---------------------------------------------------------------------------
__device__ __forceinline__ void mma_f16(float4& c,
                                        unsigned a0, unsigned a1, unsigned a2, unsigned a3,
                                        unsigned b0, unsigned b1) {
    asm("mma.sync.aligned.m16n8k16.row.col.f32.f16.f16.f32 "
        "{%0,%1,%2,%3}, {%4,%5,%6,%7}, {%8,%9}, {%0,%1,%2,%3};"
        : "+f"(c.x), "+f"(c.y), "+f"(c.z), "+f"(c.w)
        : "r"(a0), "r"(a1), "r"(a2), "r"(a3), "r"(b0), "r"(b1));
}

__device__ __forceinline__ unsigned pack_f16x2(float x, float y) {
    __half2 h = __floats2half2_rn(x, y);
    return *(unsigned*)&h;
}

// ---------------------------------------------------------------------------
__global__ void rope_tables_kernel() {
    int idx = blockIdx.x * blockDim.x + threadIdx.x;
    int s = idx >> 6, i = idx & 63;
    double invd = pow(10000.0, -((double)(2 * i)) / 128.0);
    float arg = (float)s * (float)invd;
    double sv, cv;
    sincos((double)arg, &sv, &cv);
    g_cos[idx] = (float)cv;
    g_sin[idx] = (float)sv;
}

// fp32 -> plain fp16 packed pairs.
__global__ void wpack_kernel(const float* __restrict__ s, unsigned* __restrict__ d,
                             int npairs) {
    int p = blockIdx.x * blockDim.x + threadIdx.x;
    if (p >= npairs) return;
    float2 v = *(const float2*)&s[2 * p];
    d[p] = pack_f16x2(v.x, v.y);
}

// ---------------------------------------------------------------------------
// GEMM C[m,n] = sum_k A[m,k]*B[n,k]. Both plain fp16 -> 1 MMA/tile.
// 128x128 CTA tile, 8 warps (2x4), warp 64x32, k32 stages, 3-stage ring.
// modes: 0 = fp32 C; -1 = per bx>>4: 0->Q(rope+scale), 1->K(rope), 2->V.
// ---------------------------------------------------------------------------
#define MG_P_U    2560                        // 128 rows x 20 u32
#define MG_STAGEU (2 * MG_P_U)                // 5120 u32
#define MG_SMEM_BYTES (3 * MG_STAGEU * 4)     // 61440
#define MG_KT     (DM / 32)                   // 64

__global__ __launch_bounds__(256, 2) void mgemm_h1(
        const unsigned* __restrict__ Ag, const unsigned* __restrict__ Bg,
        int modes, float* __restrict__ Cf,
        unsigned* __restrict__ Pv,
        unsigned* __restrict__ Pq, unsigned* __restrict__ Pk) {
    extern __shared__ unsigned sm[];
    const unsigned sbase = (unsigned)__cvta_generic_to_shared(sm);
    const int tid = threadIdx.x, wid = tid >> 5, lane = tid & 31;
    const int wm = wid >> 2, wn = wid & 3, g8 = lane >> 2, qd = lane & 3;
    const int bx = blockIdx.x, by = blockIdx.y;

    const int br0 = tid >> 2, bc0 = (tid & 3) << 2;
    const unsigned* sA = Ag + (size_t)(by * 128 + br0) * RWU + bc0;
    const unsigned* sB = Bg + (size_t)(bx * 128 + br0) * RWU + bc0;
    const unsigned dA0 = sbase + (unsigned)(br0 * 20 + bc0) * 4u;
    const unsigned dB0 = dA0 + MG_P_U * 4u;

    auto load_stage = [&](unsigned bufB, int kt) {
        const unsigned* a = sA + kt * 16;
        const unsigned* b = sB + kt * 16;
#pragma unroll
        for (int l = 0; l < 2; ++l) {
            asm volatile("cp.async.cg.shared.global [%0], [%1], 16;"
                         :: "r"(dA0 + bufB + (unsigned)(l * 5120)),
                            "l"(a + (size_t)l * 64 * RWU));
            asm volatile("cp.async.cg.shared.global [%0], [%1], 16;"
                         :: "r"(dB0 + bufB + (unsigned)(l * 5120)),
                            "l"(b + (size_t)l * 64 * RWU));
        }
        asm volatile("cp.async.commit_group;");
    };

    float4 acc[4][4];
#pragma unroll
    for (int i = 0; i < 4; i++)
#pragma unroll
        for (int j = 0; j < 4; j++) acc[i][j] = make_float4(0.f, 0.f, 0.f, 0.f);

    const unsigned* Aw0 = sm + (wm * 64 + g8) * 20 + qd;
    const unsigned* Bw0 = sm + MG_P_U + (wn * 32 + g8) * 20 + qd;

    auto compute = [&](const unsigned* Aw, const unsigned* Bw) {
#pragma unroll
        for (int ks = 0; ks < 2; ++ks) {
            unsigned a0[4], a1[4], a2[4], a3[4];
#pragma unroll
            for (int mi = 0; mi < 4; ++mi) {
                const unsigned* p = Aw + mi * 320 + ks * 8;
                a0[mi] = p[0];
                a2[mi] = p[4];
                a1[mi] = p[160];
                a3[mi] = p[164];
            }
            unsigned b0[4], b1[4];
#pragma unroll
            for (int ni = 0; ni < 4; ++ni) {
                const unsigned* q = Bw + ni * 160 + ks * 8;
                b0[ni] = q[0];
                b1[ni] = q[4];
            }
#pragma unroll
            for (int mi = 0; mi < 4; ++mi)
#pragma unroll
                for (int ni = 0; ni < 4; ++ni)
                    mma_f16(acc[mi][ni], a0[mi], a1[mi], a2[mi], a3[mi],
                            b0[ni], b1[ni]);
        }
    };

    load_stage(0, 0);
    load_stage(MG_STAGEU * 4u, 1);
    int cs = 0, ls = 2;
#pragma unroll 1
    for (int kt = 0; kt < MG_KT; ++kt) {
        if (kt + 1 < MG_KT) asm volatile("cp.async.wait_group 1;");
        else                asm volatile("cp.async.wait_group 0;");
        __syncthreads();
        if (kt + 2 < MG_KT) {
            load_stage((unsigned)(ls * MG_STAGEU) * 4u, kt + 2);
            ls = (ls == 2) ? 0 : ls + 1;
        }
        compute(Aw0 + cs * MG_STAGEU, Bw0 + cs * MG_STAGEU);
        cs = (cs == 2) ? 0 : cs + 1;
    }

    int mode, bxl;
    if (modes >= 0) { mode = modes; bxl = bx; }
    else { int r = bx >> 4; mode = (r == 0) ? 2 : (r == 1 ? 3 : 1); bxl = bx & 15; }
    const float SC = 0.08838834764831845f;   // 1/sqrt(128)

#pragma unroll
    for (int mi = 0; mi < 4; ++mi)
#pragma unroll
        for (int ni = 0; ni < 4; ++ni) {
            int r0 = by * 128 + wm * 64 + mi * 16 + g8;
            int c0 = bxl * 128 + wn * 32 + ni * 8 + 2 * qd;
            float4 v = acc[mi][ni];
            if (mode == 0) {
                *(float2*)&Cf[(size_t)r0 * DM + c0] = make_float2(v.x, v.y);
                *(float2*)&Cf[(size_t)(r0 + 8) * DM + c0] = make_float2(v.z, v.w);
            } else if (mode == 1) {        // V plain fp16 plane
                int pA = r0 * 1024 + (c0 >> 1);
                Pv[pA] = pack_f16x2(v.x, v.y);
                Pv[pA + 8192] = pack_f16x2(v.z, v.w);
            } else {                        // Q/K: rope (+scale), plain fp16
                int i = (c0 & 127) >> 1;
                int s0 = r0 & (SEQ - 1);
                float c_ = g_cos[(s0 << 6) + i], sn = g_sin[(s0 << 6) + i];
                float c1 = g_cos[((s0 + 8) << 6) + i], s1 = g_sin[((s0 + 8) << 6) + i];
                float x0 = v.x * c_ - v.y * sn, y0 = v.y * c_ + v.x * sn;
                float x1 = v.z * c1 - v.w * s1, y1 = v.w * c1 + v.z * s1;
                int pA = r0 * 1024 + (c0 >> 1);
                if (mode == 2) {
                    x0 *= SC; y0 *= SC; x1 *= SC; y1 *= SC;
                    Pq[pA] = pack_f16x2(x0, y0);
                    Pq[pA + 8192] = pack_f16x2(x1, y1);
                } else {
                    Pk[pA] = pack_f16x2(x0, y0);
                    Pk[pA + 8192] = pack_f16x2(x1, y1);
                }
            }
        }
}

// ---------------------------------------------------------------------------
// Flash attention: 128 q-rows per CTA (256 thr, 8 warps, 16 rows/warp),
// 64-key tiles, plain fp16 QK + PV, K/V double-buffered, 100KB smem ->
// 2 CTAs/SM.
// ---------------------------------------------------------------------------
#define FL_Q_U     (128 * 68)                 // 8704 u32
#define FLK_U      (64 * 68)
#define FLV_U      (64 * 64)
#define FL_STAGE_U (FLK_U + FLV_U)            // 8448 u32
#define FL_SMEM_BYTES ((FL_Q_U + 2 * FL_STAGE_U) * 4)   // 102400

__global__ __launch_bounds__(256, 2) void flash_mma(const unsigned* __restrict__ qs1,
                                                    const unsigned* __restrict__ ks1,
                                                    const unsigned* __restrict__ v1,
                                                    unsigned* __restrict__ As1) {
    extern __shared__ unsigned su[];
    unsigned* Qs = su;                        // [128][68]
    const unsigned sb  = (unsigned)__cvta_generic_to_shared(su);
    const unsigned QsB = sb;
    const unsigned St0 = sb + FL_Q_U * 4;

    const int tid = threadIdx.x, lane = tid & 31, w = tid >> 5;
    const int gr = lane >> 2, q4 = lane & 3;
    const int qi = (int)gridDim.x - 1 - (int)blockIdx.x;   // longest first
    const int bh = blockIdx.y;
    const int b = bh >> 4, h = bh & 15;
    const size_t qrow0 = (size_t)(b * SEQ + qi * 128);
    const int ktmax = 2 * qi + 1;

    // Q tile: 128 rows x 16 chunks = 2048
#pragma unroll
    for (int it = 0; it < 8; ++it) {
        int c = tid + it * 256;
        int r = c >> 4, ch = c & 15;
        const unsigned* src = qs1 + (qrow0 + r) * 1024 + h * 64 + ch * 4;
        unsigned dst = QsB + (unsigned)(r * 68 + ch * 4) * 4u;
        asm volatile("cp.async.cg.shared.global [%0], [%1], 16;" :: "r"(dst), "l"(src));
    }
    asm volatile("cp.async.commit_group;");

    auto load_kv = [&](int s, int kt) {
        const size_t krow0 = (size_t)(b * SEQ + kt * 64);
        const unsigned KB = St0 + (unsigned)(s * FL_STAGE_U) * 4u;
        const unsigned VB = KB + FLK_U * 4u;
#pragma unroll
        for (int it = 0; it < 4; ++it) {
            int c = tid + it * 256;
            int r = c >> 4, ch = c & 15;
            const unsigned* src = ks1 + (krow0 + r) * 1024 + h * 64 + ch * 4;
            asm volatile("cp.async.cg.shared.global [%0], [%1], 16;"
                         :: "r"(KB + (unsigned)(r * 68 + ch * 4) * 4u), "l"(src));
        }
#pragma unroll
        for (int it = 0; it < 4; ++it) {
            int c = tid + it * 256;
            int s_ = c >> 4, cb = c & 15;
            unsigned soff = (unsigned)(s_ * 64 + ((cb ^ (s_ & 7)) << 2)) * 4u;
            const unsigned* src = v1 + (krow0 + s_) * 1024 + h * 64 + cb * 4;
            asm volatile("cp.async.cg.shared.global [%0], [%1], 16;"
                         :: "r"(VB + soff), "l"(src));
        }
        asm volatile("cp.async.commit_group;");
    };

    load_kv(0, 0);

    float4 O[16];
#pragma unroll
    for (int j = 0; j < 16; ++j) O[j] = make_float4(0.f, 0.f, 0.f, 0.f);
    float m0 = -INFINITY, m1 = -INFINITY, l0 = 0.f, l1 = 0.f;

    for (int kt = 0; kt <= ktmax; ++kt) {
        if (kt + 1 <= ktmax) {
            load_kv((kt + 1) & 1, kt + 1);
            asm volatile("cp.async.wait_group 1;");
        } else {
            asm volatile("cp.async.wait_group 0;");
        }
        __syncthreads();

        const int st = kt & 1;
        const unsigned* Ks = su + FL_Q_U + st * FL_STAGE_U;
        const unsigned VB = St0 + (unsigned)(st * FL_STAGE_U + FLK_U) * 4u;

        // ---- S = Q K^T (plain fp16, 1 MMA per 8-key tile per k16) ----
        float4 s4[8];
#pragma unroll
        for (int nt = 0; nt < 8; ++nt) s4[nt] = make_float4(0.f, 0.f, 0.f, 0.f);

        const int prow = w * 16 + gr;
#pragma unroll
        for (int t = 0; t < 8; ++t) {
            unsigned a0 = Qs[prow * 68 + 8 * t + q4];
            unsigned a1 = Qs[(prow + 8) * 68 + 8 * t + q4];
            unsigned a2 = Qs[prow * 68 + 8 * t + q4 + 4];
            unsigned a3 = Qs[(prow + 8) * 68 + 8 * t + q4 + 4];
#pragma unroll
            for (int nt = 0; nt < 8; ++nt) {
                int key = nt * 8 + gr;
                unsigned b0 = Ks[key * 68 + 8 * t + q4];
                unsigned b1 = Ks[key * 68 + 8 * t + q4 + 4];
                mma_f16(s4[nt], a0, a1, a2, a3, b0, b1);
            }
        }

        if (kt >= 2 * qi) {   // causal mask: only last two tiles
            int off = (kt - 2 * qi) * 64;
            int r0 = w * 16 + gr, r1 = r0 + 8;
#pragma unroll
            for (int nt = 0; nt < 8; ++nt) {
                int c0 = nt * 8 + 2 * q4 + off;
                if (c0 > r0)     s4[nt].x = -INFINITY;
                if (c0 + 1 > r0) s4[nt].y = -INFINITY;
                if (c0 > r1)     s4[nt].z = -INFINITY;
                if (c0 + 1 > r1) s4[nt].w = -INFINITY;
            }
        }

        float mx0 = -INFINITY, mx1 = -INFINITY;
#pragma unroll
        for (int nt = 0; nt < 8; ++nt) {
            mx0 = fmaxf(mx0, fmaxf(s4[nt].x, s4[nt].y));
            mx1 = fmaxf(mx1, fmaxf(s4[nt].z, s4[nt].w));
        }
        mx0 = fmaxf(mx0, __shfl_xor_sync(0xffffffffu, mx0, 1));
        mx0 = fmaxf(mx0, __shfl_xor_sync(0xffffffffu, mx0, 2));
        mx1 = fmaxf(mx1, __shfl_xor_sync(0xffffffffu, mx1, 1));
        mx1 = fmaxf(mx1, __shfl_xor_sync(0xffffffffu, mx1, 2));
        float nm0 = fmaxf(m0, mx0), nm1 = fmaxf(m1, mx1);
        float al0 = __expf(m0 - nm0), al1 = __expf(m1 - nm1);
        m0 = nm0; m1 = nm1;

        float sum0 = 0.f, sum1 = 0.f;
#pragma unroll
        for (int nt = 0; nt < 8; ++nt) {
            s4[nt].x = __expf(s4[nt].x - nm0);
            s4[nt].y = __expf(s4[nt].y - nm0);
            s4[nt].z = __expf(s4[nt].z - nm1);
            s4[nt].w = __expf(s4[nt].w - nm1);
            sum0 += s4[nt].x + s4[nt].y;
            sum1 += s4[nt].z + s4[nt].w;
        }
        sum0 += __shfl_xor_sync(0xffffffffu, sum0, 1);
        sum0 += __shfl_xor_sync(0xffffffffu, sum0, 2);
        sum1 += __shfl_xor_sync(0xffffffffu, sum1, 1);
        sum1 += __shfl_xor_sync(0xffffffffu, sum1, 2);
        l0 = l0 * al0 + sum0;
        l1 = l1 * al1 + sum1;
#pragma unroll
        for (int j = 0; j < 16; ++j) {
            O[j].x *= al0; O[j].y *= al0; O[j].z *= al1; O[j].w *= al1;
        }

        // ---- P plain fp16; O += P V ----
        unsigned phi[16];
#pragma unroll
        for (int nt = 0; nt < 8; ++nt) {
            phi[2 * nt]     = pack_f16x2(s4[nt].x, s4[nt].y);
            phi[2 * nt + 1] = pack_f16x2(s4[nt].z, s4[nt].w);
        }

        const int mgrp = lane >> 3, lr2 = lane & 7;
#pragma unroll
        for (int t2 = 0; t2 < 4; ++t2) {
            unsigned pa0 = phi[4 * t2], pa1 = phi[4 * t2 + 1];
            unsigned pa2 = phi[4 * t2 + 2], pa3 = phi[4 * t2 + 3];
#pragma unroll
            for (int nb = 0; nb < 8; ++nb) {
                int s = 16 * t2 + ((mgrp & 1) << 3) + lr2;
                int cb = 2 * nb + (mgrp >> 1);
                unsigned off = (unsigned)(s * 64 + ((cb ^ (s & 7)) << 2)) * 4u;
                unsigned h0, h1, h2, h3;
                asm volatile("ldmatrix.sync.aligned.m8n8.x4.trans.shared.b16 "
                             "{%0,%1,%2,%3}, [%4];"
                             : "=r"(h0), "=r"(h1), "=r"(h2), "=r"(h3)
                             : "r"(VB + off));
                mma_f16(O[2 * nb], pa0, pa1, pa2, pa3, h0, h1);
                mma_f16(O[2 * nb + 1], pa0, pa1, pa2, pa3, h2, h3);
            }
        }
        __syncthreads();
    }

    // epilogue: normalize + plain fp16 pack (A-side of Wo GEMM)
    float inv0 = 1.0f / l0, inv1 = 1.0f / l1;
    size_t p0 = (qrow0 + w * 16 + gr) * RWU + h * 64;
    size_t p1 = p0 + (size_t)8 * RWU;
#pragma unroll
    for (int j = 0; j < 16; ++j) {
        int pc = j * 4 + q4;
        As1[p0 + pc] = pack_f16x2(O[j].x * inv0, O[j].y * inv0);
        As1[p1 + pc] = pack_f16x2(O[j].z * inv1, O[j].w * inv1);
    }
}

// ---------------------------------------------------------------------------
extern "C" void kernel_launch(void* const* d_in, const int* in_sizes, int n_in,
                              void* d_out, int out_size) {
    const float* x  = (const float*)d_in[0];
    const float* Wq = (const float*)d_in[1];
    const float* Wk = (const float*)d_in[2];
    const float* Wv = (const float*)d_in[3];
    const float* Wo = (const float*)d_in[4];
    float* out = (float*)d_out;

    unsigned *xs, *as, *ws, *v1, *ks1, *qs1;
    cudaGetSymbolAddress((void**)&xs, g_xs);
    cudaGetSymbolAddress((void**)&as, g_as);
    cudaGetSymbolAddress((void**)&ws, g_ws);
    cudaGetSymbolAddress((void**)&v1, g_v1);
    cudaGetSymbolAddress((void**)&ks1, g_ks1);
    cudaGetSymbolAddress((void**)&qs1, g_qs1);

    rope_tables_kernel<<<(SEQ * 64) / 256, 256>>>();

    const int XP = ROWS * DM / 2;
    const int WP = DM * DM / 2;
    wpack_kernel<<<XP / 256, 256>>>(x, xs, XP);
    wpack_kernel<<<WP / 256, 256>>>(Wq, ws, WP);
    wpack_kernel<<<WP / 256, 256>>>(Wk, ws + WU, WP);
    wpack_kernel<<<WP / 256, 256>>>(Wv, ws + 2 * WU, WP);

    cudaFuncSetAttribute(mgemm_h1, cudaFuncAttributeMaxDynamicSharedMemorySize,
                         MG_SMEM_BYTES);
    // QKV mega-GEMM: bx 0-15 -> Q, 16-31 -> K, 32-47 -> V
    mgemm_h1<<<dim3(48, 64), 256, MG_SMEM_BYTES>>>(xs, ws, -1, nullptr,
                                                   v1, qs1, ks1);

    cudaFuncSetAttribute(flash_mma, cudaFuncAttributeMaxDynamicSharedMemorySize,
                         FL_SMEM_BYTES);
    flash_mma<<<dim3(SEQ / 128, BATCH * NH), 256, FL_SMEM_BYTES>>>(
        qs1, ks1, v1, as);

    wpack_kernel<<<WP / 256, 256>>>(Wo, ws, WP);
    mgemm_h1<<<dim3(16, 64), 256, MG_SMEM_BYTES>>>(as, ws, 0, out,
                                                   nullptr, nullptr, nullptr);
}

// round 12
// speedup vs baseline: 6.0312x; 1.1235x over previous
#include <cuda_runtime.h>
#include <cuda_fp16.h>
#include <math.h>

// ---------------------------------------------------------------------------
// Fused causal MHA forward — plain-fp16 mma.sync, ldmatrix fragment loads.
//   GEMMs: A,B plain fp16 (1 MMA/tile), 3-stage cp.async ring, fused epilogues.
//   Flash: 128 q-rows/CTA, plain fp16 QK+PV, K/V double-buffered, 2 CTA/SM.
// ---------------------------------------------------------------------------

#define SEQ   4096
#define BATCH 2
#define DM    2048
#define NH    16
#define DH    128
#define ROWS  (BATCH * SEQ)      // 8192
#define WU    (DM * DM / 2)      // u32 per packed weight plane
#define RWU   (DM / 2)           // u32 per packed activation row

__device__ float    g_cos[SEQ * 64];
__device__ float    g_sin[SEQ * 64];
__device__ unsigned g_xs[ROWS * RWU];       // x plain fp16
__device__ unsigned g_as[ROWS * RWU];       // attn out plain fp16
__device__ unsigned g_ws[4 * WU];           // Wq|Wk|Wv|Wo plain fp16
__device__ unsigned g_qs1[ROWS * 1024];     // Q rope+scale, plain fp16
__device__ unsigned g_ks1[ROWS * 1024];     // K rope, plain fp16
__device__ unsigned g_v1[ROWS * 1024];      // V plain fp16 plane

// ---------------------------------------------------------------------------
__device__ __forceinline__ void mma_f16(float4& c,
                                        unsigned a0, unsigned a1, unsigned a2, unsigned a3,
                                        unsigned b0, unsigned b1) {
    asm("mma.sync.aligned.m16n8k16.row.col.f32.f16.f16.f32 "
        "{%0,%1,%2,%3}, {%4,%5,%6,%7}, {%8,%9}, {%0,%1,%2,%3};"
        : "+f"(c.x), "+f"(c.y), "+f"(c.z), "+f"(c.w)
        : "r"(a0), "r"(a1), "r"(a2), "r"(a3), "r"(b0), "r"(b1));
}

__device__ __forceinline__ void ldsm_x4(uint4& r, unsigned addr) {
    asm volatile("ldmatrix.sync.aligned.m8n8.x4.shared.b16 {%0,%1,%2,%3}, [%4];"
                 : "=r"(r.x), "=r"(r.y), "=r"(r.z), "=r"(r.w) : "r"(addr));
}

__device__ __forceinline__ unsigned pack_f16x2(float x, float y) {
    __half2 h = __floats2half2_rn(x, y);
    return *(unsigned*)&h;
}

// ---------------------------------------------------------------------------
__global__ void rope_tables_kernel() {
    int idx = blockIdx.x * blockDim.x + threadIdx.x;
    int s = idx >> 6, i = idx & 63;
    double invd = pow(10000.0, -((double)(2 * i)) / 128.0);
    float arg = (float)s * (float)invd;
    double sv, cv;
    sincos((double)arg, &sv, &cv);
    g_cos[idx] = (float)cv;
    g_sin[idx] = (float)sv;
}

// One launch packs x + all four weights to fp16.
__global__ void packall_kernel(const float* __restrict__ x,
                               const float* __restrict__ Wq,
                               const float* __restrict__ Wk,
                               const float* __restrict__ Wv,
                               const float* __restrict__ Wo,
                               unsigned* __restrict__ xs,
                               unsigned* __restrict__ ws) {
    int p = blockIdx.x * blockDim.x + threadIdx.x;
    const int XP = ROWS * RWU;     // 8388608 pairs in x
    const float* src;
    unsigned* dst;
    int off;
    if (p < XP) {
        src = x; dst = xs; off = p;
    } else {
        int q = p - XP;
        int wsel = q >> 21;                 // WP = 2^21
        off = q & (WU - 1);
        src = (wsel == 0) ? Wq : (wsel == 1) ? Wk : (wsel == 2) ? Wv : Wo;
        dst = ws + wsel * WU;
    }
    float2 v = *(const float2*)&src[2 * off];
    dst[off] = pack_f16x2(v.x, v.y);
}

// ---------------------------------------------------------------------------
// GEMM C[m,n] = sum_k A[m,k]*B[n,k]. Both plain fp16, ldmatrix fragments.
// 128x128 CTA tile, 8 warps (2x4), warp 64x32, k32 stages, 3-stage ring.
// modes: 0 = fp32 C; -1 = per bx>>4: 0->Q(rope+scale), 1->K(rope), 2->V.
// ---------------------------------------------------------------------------
#define MG_P_U    2560                        // 128 rows x 20 u32
#define MG_STAGEU (2 * MG_P_U)                // 5120 u32
#define MG_SMEM_BYTES (3 * MG_STAGEU * 4)     // 61440
#define MG_KT     (DM / 32)                   // 64

__global__ __launch_bounds__(256, 2) void mgemm_h1(
        const unsigned* __restrict__ Ag, const unsigned* __restrict__ Bg,
        int modes, float* __restrict__ Cf,
        unsigned* __restrict__ Pv,
        unsigned* __restrict__ Pq, unsigned* __restrict__ Pk) {
    extern __shared__ unsigned sm[];
    const unsigned sbase = (unsigned)__cvta_generic_to_shared(sm);
    const int tid = threadIdx.x, wid = tid >> 5, lane = tid & 31;
    const int wm = wid >> 2, wn = wid & 3, g8 = lane >> 2, qd = lane & 3;
    const int bx = blockIdx.x, by = blockIdx.y;

    const int br0 = tid >> 2, bc0 = (tid & 3) << 2;
    const unsigned* sA = Ag + (size_t)(by * 128 + br0) * RWU + bc0;
    const unsigned* sB = Bg + (size_t)(bx * 128 + br0) * RWU + bc0;
    const unsigned dA0 = sbase + (unsigned)(br0 * 20 + bc0) * 4u;
    const unsigned dB0 = dA0 + MG_P_U * 4u;

    auto load_stage = [&](unsigned bufB, int kt) {
        const unsigned* a = sA + kt * 16;
        const unsigned* b = sB + kt * 16;
#pragma unroll
        for (int l = 0; l < 2; ++l) {
            asm volatile("cp.async.cg.shared.global [%0], [%1], 16;"
                         :: "r"(dA0 + bufB + (unsigned)(l * 5120)),
                            "l"(a + (size_t)l * 64 * RWU));
            asm volatile("cp.async.cg.shared.global [%0], [%1], 16;"
                         :: "r"(dB0 + bufB + (unsigned)(l * 5120)),
                            "l"(b + (size_t)l * 64 * RWU));
        }
        asm volatile("cp.async.commit_group;");
    };

    float4 acc[4][4];
#pragma unroll
    for (int i = 0; i < 4; i++)
#pragma unroll
        for (int j = 0; j < 4; j++) acc[i][j] = make_float4(0.f, 0.f, 0.f, 0.f);

    // ldmatrix lane addresses (bytes):
    //  A x4: lanes 0-7 rows r0-7 k0 | 8-15 r8-15 k0 | 16-23 r0-7 k8 | 24-31 r8-15 k8
    const int lrow16 = lane & 15, lkh = lane >> 4;
    const unsigned aLd0 = sbase
        + (unsigned)(((wm * 64 + lrow16) * 20 + lkh * 4) * 4);
    //  B x4: groups (pairhalf, khalf) -> (b0 ni, b1 ni, b0 ni+1, b1 ni+1)
    const int bg = lane >> 3, brow = lane & 7;
    const unsigned bLd0 = sbase
        + (unsigned)((MG_P_U + (wn * 32 + (bg >> 1) * 8 + brow) * 20 + (bg & 1) * 4) * 4);

    auto compute = [&](unsigned so) {
#pragma unroll
        for (int ks = 0; ks < 2; ++ks) {
            uint4 af[4];
#pragma unroll
            for (int mi = 0; mi < 4; ++mi)
                ldsm_x4(af[mi], aLd0 + so + (unsigned)((mi * 320 + ks * 8) * 4));
            uint4 bf[2];
#pragma unroll
            for (int np = 0; np < 2; ++np)
                ldsm_x4(bf[np], bLd0 + so + (unsigned)((np * 320 + ks * 8) * 4));
#pragma unroll
            for (int mi = 0; mi < 4; ++mi) {
                mma_f16(acc[mi][0], af[mi].x, af[mi].y, af[mi].z, af[mi].w,
                        bf[0].x, bf[0].y);
                mma_f16(acc[mi][1], af[mi].x, af[mi].y, af[mi].z, af[mi].w,
                        bf[0].z, bf[0].w);
                mma_f16(acc[mi][2], af[mi].x, af[mi].y, af[mi].z, af[mi].w,
                        bf[1].x, bf[1].y);
                mma_f16(acc[mi][3], af[mi].x, af[mi].y, af[mi].z, af[mi].w,
                        bf[1].z, bf[1].w);
            }
        }
    };

    load_stage(0, 0);
    load_stage(MG_STAGEU * 4u, 1);
    int cs = 0, ls = 2;
#pragma unroll 1
    for (int kt = 0; kt < MG_KT; ++kt) {
        if (kt + 1 < MG_KT) asm volatile("cp.async.wait_group 1;");
        else                asm volatile("cp.async.wait_group 0;");
        __syncthreads();
        if (kt + 2 < MG_KT) {
            load_stage((unsigned)(ls * MG_STAGEU) * 4u, kt + 2);
            ls = (ls == 2) ? 0 : ls + 1;
        }
        compute((unsigned)(cs * MG_STAGEU) * 4u);
        cs = (cs == 2) ? 0 : cs + 1;
    }

    int mode, bxl;
    if (modes >= 0) { mode = modes; bxl = bx; }
    else { int r = bx >> 4; mode = (r == 0) ? 2 : (r == 1 ? 3 : 1); bxl = bx & 15; }
    const float SC = 0.08838834764831845f;   // 1/sqrt(128)

#pragma unroll
    for (int mi = 0; mi < 4; ++mi)
#pragma unroll
        for (int ni = 0; ni < 4; ++ni) {
            int r0 = by * 128 + wm * 64 + mi * 16 + g8;
            int c0 = bxl * 128 + wn * 32 + ni * 8 + 2 * qd;
            float4 v = acc[mi][ni];
            if (mode == 0) {
                *(float2*)&Cf[(size_t)r0 * DM + c0] = make_float2(v.x, v.y);
                *(float2*)&Cf[(size_t)(r0 + 8) * DM + c0] = make_float2(v.z, v.w);
            } else if (mode == 1) {        // V plain fp16 plane
                int pA = r0 * 1024 + (c0 >> 1);
                Pv[pA] = pack_f16x2(v.x, v.y);
                Pv[pA + 8192] = pack_f16x2(v.z, v.w);
            } else {                        // Q/K: rope (+scale), plain fp16
                int i = (c0 & 127) >> 1;
                int s0 = r0 & (SEQ - 1);
                float c_ = g_cos[(s0 << 6) + i], sn = g_sin[(s0 << 6) + i];
                float c1 = g_cos[((s0 + 8) << 6) + i], s1 = g_sin[((s0 + 8) << 6) + i];
                float x0 = v.x * c_ - v.y * sn, y0 = v.y * c_ + v.x * sn;
                float x1 = v.z * c1 - v.w * s1, y1 = v.w * c1 + v.z * s1;
                int pA = r0 * 1024 + (c0 >> 1);
                if (mode == 2) {
                    x0 *= SC; y0 *= SC; x1 *= SC; y1 *= SC;
                    Pq[pA] = pack_f16x2(x0, y0);
                    Pq[pA + 8192] = pack_f16x2(x1, y1);
                } else {
                    Pk[pA] = pack_f16x2(x0, y0);
                    Pk[pA + 8192] = pack_f16x2(x1, y1);
                }
            }
        }
}

// ---------------------------------------------------------------------------
// Flash attention: 128 q-rows/CTA (256 thr, 8 warps, 16 rows/warp), 64-key
// tiles, plain fp16 QK + PV, ldmatrix fragments, K/V dbuf, 2 CTAs/SM.
// ---------------------------------------------------------------------------
#define FL_Q_U     (128 * 68)                 // 8704 u32
#define FLK_U      (64 * 68)
#define FLV_U      (64 * 64)
#define FL_STAGE_U (FLK_U + FLV_U)            // 8448 u32
#define FL_SMEM_BYTES ((FL_Q_U + 2 * FL_STAGE_U) * 4)   // 102400

__global__ __launch_bounds__(256, 2) void flash_mma(const unsigned* __restrict__ qs1,
                                                    const unsigned* __restrict__ ks1,
                                                    const unsigned* __restrict__ v1,
                                                    unsigned* __restrict__ As1) {
    extern __shared__ unsigned su[];
    const unsigned sb  = (unsigned)__cvta_generic_to_shared(su);
    const unsigned QsB = sb;
    const unsigned St0 = sb + FL_Q_U * 4;

    const int tid = threadIdx.x, lane = tid & 31, w = tid >> 5;
    const int gr = lane >> 2, q4 = lane & 3;
    const int qi = (int)gridDim.x - 1 - (int)blockIdx.x;   // longest first
    const int bh = blockIdx.y;
    const int b = bh >> 4, h = bh & 15;
    const size_t qrow0 = (size_t)(b * SEQ + qi * 128);
    const int ktmax = 2 * qi + 1;

    // Q tile: 128 rows x 16 chunks
#pragma unroll
    for (int it = 0; it < 8; ++it) {
        int c = tid + it * 256;
        int r = c >> 4, ch = c & 15;
        const unsigned* src = qs1 + (qrow0 + r) * 1024 + h * 64 + ch * 4;
        unsigned dst = QsB + (unsigned)(r * 68 + ch * 4) * 4u;
        asm volatile("cp.async.cg.shared.global [%0], [%1], 16;" :: "r"(dst), "l"(src));
    }
    asm volatile("cp.async.commit_group;");

    auto load_kv = [&](int s, int kt) {
        const size_t krow0 = (size_t)(b * SEQ + kt * 64);
        const unsigned KB = St0 + (unsigned)(s * FL_STAGE_U) * 4u;
        const unsigned VB = KB + FLK_U * 4u;
#pragma unroll
        for (int it = 0; it < 4; ++it) {
            int c = tid + it * 256;
            int r = c >> 4, ch = c & 15;
            const unsigned* src = ks1 + (krow0 + r) * 1024 + h * 64 + ch * 4;
            asm volatile("cp.async.cg.shared.global [%0], [%1], 16;"
                         :: "r"(KB + (unsigned)(r * 68 + ch * 4) * 4u), "l"(src));
        }
#pragma unroll
        for (int it = 0; it < 4; ++it) {
            int c = tid + it * 256;
            int s_ = c >> 4, cb = c & 15;
            unsigned soff = (unsigned)(s_ * 64 + ((cb ^ (s_ & 7)) << 2)) * 4u;
            const unsigned* src = v1 + (krow0 + s_) * 1024 + h * 64 + cb * 4;
            asm volatile("cp.async.cg.shared.global [%0], [%1], 16;"
                         :: "r"(VB + soff), "l"(src));
        }
        asm volatile("cp.async.commit_group;");
    };

    load_kv(0, 0);

    // ldmatrix lane addresses
    const int lrow16 = lane & 15, lkh = lane >> 4;
    const unsigned qLd0 = QsB + (unsigned)(((w * 16 + lrow16) * 68 + lkh * 4) * 4);
    const int bg = lane >> 3, brow = lane & 7;
    const unsigned kLdLane = (unsigned)((((bg >> 1) * 8 + brow) * 68 + (bg & 1) * 4) * 4);

    float4 O[16];
#pragma unroll
    for (int j = 0; j < 16; ++j) O[j] = make_float4(0.f, 0.f, 0.f, 0.f);
    float m0 = -INFINITY, m1 = -INFINITY, l0 = 0.f, l1 = 0.f;

    for (int kt = 0; kt <= ktmax; ++kt) {
        if (kt + 1 <= ktmax) {
            load_kv((kt + 1) & 1, kt + 1);
            asm volatile("cp.async.wait_group 1;");
        } else {
            asm volatile("cp.async.wait_group 0;");
        }
        __syncthreads();

        const int st = kt & 1;
        const unsigned KBb = St0 + (unsigned)(st * FL_STAGE_U) * 4u;
        const unsigned VB = KBb + FLK_U * 4u;

        // ---- S = Q K^T (ldmatrix fragments) ----
        float4 s4[8];
#pragma unroll
        for (int nt = 0; nt < 8; ++nt) s4[nt] = make_float4(0.f, 0.f, 0.f, 0.f);

#pragma unroll
        for (int t = 0; t < 8; ++t) {
            uint4 aq;
            ldsm_x4(aq, qLd0 + (unsigned)(t * 32));
#pragma unroll
            for (int p = 0; p < 4; ++p) {
                uint4 kf;
                ldsm_x4(kf, KBb + kLdLane + (unsigned)(p * 4352 + t * 32));
                mma_f16(s4[2 * p],     aq.x, aq.y, aq.z, aq.w, kf.x, kf.y);
                mma_f16(s4[2 * p + 1], aq.x, aq.y, aq.z, aq.w, kf.z, kf.w);
            }
        }

        if (kt >= 2 * qi) {   // causal mask: only last two tiles
            int off = (kt - 2 * qi) * 64;
            int r0 = w * 16 + gr, r1 = r0 + 8;
#pragma unroll
            for (int nt = 0; nt < 8; ++nt) {
                int c0 = nt * 8 + 2 * q4 + off;
                if (c0 > r0)     s4[nt].x = -INFINITY;
                if (c0 + 1 > r0) s4[nt].y = -INFINITY;
                if (c0 > r1)     s4[nt].z = -INFINITY;
                if (c0 + 1 > r1) s4[nt].w = -INFINITY;
            }
        }

        float mx0 = -INFINITY, mx1 = -INFINITY;
#pragma unroll
        for (int nt = 0; nt < 8; ++nt) {
            mx0 = fmaxf(mx0, fmaxf(s4[nt].x, s4[nt].y));
            mx1 = fmaxf(mx1, fmaxf(s4[nt].z, s4[nt].w));
        }
        mx0 = fmaxf(mx0, __shfl_xor_sync(0xffffffffu, mx0, 1));
        mx0 = fmaxf(mx0, __shfl_xor_sync(0xffffffffu, mx0, 2));
        mx1 = fmaxf(mx1, __shfl_xor_sync(0xffffffffu, mx1, 1));
        mx1 = fmaxf(mx1, __shfl_xor_sync(0xffffffffu, mx1, 2));
        float nm0 = fmaxf(m0, mx0), nm1 = fmaxf(m1, mx1);
        float al0 = __expf(m0 - nm0), al1 = __expf(m1 - nm1);
        m0 = nm0; m1 = nm1;

        float sum0 = 0.f, sum1 = 0.f;
#pragma unroll
        for (int nt = 0; nt < 8; ++nt) {
            s4[nt].x = __expf(s4[nt].x - nm0);
            s4[nt].y = __expf(s4[nt].y - nm0);
            s4[nt].z = __expf(s4[nt].z - nm1);
            s4[nt].w = __expf(s4[nt].w - nm1);
            sum0 += s4[nt].x + s4[nt].y;
            sum1 += s4[nt].z + s4[nt].w;
        }
        sum0 += __shfl_xor_sync(0xffffffffu, sum0, 1);
        sum0 += __shfl_xor_sync(0xffffffffu, sum0, 2);
        sum1 += __shfl_xor_sync(0xffffffffu, sum1, 1);
        sum1 += __shfl_xor_sync(0xffffffffu, sum1, 2);
        l0 = l0 * al0 + sum0;
        l1 = l1 * al1 + sum1;
#pragma unroll
        for (int j = 0; j < 16; ++j) {
            O[j].x *= al0; O[j].y *= al0; O[j].z *= al1; O[j].w *= al1;
        }

        // ---- P plain fp16; O += P V ----
        unsigned phi[16];
#pragma unroll
        for (int nt = 0; nt < 8; ++nt) {
            phi[2 * nt]     = pack_f16x2(s4[nt].x, s4[nt].y);
            phi[2 * nt + 1] = pack_f16x2(s4[nt].z, s4[nt].w);
        }

        const int mgrp = lane >> 3, lr2 = lane & 7;
#pragma unroll
        for (int t2 = 0; t2 < 4; ++t2) {
            unsigned pa0 = phi[4 * t2], pa1 = phi[4 * t2 + 1];
            unsigned pa2 = phi[4 * t2 + 2], pa3 = phi[4 * t2 + 3];
#pragma unroll
            for (int nb = 0; nb < 8; ++nb) {
                int s = 16 * t2 + ((mgrp & 1) << 3) + lr2;
                int cb = 2 * nb + (mgrp >> 1);
                unsigned off = (unsigned)(s * 64 + ((cb ^ (s & 7)) << 2)) * 4u;
                unsigned h0, h1, h2, h3;
                asm volatile("ldmatrix.sync.aligned.m8n8.x4.trans.shared.b16 "
                             "{%0,%1,%2,%3}, [%4];"
                             : "=r"(h0), "=r"(h1), "=r"(h2), "=r"(h3)
                             : "r"(VB + off));
                mma_f16(O[2 * nb], pa0, pa1, pa2, pa3, h0, h1);
                mma_f16(O[2 * nb + 1], pa0, pa1, pa2, pa3, h2, h3);
            }
        }
        __syncthreads();
    }

    // epilogue: normalize + plain fp16 pack (A-side of Wo GEMM)
    float inv0 = 1.0f / l0, inv1 = 1.0f / l1;
    size_t p0 = (qrow0 + w * 16 + gr) * RWU + h * 64;
    size_t p1 = p0 + (size_t)8 * RWU;
#pragma unroll
    for (int j = 0; j < 16; ++j) {
        int pc = j * 4 + q4;
        As1[p0 + pc] = pack_f16x2(O[j].x * inv0, O[j].y * inv0);
        As1[p1 + pc] = pack_f16x2(O[j].z * inv1, O[j].w * inv1);
    }
}

// ---------------------------------------------------------------------------
extern "C" void kernel_launch(void* const* d_in, const int* in_sizes, int n_in,
                              void* d_out, int out_size) {
    const float* x  = (const float*)d_in[0];
    const float* Wq = (const float*)d_in[1];
    const float* Wk = (const float*)d_in[2];
    const float* Wv = (const float*)d_in[3];
    const float* Wo = (const float*)d_in[4];
    float* out = (float*)d_out;

    unsigned *xs, *as, *ws, *v1, *ks1, *qs1;
    cudaGetSymbolAddress((void**)&xs, g_xs);
    cudaGetSymbolAddress((void**)&as, g_as);
    cudaGetSymbolAddress((void**)&ws, g_ws);
    cudaGetSymbolAddress((void**)&v1, g_v1);
    cudaGetSymbolAddress((void**)&ks1, g_ks1);
    cudaGetSymbolAddress((void**)&qs1, g_qs1);

    rope_tables_kernel<<<(SEQ * 64) / 256, 256>>>();

    const int TOTALP = ROWS * RWU + 4 * WU;   // 16777216
    packall_kernel<<<TOTALP / 256, 256>>>(x, Wq, Wk, Wv, Wo, xs, ws);

    cudaFuncSetAttribute(mgemm_h1, cudaFuncAttributeMaxDynamicSharedMemorySize,
                         MG_SMEM_BYTES);
    // QKV mega-GEMM: bx 0-15 -> Q, 16-31 -> K, 32-47 -> V
    mgemm_h1<<<dim3(48, 64), 256, MG_SMEM_BYTES>>>(xs, ws, -1, nullptr,
                                                   v1, qs1, ks1);

    cudaFuncSetAttribute(flash_mma, cudaFuncAttributeMaxDynamicSharedMemorySize,
                         FL_SMEM_BYTES);
    flash_mma<<<dim3(SEQ / 128, BATCH * NH), 256, FL_SMEM_BYTES>>>(
        qs1, ks1, v1, as);

    mgemm_h1<<<dim3(16, 64), 256, MG_SMEM_BYTES>>>(as, ws + 3 * WU, 0, out,
                                                   nullptr, nullptr, nullptr);
}

// round 13
// speedup vs baseline: 6.4377x; 1.0674x over previous
#include <cuda_runtime.h>
#include <cuda_fp16.h>
#include <math.h>

// ---------------------------------------------------------------------------
// Fused causal MHA forward — plain-fp16 mma.sync, ldmatrix fragment loads.
//   GEMMs: k64 stages, 3-stage cp.async ring, fused epilogues.
//   Flash: 128 q-rows/CTA, batched ldmatrix (MLP>=4), K/V dbuf, 2 CTA/SM.
// ---------------------------------------------------------------------------

#define SEQ   4096
#define BATCH 2
#define DM    2048
#define NH    16
#define DH    128
#define ROWS  (BATCH * SEQ)      // 8192
#define WU    (DM * DM / 2)      // u32 per packed weight plane
#define RWU   (DM / 2)           // u32 per packed activation row

__device__ float    g_cos[SEQ * 64];
__device__ float    g_sin[SEQ * 64];
__device__ unsigned g_xs[ROWS * RWU];       // x plain fp16
__device__ unsigned g_as[ROWS * RWU];       // attn out plain fp16
__device__ unsigned g_ws[4 * WU];           // Wq|Wk|Wv|Wo plain fp16
__device__ unsigned g_qs1[ROWS * 1024];     // Q rope+scale, plain fp16
__device__ unsigned g_ks1[ROWS * 1024];     // K rope, plain fp16
__device__ unsigned g_v1[ROWS * 1024];      // V plain fp16 plane

// ---------------------------------------------------------------------------
__device__ __forceinline__ void mma_f16(float4& c,
                                        unsigned a0, unsigned a1, unsigned a2, unsigned a3,
                                        unsigned b0, unsigned b1) {
    asm("mma.sync.aligned.m16n8k16.row.col.f32.f16.f16.f32 "
        "{%0,%1,%2,%3}, {%4,%5,%6,%7}, {%8,%9}, {%0,%1,%2,%3};"
        : "+f"(c.x), "+f"(c.y), "+f"(c.z), "+f"(c.w)
        : "r"(a0), "r"(a1), "r"(a2), "r"(a3), "r"(b0), "r"(b1));
}

__device__ __forceinline__ void ldsm_x4(uint4& r, unsigned addr) {
    asm volatile("ldmatrix.sync.aligned.m8n8.x4.shared.b16 {%0,%1,%2,%3}, [%4];"
                 : "=r"(r.x), "=r"(r.y), "=r"(r.z), "=r"(r.w) : "r"(addr));
}

__device__ __forceinline__ void ldsm_x4t(uint4& r, unsigned addr) {
    asm volatile("ldmatrix.sync.aligned.m8n8.x4.trans.shared.b16 {%0,%1,%2,%3}, [%4];"
                 : "=r"(r.x), "=r"(r.y), "=r"(r.z), "=r"(r.w) : "r"(addr));
}

__device__ __forceinline__ unsigned pack_f16x2(float x, float y) {
    __half2 h = __floats2half2_rn(x, y);
    return *(unsigned*)&h;
}

// ---------------------------------------------------------------------------
__global__ void rope_tables_kernel() {
    int idx = blockIdx.x * blockDim.x + threadIdx.x;
    int s = idx >> 6, i = idx & 63;
    double invd = pow(10000.0, -((double)(2 * i)) / 128.0);
    float arg = (float)s * (float)invd;
    double sv, cv;
    sincos((double)arg, &sv, &cv);
    g_cos[idx] = (float)cv;
    g_sin[idx] = (float)sv;
}

// One launch packs x + all four weights to fp16.
__global__ void packall_kernel(const float* __restrict__ x,
                               const float* __restrict__ Wq,
                               const float* __restrict__ Wk,
                               const float* __restrict__ Wv,
                               const float* __restrict__ Wo,
                               unsigned* __restrict__ xs,
                               unsigned* __restrict__ ws) {
    int p = blockIdx.x * blockDim.x + threadIdx.x;
    const int XP = ROWS * RWU;
    const float* src;
    unsigned* dst;
    int off;
    if (p < XP) {
        src = x; dst = xs; off = p;
    } else {
        int q = p - XP;
        int wsel = q >> 21;
        off = q & (WU - 1);
        src = (wsel == 0) ? Wq : (wsel == 1) ? Wk : (wsel == 2) ? Wv : Wo;
        dst = ws + wsel * WU;
    }
    float2 v = *(const float2*)&src[2 * off];
    dst[off] = pack_f16x2(v.x, v.y);
}

// ---------------------------------------------------------------------------
// GEMM C[m,n] = sum_k A[m,k]*B[n,k]. Plain fp16, ldmatrix, k64 stages.
// 128x128 CTA tile, 8 warps (2x4), warp 64x32, 3-stage cp.async ring.
// modes: 0 = fp32 C; -1 = per bx>>4: 0->Q(rope+scale), 1->K(rope), 2->V.
// ---------------------------------------------------------------------------
#define MG_P_U    4608                        // 128 rows x 36 u32 (32 data + 4 pad)
#define MG_STAGEU (2 * MG_P_U)                // 9216 u32 = 36864 B
#define MG_SMEM_BYTES (3 * MG_STAGEU * 4)     // 110592
#define MG_KT     (DM / 64)                   // 32

__global__ __launch_bounds__(256, 2) void mgemm_h1(
        const unsigned* __restrict__ Ag, const unsigned* __restrict__ Bg,
        int modes, float* __restrict__ Cf,
        unsigned* __restrict__ Pv,
        unsigned* __restrict__ Pq, unsigned* __restrict__ Pk) {
    extern __shared__ unsigned sm[];
    const unsigned sbase = (unsigned)__cvta_generic_to_shared(sm);
    const int tid = threadIdx.x, wid = tid >> 5, lane = tid & 31;
    const int wm = wid >> 2, wn = wid & 3, g8 = lane >> 2, qd = lane & 3;
    const int bx = blockIdx.x, by = blockIdx.y;

    // loaders: 1024 chunks per matrix (128 rows x 8), per thread 4 A + 4 B,
    // rows lr + {0,32,64,96}
    const int lr = tid >> 3, lc = (tid & 7) << 2;
    const unsigned* sA = Ag + (size_t)(by * 128 + lr) * RWU + lc;
    const unsigned* sB = Bg + (size_t)(bx * 128 + lr) * RWU + lc;
    const unsigned dA0 = sbase + (unsigned)(lr * 36 + lc) * 4u;
    const unsigned dB0 = dA0 + MG_P_U * 4u;

    auto load_stage = [&](unsigned bufB, int kt) {
        const unsigned* a = sA + kt * 32;
        const unsigned* b = sB + kt * 32;
#pragma unroll
        for (int l = 0; l < 4; ++l) {
            asm volatile("cp.async.cg.shared.global [%0], [%1], 16;"
                         :: "r"(dA0 + bufB + (unsigned)(l * 4608)),
                            "l"(a + (size_t)l * 32 * RWU));
            asm volatile("cp.async.cg.shared.global [%0], [%1], 16;"
                         :: "r"(dB0 + bufB + (unsigned)(l * 4608)),
                            "l"(b + (size_t)l * 32 * RWU));
        }
        asm volatile("cp.async.commit_group;");
    };

    float4 acc[4][4];
#pragma unroll
    for (int i = 0; i < 4; i++)
#pragma unroll
        for (int j = 0; j < 4; j++) acc[i][j] = make_float4(0.f, 0.f, 0.f, 0.f);

    // ldmatrix lane addresses (bytes)
    const int lrow16 = lane & 15, lkh = lane >> 4;
    const unsigned aLd0 = sbase
        + (unsigned)(((wm * 64 + lrow16) * 36 + lkh * 4) * 4);
    const int bg = lane >> 3, brow = lane & 7;
    const unsigned bLd0 = sbase
        + (unsigned)((MG_P_U + (wn * 32 + (bg >> 1) * 8 + brow) * 36 + (bg & 1) * 4) * 4);

    auto compute = [&](unsigned so) {
#pragma unroll
        for (int ks = 0; ks < 4; ++ks) {
            uint4 af[4];
#pragma unroll
            for (int mi = 0; mi < 4; ++mi)
                ldsm_x4(af[mi], aLd0 + so + (unsigned)((mi * 576 + ks * 8) * 4));
            uint4 bf[2];
#pragma unroll
            for (int np = 0; np < 2; ++np)
                ldsm_x4(bf[np], bLd0 + so + (unsigned)((np * 576 + ks * 8) * 4));
#pragma unroll
            for (int mi = 0; mi < 4; ++mi) {
                mma_f16(acc[mi][0], af[mi].x, af[mi].y, af[mi].z, af[mi].w,
                        bf[0].x, bf[0].y);
                mma_f16(acc[mi][1], af[mi].x, af[mi].y, af[mi].z, af[mi].w,
                        bf[0].z, bf[0].w);
                mma_f16(acc[mi][2], af[mi].x, af[mi].y, af[mi].z, af[mi].w,
                        bf[1].x, bf[1].y);
                mma_f16(acc[mi][3], af[mi].x, af[mi].y, af[mi].z, af[mi].w,
                        bf[1].z, bf[1].w);
            }
        }
    };

    load_stage(0, 0);
    load_stage(MG_STAGEU * 4u, 1);
    int cs = 0, ls = 2;
#pragma unroll 1
    for (int kt = 0; kt < MG_KT; ++kt) {
        if (kt + 1 < MG_KT) asm volatile("cp.async.wait_group 1;");
        else                asm volatile("cp.async.wait_group 0;");
        __syncthreads();
        if (kt + 2 < MG_KT) {
            load_stage((unsigned)(ls * MG_STAGEU) * 4u, kt + 2);
            ls = (ls == 2) ? 0 : ls + 1;
        }
        compute((unsigned)(cs * MG_STAGEU) * 4u);
        cs = (cs == 2) ? 0 : cs + 1;
    }

    int mode, bxl;
    if (modes >= 0) { mode = modes; bxl = bx; }
    else { int r = bx >> 4; mode = (r == 0) ? 2 : (r == 1 ? 3 : 1); bxl = bx & 15; }
    const float SC = 0.08838834764831845f;   // 1/sqrt(128)

#pragma unroll
    for (int mi = 0; mi < 4; ++mi)
#pragma unroll
        for (int ni = 0; ni < 4; ++ni) {
            int r0 = by * 128 + wm * 64 + mi * 16 + g8;
            int c0 = bxl * 128 + wn * 32 + ni * 8 + 2 * qd;
            float4 v = acc[mi][ni];
            if (mode == 0) {
                *(float2*)&Cf[(size_t)r0 * DM + c0] = make_float2(v.x, v.y);
                *(float2*)&Cf[(size_t)(r0 + 8) * DM + c0] = make_float2(v.z, v.w);
            } else if (mode == 1) {        // V plain fp16 plane
                int pA = r0 * 1024 + (c0 >> 1);
                Pv[pA] = pack_f16x2(v.x, v.y);
                Pv[pA + 8192] = pack_f16x2(v.z, v.w);
            } else {                        // Q/K: rope (+scale), plain fp16
                int i = (c0 & 127) >> 1;
                int s0 = r0 & (SEQ - 1);
                float c_ = g_cos[(s0 << 6) + i], sn = g_sin[(s0 << 6) + i];
                float c1 = g_cos[((s0 + 8) << 6) + i], s1 = g_sin[((s0 + 8) << 6) + i];
                float x0 = v.x * c_ - v.y * sn, y0 = v.y * c_ + v.x * sn;
                float x1 = v.z * c1 - v.w * s1, y1 = v.w * c1 + v.z * s1;
                int pA = r0 * 1024 + (c0 >> 1);
                if (mode == 2) {
                    x0 *= SC; y0 *= SC; x1 *= SC; y1 *= SC;
                    Pq[pA] = pack_f16x2(x0, y0);
                    Pq[pA + 8192] = pack_f16x2(x1, y1);
                } else {
                    Pk[pA] = pack_f16x2(x0, y0);
                    Pk[pA + 8192] = pack_f16x2(x1, y1);
                }
            }
        }
}

// ---------------------------------------------------------------------------
// Flash attention: 128 q-rows/CTA (256 thr, 8 warps, 16 rows/warp), 64-key
// tiles, plain fp16 QK + PV, batched ldmatrix, K/V dbuf, 2 CTAs/SM.
// ---------------------------------------------------------------------------
#define FL_Q_U     (128 * 68)                 // 8704 u32
#define FLK_U      (64 * 68)
#define FLV_U      (64 * 64)
#define FL_STAGE_U (FLK_U + FLV_U)            // 8448 u32
#define FL_SMEM_BYTES ((FL_Q_U + 2 * FL_STAGE_U) * 4)   // 102400

__global__ __launch_bounds__(256, 2) void flash_mma(const unsigned* __restrict__ qs1,
                                                    const unsigned* __restrict__ ks1,
                                                    const unsigned* __restrict__ v1,
                                                    unsigned* __restrict__ As1) {
    extern __shared__ unsigned su[];
    const unsigned sb  = (unsigned)__cvta_generic_to_shared(su);
    const unsigned QsB = sb;
    const unsigned St0 = sb + FL_Q_U * 4;

    const int tid = threadIdx.x, lane = tid & 31, w = tid >> 5;
    const int gr = lane >> 2, q4 = lane & 3;
    const int qi = (int)gridDim.x - 1 - (int)blockIdx.x;   // longest first
    const int bh = blockIdx.y;
    const int b = bh >> 4, h = bh & 15;
    const size_t qrow0 = (size_t)(b * SEQ + qi * 128);
    const int ktmax = 2 * qi + 1;

    // Q tile
#pragma unroll
    for (int it = 0; it < 8; ++it) {
        int c = tid + it * 256;
        int r = c >> 4, ch = c & 15;
        const unsigned* src = qs1 + (qrow0 + r) * 1024 + h * 64 + ch * 4;
        unsigned dst = QsB + (unsigned)(r * 68 + ch * 4) * 4u;
        asm volatile("cp.async.cg.shared.global [%0], [%1], 16;" :: "r"(dst), "l"(src));
    }
    asm volatile("cp.async.commit_group;");

    auto load_kv = [&](int s, int kt) {
        const size_t krow0 = (size_t)(b * SEQ + kt * 64);
        const unsigned KB = St0 + (unsigned)(s * FL_STAGE_U) * 4u;
        const unsigned VB = KB + FLK_U * 4u;
#pragma unroll
        for (int it = 0; it < 4; ++it) {
            int c = tid + it * 256;
            int r = c >> 4, ch = c & 15;
            const unsigned* src = ks1 + (krow0 + r) * 1024 + h * 64 + ch * 4;
            asm volatile("cp.async.cg.shared.global [%0], [%1], 16;"
                         :: "r"(KB + (unsigned)(r * 68 + ch * 4) * 4u), "l"(src));
        }
#pragma unroll
        for (int it = 0; it < 4; ++it) {
            int c = tid + it * 256;
            int s_ = c >> 4, cb = c & 15;
            unsigned soff = (unsigned)(s_ * 64 + ((cb ^ (s_ & 7)) << 2)) * 4u;
            const unsigned* src = v1 + (krow0 + s_) * 1024 + h * 64 + cb * 4;
            asm volatile("cp.async.cg.shared.global [%0], [%1], 16;"
                         :: "r"(VB + soff), "l"(src));
        }
        asm volatile("cp.async.commit_group;");
    };

    load_kv(0, 0);

    // ldmatrix lane addresses
    const int lrow16 = lane & 15, lkh = lane >> 4;
    const unsigned qLd0 = QsB + (unsigned)(((w * 16 + lrow16) * 68 + lkh * 4) * 4);
    const int bg = lane >> 3, brow = lane & 7;
    const unsigned kLdLane = (unsigned)((((bg >> 1) * 8 + brow) * 68 + (bg & 1) * 4) * 4);
    const int mgrp = lane >> 3, lr2 = lane & 7;

    float4 O[16];
#pragma unroll
    for (int j = 0; j < 16; ++j) O[j] = make_float4(0.f, 0.f, 0.f, 0.f);
    float m0 = -INFINITY, m1 = -INFINITY, l0 = 0.f, l1 = 0.f;

    for (int kt = 0; kt <= ktmax; ++kt) {
        if (kt + 1 <= ktmax) {
            load_kv((kt + 1) & 1, kt + 1);
            asm volatile("cp.async.wait_group 1;");
        } else {
            asm volatile("cp.async.wait_group 0;");
        }
        __syncthreads();

        const int st = kt & 1;
        const unsigned KBb = St0 + (unsigned)(st * FL_STAGE_U) * 4u;
        const unsigned VB = KBb + FLK_U * 4u;

        // ---- S = Q K^T: batch 1 Q + 4 K ldsm before the 8 MMAs ----
        float4 s4[8];
#pragma unroll
        for (int nt = 0; nt < 8; ++nt) s4[nt] = make_float4(0.f, 0.f, 0.f, 0.f);

#pragma unroll
        for (int t = 0; t < 8; ++t) {
            uint4 aq;
            ldsm_x4(aq, qLd0 + (unsigned)(t * 32));
            uint4 kf[4];
#pragma unroll
            for (int p = 0; p < 4; ++p)
                ldsm_x4(kf[p], KBb + kLdLane + (unsigned)(p * 4352 + t * 32));
#pragma unroll
            for (int p = 0; p < 4; ++p) {
                mma_f16(s4[2 * p],     aq.x, aq.y, aq.z, aq.w, kf[p].x, kf[p].y);
                mma_f16(s4[2 * p + 1], aq.x, aq.y, aq.z, aq.w, kf[p].z, kf[p].w);
            }
        }

        if (kt >= 2 * qi) {   // causal mask: only last two tiles
            int off = (kt - 2 * qi) * 64;
            int r0 = w * 16 + gr, r1 = r0 + 8;
#pragma unroll
            for (int nt = 0; nt < 8; ++nt) {
                int c0 = nt * 8 + 2 * q4 + off;
                if (c0 > r0)     s4[nt].x = -INFINITY;
                if (c0 + 1 > r0) s4[nt].y = -INFINITY;
                if (c0 > r1)     s4[nt].z = -INFINITY;
                if (c0 + 1 > r1) s4[nt].w = -INFINITY;
            }
        }

        float mx0 = -INFINITY, mx1 = -INFINITY;
#pragma unroll
        for (int nt = 0; nt < 8; ++nt) {
            mx0 = fmaxf(mx0, fmaxf(s4[nt].x, s4[nt].y));
            mx1 = fmaxf(mx1, fmaxf(s4[nt].z, s4[nt].w));
        }
        mx0 = fmaxf(mx0, __shfl_xor_sync(0xffffffffu, mx0, 1));
        mx0 = fmaxf(mx0, __shfl_xor_sync(0xffffffffu, mx0, 2));
        mx1 = fmaxf(mx1, __shfl_xor_sync(0xffffffffu, mx1, 1));
        mx1 = fmaxf(mx1, __shfl_xor_sync(0xffffffffu, mx1, 2));
        float nm0 = fmaxf(m0, mx0), nm1 = fmaxf(m1, mx1);
        float al0 = __expf(m0 - nm0), al1 = __expf(m1 - nm1);
        m0 = nm0; m1 = nm1;

        float sum0 = 0.f, sum1 = 0.f;
#pragma unroll
        for (int nt = 0; nt < 8; ++nt) {
            s4[nt].x = __expf(s4[nt].x - nm0);
            s4[nt].y = __expf(s4[nt].y - nm0);
            s4[nt].z = __expf(s4[nt].z - nm1);
            s4[nt].w = __expf(s4[nt].w - nm1);
            sum0 += s4[nt].x + s4[nt].y;
            sum1 += s4[nt].z + s4[nt].w;
        }
        sum0 += __shfl_xor_sync(0xffffffffu, sum0, 1);
        sum0 += __shfl_xor_sync(0xffffffffu, sum0, 2);
        sum1 += __shfl_xor_sync(0xffffffffu, sum1, 1);
        sum1 += __shfl_xor_sync(0xffffffffu, sum1, 2);
        l0 = l0 * al0 + sum0;
        l1 = l1 * al1 + sum1;
#pragma unroll
        for (int j = 0; j < 16; ++j) {
            O[j].x *= al0; O[j].y *= al0; O[j].z *= al1; O[j].w *= al1;
        }

        // ---- P plain fp16; O += P V (batch 4 V-ldsm before 8 MMAs) ----
        unsigned phi[16];
#pragma unroll
        for (int nt = 0; nt < 8; ++nt) {
            phi[2 * nt]     = pack_f16x2(s4[nt].x, s4[nt].y);
            phi[2 * nt + 1] = pack_f16x2(s4[nt].z, s4[nt].w);
        }

#pragma unroll
        for (int t2 = 0; t2 < 4; ++t2) {
            unsigned pa0 = phi[4 * t2], pa1 = phi[4 * t2 + 1];
            unsigned pa2 = phi[4 * t2 + 2], pa3 = phi[4 * t2 + 3];
            const int srow = 16 * t2 + ((mgrp & 1) << 3) + lr2;
#pragma unroll
            for (int nh = 0; nh < 2; ++nh) {      // nb batches of 4
                uint4 vf[4];
#pragma unroll
                for (int nb = 0; nb < 4; ++nb) {
                    int cb = 2 * (4 * nh + nb) + (mgrp >> 1);
                    unsigned off = (unsigned)(srow * 64 + ((cb ^ (srow & 7)) << 2)) * 4u;
                    ldsm_x4t(vf[nb], VB + off);
                }
#pragma unroll
                for (int nb = 0; nb < 4; ++nb) {
                    int j = 2 * (4 * nh + nb);
                    mma_f16(O[j],     pa0, pa1, pa2, pa3, vf[nb].x, vf[nb].y);
                    mma_f16(O[j + 1], pa0, pa1, pa2, pa3, vf[nb].z, vf[nb].w);
                }
            }
        }
        __syncthreads();
    }

    // epilogue: normalize + plain fp16 pack (A-side of Wo GEMM)
    float inv0 = 1.0f / l0, inv1 = 1.0f / l1;
    size_t p0 = (qrow0 + w * 16 + gr) * RWU + h * 64;
    size_t p1 = p0 + (size_t)8 * RWU;
#pragma unroll
    for (int j = 0; j < 16; ++j) {
        int pc = j * 4 + q4;
        As1[p0 + pc] = pack_f16x2(O[j].x * inv0, O[j].y * inv0);
        As1[p1 + pc] = pack_f16x2(O[j].z * inv1, O[j].w * inv1);
    }
}

// ---------------------------------------------------------------------------
extern "C" void kernel_launch(void* const* d_in, const int* in_sizes, int n_in,
                              void* d_out, int out_size) {
    const float* x  = (const float*)d_in[0];
    const float* Wq = (const float*)d_in[1];
    const float* Wk = (const float*)d_in[2];
    const float* Wv = (const float*)d_in[3];
    const float* Wo = (const float*)d_in[4];
    float* out = (float*)d_out;

    unsigned *xs, *as, *ws, *v1, *ks1, *qs1;
    cudaGetSymbolAddress((void**)&xs, g_xs);
    cudaGetSymbolAddress((void**)&as, g_as);
    cudaGetSymbolAddress((void**)&ws, g_ws);
    cudaGetSymbolAddress((void**)&v1, g_v1);
    cudaGetSymbolAddress((void**)&ks1, g_ks1);
    cudaGetSymbolAddress((void**)&qs1, g_qs1);

    rope_tables_kernel<<<(SEQ * 64) / 256, 256>>>();

    const int TOTALP = ROWS * RWU + 4 * WU;
    packall_kernel<<<TOTALP / 256, 256>>>(x, Wq, Wk, Wv, Wo, xs, ws);

    cudaFuncSetAttribute(mgemm_h1, cudaFuncAttributeMaxDynamicSharedMemorySize,
                         MG_SMEM_BYTES);
    // QKV mega-GEMM: bx 0-15 -> Q, 16-31 -> K, 32-47 -> V
    mgemm_h1<<<dim3(48, 64), 256, MG_SMEM_BYTES>>>(xs, ws, -1, nullptr,
                                                   v1, qs1, ks1);

    cudaFuncSetAttribute(flash_mma, cudaFuncAttributeMaxDynamicSharedMemorySize,
                         FL_SMEM_BYTES);
    flash_mma<<<dim3(SEQ / 128, BATCH * NH), 256, FL_SMEM_BYTES>>>(
        qs1, ks1, v1, as);

    mgemm_h1<<<dim3(16, 64), 256, MG_SMEM_BYTES>>>(as, ws + 3 * WU, 0, out,
                                                   nullptr, nullptr, nullptr);
}

// round 14
// speedup vs baseline: 6.6161x; 1.0277x over previous
#include <cuda_runtime.h>
#include <cuda_fp16.h>
#include <math.h>

// ---------------------------------------------------------------------------
// Fused causal MHA forward — plain-fp16 mma.sync, ldmatrix fragment loads.
//   GEMMs: k64 stages, 3-stage cp.async ring, fused epilogues (round-13).
//   Flash: ex2.f16x2 softmax, ones-column MMA row sums, rescale-skip.
// ---------------------------------------------------------------------------

#define SEQ   4096
#define BATCH 2
#define DM    2048
#define NH    16
#define DH    128
#define ROWS  (BATCH * SEQ)      // 8192
#define WU    (DM * DM / 2)      // u32 per packed weight plane
#define RWU   (DM / 2)           // u32 per packed activation row

__device__ float    g_cos[SEQ * 64];
__device__ float    g_sin[SEQ * 64];
__device__ unsigned g_xs[ROWS * RWU];       // x plain fp16
__device__ unsigned g_as[ROWS * RWU];       // attn out plain fp16
__device__ unsigned g_ws[4 * WU];           // Wq|Wk|Wv|Wo plain fp16
__device__ unsigned g_qs1[ROWS * 1024];     // Q rope+scale, plain fp16
__device__ unsigned g_ks1[ROWS * 1024];     // K rope, plain fp16
__device__ unsigned g_v1[ROWS * 1024];      // V plain fp16 plane

// ---------------------------------------------------------------------------
__device__ __forceinline__ void mma_f16(float4& c,
                                        unsigned a0, unsigned a1, unsigned a2, unsigned a3,
                                        unsigned b0, unsigned b1) {
    asm("mma.sync.aligned.m16n8k16.row.col.f32.f16.f16.f32 "
        "{%0,%1,%2,%3}, {%4,%5,%6,%7}, {%8,%9}, {%0,%1,%2,%3};"
        : "+f"(c.x), "+f"(c.y), "+f"(c.z), "+f"(c.w)
        : "r"(a0), "r"(a1), "r"(a2), "r"(a3), "r"(b0), "r"(b1));
}

__device__ __forceinline__ void ldsm_x4(uint4& r, unsigned addr) {
    asm volatile("ldmatrix.sync.aligned.m8n8.x4.shared.b16 {%0,%1,%2,%3}, [%4];"
                 : "=r"(r.x), "=r"(r.y), "=r"(r.z), "=r"(r.w) : "r"(addr));
}

__device__ __forceinline__ void ldsm_x4t(uint4& r, unsigned addr) {
    asm volatile("ldmatrix.sync.aligned.m8n8.x4.trans.shared.b16 {%0,%1,%2,%3}, [%4];"
                 : "=r"(r.x), "=r"(r.y), "=r"(r.z), "=r"(r.w) : "r"(addr));
}

__device__ __forceinline__ unsigned pack_f16x2(float x, float y) {
    __half2 h = __floats2half2_rn(x, y);
    return *(unsigned*)&h;
}

__device__ __forceinline__ unsigned ex2_f16x2(unsigned a) {
    unsigned r;
    asm("ex2.approx.f16x2 %0, %1;" : "=r"(r) : "r"(a));
    return r;
}

// ---------------------------------------------------------------------------
__global__ void rope_tables_kernel() {
    int idx = blockIdx.x * blockDim.x + threadIdx.x;
    int s = idx >> 6, i = idx & 63;
    double invd = pow(10000.0, -((double)(2 * i)) / 128.0);
    float arg = (float)s * (float)invd;
    double sv, cv;
    sincos((double)arg, &sv, &cv);
    g_cos[idx] = (float)cv;
    g_sin[idx] = (float)sv;
}

// One launch packs x + all four weights to fp16.
__global__ void packall_kernel(const float* __restrict__ x,
                               const float* __restrict__ Wq,
                               const float* __restrict__ Wk,
                               const float* __restrict__ Wv,
                               const float* __restrict__ Wo,
                               unsigned* __restrict__ xs,
                               unsigned* __restrict__ ws) {
    int p = blockIdx.x * blockDim.x + threadIdx.x;
    const int XP = ROWS * RWU;
    const float* src;
    unsigned* dst;
    int off;
    if (p < XP) {
        src = x; dst = xs; off = p;
    } else {
        int q = p - XP;
        int wsel = q >> 21;
        off = q & (WU - 1);
        src = (wsel == 0) ? Wq : (wsel == 1) ? Wk : (wsel == 2) ? Wv : Wo;
        dst = ws + wsel * WU;
    }
    float2 v = *(const float2*)&src[2 * off];
    dst[off] = pack_f16x2(v.x, v.y);
}

// ---------------------------------------------------------------------------
// GEMM C[m,n] = sum_k A[m,k]*B[n,k]. Plain fp16, ldmatrix, k64 stages.
// 128x128 CTA tile, 8 warps (2x4), warp 64x32, 3-stage cp.async ring.
// modes: 0 = fp32 C; -1 = per bx>>4: 0->Q(rope+scale), 1->K(rope), 2->V.
// ---------------------------------------------------------------------------
#define MG_P_U    4608                        // 128 rows x 36 u32
#define MG_STAGEU (2 * MG_P_U)                // 9216 u32
#define MG_SMEM_BYTES (3 * MG_STAGEU * 4)     // 110592
#define MG_KT     (DM / 64)                   // 32

__global__ __launch_bounds__(256, 2) void mgemm_h1(
        const unsigned* __restrict__ Ag, const unsigned* __restrict__ Bg,
        int modes, float* __restrict__ Cf,
        unsigned* __restrict__ Pv,
        unsigned* __restrict__ Pq, unsigned* __restrict__ Pk) {
    extern __shared__ unsigned sm[];
    const unsigned sbase = (unsigned)__cvta_generic_to_shared(sm);
    const int tid = threadIdx.x, wid = tid >> 5, lane = tid & 31;
    const int wm = wid >> 2, wn = wid & 3, g8 = lane >> 2, qd = lane & 3;
    const int bx = blockIdx.x, by = blockIdx.y;

    const int lr = tid >> 3, lc = (tid & 7) << 2;
    const unsigned* sA = Ag + (size_t)(by * 128 + lr) * RWU + lc;
    const unsigned* sB = Bg + (size_t)(bx * 128 + lr) * RWU + lc;
    const unsigned dA0 = sbase + (unsigned)(lr * 36 + lc) * 4u;
    const unsigned dB0 = dA0 + MG_P_U * 4u;

    auto load_stage = [&](unsigned bufB, int kt) {
        const unsigned* a = sA + kt * 32;
        const unsigned* b = sB + kt * 32;
#pragma unroll
        for (int l = 0; l < 4; ++l) {
            asm volatile("cp.async.cg.shared.global [%0], [%1], 16;"
                         :: "r"(dA0 + bufB + (unsigned)(l * 4608)),
                            "l"(a + (size_t)l * 32 * RWU));
            asm volatile("cp.async.cg.shared.global [%0], [%1], 16;"
                         :: "r"(dB0 + bufB + (unsigned)(l * 4608)),
                            "l"(b + (size_t)l * 32 * RWU));
        }
        asm volatile("cp.async.commit_group;");
    };

    float4 acc[4][4];
#pragma unroll
    for (int i = 0; i < 4; i++)
#pragma unroll
        for (int j = 0; j < 4; j++) acc[i][j] = make_float4(0.f, 0.f, 0.f, 0.f);

    const int lrow16 = lane & 15, lkh = lane >> 4;
    const unsigned aLd0 = sbase
        + (unsigned)(((wm * 64 + lrow16) * 36 + lkh * 4) * 4);
    const int bg = lane >> 3, brow = lane & 7;
    const unsigned bLd0 = sbase
        + (unsigned)((MG_P_U + (wn * 32 + (bg >> 1) * 8 + brow) * 36 + (bg & 1) * 4) * 4);

    auto compute = [&](unsigned so) {
#pragma unroll
        for (int ks = 0; ks < 4; ++ks) {
            uint4 af[4];
#pragma unroll
            for (int mi = 0; mi < 4; ++mi)
                ldsm_x4(af[mi], aLd0 + so + (unsigned)((mi * 576 + ks * 8) * 4));
            uint4 bf[2];
#pragma unroll
            for (int np = 0; np < 2; ++np)
                ldsm_x4(bf[np], bLd0 + so + (unsigned)((np * 576 + ks * 8) * 4));
#pragma unroll
            for (int mi = 0; mi < 4; ++mi) {
                mma_f16(acc[mi][0], af[mi].x, af[mi].y, af[mi].z, af[mi].w,
                        bf[0].x, bf[0].y);
                mma_f16(acc[mi][1], af[mi].x, af[mi].y, af[mi].z, af[mi].w,
                        bf[0].z, bf[0].w);
                mma_f16(acc[mi][2], af[mi].x, af[mi].y, af[mi].z, af[mi].w,
                        bf[1].x, bf[1].y);
                mma_f16(acc[mi][3], af[mi].x, af[mi].y, af[mi].z, af[mi].w,
                        bf[1].z, bf[1].w);
            }
        }
    };

    load_stage(0, 0);
    load_stage(MG_STAGEU * 4u, 1);
    int cs = 0, ls = 2;
#pragma unroll 1
    for (int kt = 0; kt < MG_KT; ++kt) {
        if (kt + 1 < MG_KT) asm volatile("cp.async.wait_group 1;");
        else                asm volatile("cp.async.wait_group 0;");
        __syncthreads();
        if (kt + 2 < MG_KT) {
            load_stage((unsigned)(ls * MG_STAGEU) * 4u, kt + 2);
            ls = (ls == 2) ? 0 : ls + 1;
        }
        compute((unsigned)(cs * MG_STAGEU) * 4u);
        cs = (cs == 2) ? 0 : cs + 1;
    }

    int mode, bxl;
    if (modes >= 0) { mode = modes; bxl = bx; }
    else { int r = bx >> 4; mode = (r == 0) ? 2 : (r == 1 ? 3 : 1); bxl = bx & 15; }
    const float SC = 0.08838834764831845f;   // 1/sqrt(128)

#pragma unroll
    for (int mi = 0; mi < 4; ++mi)
#pragma unroll
        for (int ni = 0; ni < 4; ++ni) {
            int r0 = by * 128 + wm * 64 + mi * 16 + g8;
            int c0 = bxl * 128 + wn * 32 + ni * 8 + 2 * qd;
            float4 v = acc[mi][ni];
            if (mode == 0) {
                *(float2*)&Cf[(size_t)r0 * DM + c0] = make_float2(v.x, v.y);
                *(float2*)&Cf[(size_t)(r0 + 8) * DM + c0] = make_float2(v.z, v.w);
            } else if (mode == 1) {        // V plain fp16 plane
                int pA = r0 * 1024 + (c0 >> 1);
                Pv[pA] = pack_f16x2(v.x, v.y);
                Pv[pA + 8192] = pack_f16x2(v.z, v.w);
            } else {                        // Q/K: rope (+scale), plain fp16
                int i = (c0 & 127) >> 1;
                int s0 = r0 & (SEQ - 1);
                float c_ = g_cos[(s0 << 6) + i], sn = g_sin[(s0 << 6) + i];
                float c1 = g_cos[((s0 + 8) << 6) + i], s1 = g_sin[((s0 + 8) << 6) + i];
                float x0 = v.x * c_ - v.y * sn, y0 = v.y * c_ + v.x * sn;
                float x1 = v.z * c1 - v.w * s1, y1 = v.w * c1 + v.z * s1;
                int pA = r0 * 1024 + (c0 >> 1);
                if (mode == 2) {
                    x0 *= SC; y0 *= SC; x1 *= SC; y1 *= SC;
                    Pq[pA] = pack_f16x2(x0, y0);
                    Pq[pA + 8192] = pack_f16x2(x1, y1);
                } else {
                    Pk[pA] = pack_f16x2(x0, y0);
                    Pk[pA + 8192] = pack_f16x2(x1, y1);
                }
            }
        }
}

// ---------------------------------------------------------------------------
// Flash attention: 128 q-rows/CTA (256 thr, 8 warps, 16 rows/warp), 64-key
// tiles, plain fp16 QK + PV. Softmax: ex2.f16x2 -> fp16 P directly; row sums
// via ones-column MMA; alpha-rescale skipped when max unchanged (warp vote).
// ---------------------------------------------------------------------------
#define FL_Q_U     (128 * 68)                 // 8704 u32
#define FLK_U      (64 * 68)
#define FLV_U      (64 * 64)
#define FL_STAGE_U (FLK_U + FLV_U)            // 8448 u32
#define FL_SMEM_BYTES ((FL_Q_U + 2 * FL_STAGE_U) * 4)   // 102400

#define ONES_F16X2 0x3C003C00u

__global__ __launch_bounds__(256, 2) void flash_mma(const unsigned* __restrict__ qs1,
                                                    const unsigned* __restrict__ ks1,
                                                    const unsigned* __restrict__ v1,
                                                    unsigned* __restrict__ As1) {
    extern __shared__ unsigned su[];
    const unsigned sb  = (unsigned)__cvta_generic_to_shared(su);
    const unsigned QsB = sb;
    const unsigned St0 = sb + FL_Q_U * 4;

    const int tid = threadIdx.x, lane = tid & 31, w = tid >> 5;
    const int gr = lane >> 2, q4 = lane & 3;
    const int qi = (int)gridDim.x - 1 - (int)blockIdx.x;   // longest first
    const int bh = blockIdx.y;
    const int b = bh >> 4, h = bh & 15;
    const size_t qrow0 = (size_t)(b * SEQ + qi * 128);
    const int ktmax = 2 * qi + 1;
    const float L2E = 1.4426950408889634f;

    // Q tile
#pragma unroll
    for (int it = 0; it < 8; ++it) {
        int c = tid + it * 256;
        int r = c >> 4, ch = c & 15;
        const unsigned* src = qs1 + (qrow0 + r) * 1024 + h * 64 + ch * 4;
        unsigned dst = QsB + (unsigned)(r * 68 + ch * 4) * 4u;
        asm volatile("cp.async.cg.shared.global [%0], [%1], 16;" :: "r"(dst), "l"(src));
    }
    asm volatile("cp.async.commit_group;");

    auto load_kv = [&](int s, int kt) {
        const size_t krow0 = (size_t)(b * SEQ + kt * 64);
        const unsigned KB = St0 + (unsigned)(s * FL_STAGE_U) * 4u;
        const unsigned VB = KB + FLK_U * 4u;
#pragma unroll
        for (int it = 0; it < 4; ++it) {
            int c = tid + it * 256;
            int r = c >> 4, ch = c & 15;
            const unsigned* src = ks1 + (krow0 + r) * 1024 + h * 64 + ch * 4;
            asm volatile("cp.async.cg.shared.global [%0], [%1], 16;"
                         :: "r"(KB + (unsigned)(r * 68 + ch * 4) * 4u), "l"(src));
        }
#pragma unroll
        for (int it = 0; it < 4; ++it) {
            int c = tid + it * 256;
            int s_ = c >> 4, cb = c & 15;
            unsigned soff = (unsigned)(s_ * 64 + ((cb ^ (s_ & 7)) << 2)) * 4u;
            const unsigned* src = v1 + (krow0 + s_) * 1024 + h * 64 + cb * 4;
            asm volatile("cp.async.cg.shared.global [%0], [%1], 16;"
                         :: "r"(VB + soff), "l"(src));
        }
        asm volatile("cp.async.commit_group;");
    };

    load_kv(0, 0);

    const int lrow16 = lane & 15, lkh = lane >> 4;
    const unsigned qLd0 = QsB + (unsigned)(((w * 16 + lrow16) * 68 + lkh * 4) * 4);
    const int bg = lane >> 3, brow = lane & 7;
    const unsigned kLdLane = (unsigned)((((bg >> 1) * 8 + brow) * 68 + (bg & 1) * 4) * 4);
    const int mgrp = lane >> 3, lr2 = lane & 7;

    float4 O[16];
#pragma unroll
    for (int j = 0; j < 16; ++j) O[j] = make_float4(0.f, 0.f, 0.f, 0.f);
    float4 Osum = make_float4(0.f, 0.f, 0.f, 0.f);   // ones-column: row sums (l)
    float m0 = -INFINITY, m1 = -INFINITY;

    for (int kt = 0; kt <= ktmax; ++kt) {
        if (kt + 1 <= ktmax) {
            load_kv((kt + 1) & 1, kt + 1);
            asm volatile("cp.async.wait_group 1;");
        } else {
            asm volatile("cp.async.wait_group 0;");
        }
        __syncthreads();

        const int st = kt & 1;
        const unsigned KBb = St0 + (unsigned)(st * FL_STAGE_U) * 4u;
        const unsigned VB = KBb + FLK_U * 4u;

        // ---- S = Q K^T ----
        float4 s4[8];
#pragma unroll
        for (int nt = 0; nt < 8; ++nt) s4[nt] = make_float4(0.f, 0.f, 0.f, 0.f);

#pragma unroll
        for (int t = 0; t < 8; ++t) {
            uint4 aq;
            ldsm_x4(aq, qLd0 + (unsigned)(t * 32));
            uint4 kf[4];
#pragma unroll
            for (int p = 0; p < 4; ++p)
                ldsm_x4(kf[p], KBb + kLdLane + (unsigned)(p * 4352 + t * 32));
#pragma unroll
            for (int p = 0; p < 4; ++p) {
                mma_f16(s4[2 * p],     aq.x, aq.y, aq.z, aq.w, kf[p].x, kf[p].y);
                mma_f16(s4[2 * p + 1], aq.x, aq.y, aq.z, aq.w, kf[p].z, kf[p].w);
            }
        }

        if (kt >= 2 * qi) {   // causal mask: only last two tiles
            int off = (kt - 2 * qi) * 64;
            int r0 = w * 16 + gr, r1 = r0 + 8;
#pragma unroll
            for (int nt = 0; nt < 8; ++nt) {
                int c0 = nt * 8 + 2 * q4 + off;
                if (c0 > r0)     s4[nt].x = -INFINITY;
                if (c0 + 1 > r0) s4[nt].y = -INFINITY;
                if (c0 > r1)     s4[nt].z = -INFINITY;
                if (c0 + 1 > r1) s4[nt].w = -INFINITY;
            }
        }

        // ---- online max ----
        float mx0 = -INFINITY, mx1 = -INFINITY;
#pragma unroll
        for (int nt = 0; nt < 8; ++nt) {
            mx0 = fmaxf(mx0, fmaxf(s4[nt].x, s4[nt].y));
            mx1 = fmaxf(mx1, fmaxf(s4[nt].z, s4[nt].w));
        }
        mx0 = fmaxf(mx0, __shfl_xor_sync(0xffffffffu, mx0, 1));
        mx0 = fmaxf(mx0, __shfl_xor_sync(0xffffffffu, mx0, 2));
        mx1 = fmaxf(mx1, __shfl_xor_sync(0xffffffffu, mx1, 1));
        mx1 = fmaxf(mx1, __shfl_xor_sync(0xffffffffu, mx1, 2));
        float nm0 = fmaxf(m0, mx0), nm1 = fmaxf(m1, mx1);
        float al0 = __expf(m0 - nm0), al1 = __expf(m1 - nm1);
        m0 = nm0; m1 = nm1;

        // rescale only if any row's max moved (warp-uniform vote)
        unsigned need = __ballot_sync(0xffffffffu, (al0 < 1.f) | (al1 < 1.f));
        if (need) {
#pragma unroll
            for (int j = 0; j < 16; ++j) {
                O[j].x *= al0; O[j].y *= al0; O[j].z *= al1; O[j].w *= al1;
            }
            Osum.x *= al0; Osum.y *= al0; Osum.z *= al1; Osum.w *= al1;
        }

        // ---- P = 2^((s-m)*log2e) directly in fp16x2 ----
        const float nmL0 = nm0 * L2E, nmL1 = nm1 * L2E;
        unsigned phi[16];
#pragma unroll
        for (int nt = 0; nt < 8; ++nt) {
            unsigned lo = pack_f16x2(fmaf(s4[nt].x, L2E, -nmL0),
                                     fmaf(s4[nt].y, L2E, -nmL0));
            unsigned hi = pack_f16x2(fmaf(s4[nt].z, L2E, -nmL1),
                                     fmaf(s4[nt].w, L2E, -nmL1));
            phi[2 * nt]     = ex2_f16x2(lo);
            phi[2 * nt + 1] = ex2_f16x2(hi);
        }

        // ---- O += P V (+ ones column -> row sums) ----
#pragma unroll
        for (int t2 = 0; t2 < 4; ++t2) {
            unsigned pa0 = phi[4 * t2], pa1 = phi[4 * t2 + 1];
            unsigned pa2 = phi[4 * t2 + 2], pa3 = phi[4 * t2 + 3];
            const int srow = 16 * t2 + ((mgrp & 1) << 3) + lr2;
#pragma unroll
            for (int nh = 0; nh < 2; ++nh) {
                uint4 vf[4];
#pragma unroll
                for (int nb = 0; nb < 4; ++nb) {
                    int cb = 2 * (4 * nh + nb) + (mgrp >> 1);
                    unsigned off = (unsigned)(srow * 64 + ((cb ^ (srow & 7)) << 2)) * 4u;
                    ldsm_x4t(vf[nb], VB + off);
                }
#pragma unroll
                for (int nb = 0; nb < 4; ++nb) {
                    int j = 2 * (4 * nh + nb);
                    mma_f16(O[j],     pa0, pa1, pa2, pa3, vf[nb].x, vf[nb].y);
                    mma_f16(O[j + 1], pa0, pa1, pa2, pa3, vf[nb].z, vf[nb].w);
                }
            }
            mma_f16(Osum, pa0, pa1, pa2, pa3, ONES_F16X2, ONES_F16X2);
        }
        __syncthreads();
    }

    // epilogue: normalize by MMA-accumulated row sums + fp16 pack
    float inv0 = 1.0f / Osum.x, inv1 = 1.0f / Osum.z;
    size_t p0 = (qrow0 + w * 16 + gr) * RWU + h * 64;
    size_t p1 = p0 + (size_t)8 * RWU;
#pragma unroll
    for (int j = 0; j < 16; ++j) {
        int pc = j * 4 + q4;
        As1[p0 + pc] = pack_f16x2(O[j].x * inv0, O[j].y * inv0);
        As1[p1 + pc] = pack_f16x2(O[j].z * inv1, O[j].w * inv1);
    }
}

// ---------------------------------------------------------------------------
extern "C" void kernel_launch(void* const* d_in, const int* in_sizes, int n_in,
                              void* d_out, int out_size) {
    const float* x  = (const float*)d_in[0];
    const float* Wq = (const float*)d_in[1];
    const float* Wk = (const float*)d_in[2];
    const float* Wv = (const float*)d_in[3];
    const float* Wo = (const float*)d_in[4];
    float* out = (float*)d_out;

    unsigned *xs, *as, *ws, *v1, *ks1, *qs1;
    cudaGetSymbolAddress((void**)&xs, g_xs);
    cudaGetSymbolAddress((void**)&as, g_as);
    cudaGetSymbolAddress((void**)&ws, g_ws);
    cudaGetSymbolAddress((void**)&v1, g_v1);
    cudaGetSymbolAddress((void**)&ks1, g_ks1);
    cudaGetSymbolAddress((void**)&qs1, g_qs1);

    rope_tables_kernel<<<(SEQ * 64) / 256, 256>>>();

    const int TOTALP = ROWS * RWU + 4 * WU;
    packall_kernel<<<TOTALP / 256, 256>>>(x, Wq, Wk, Wv, Wo, xs, ws);

    cudaFuncSetAttribute(mgemm_h1, cudaFuncAttributeMaxDynamicSharedMemorySize,
                         MG_SMEM_BYTES);
    // QKV mega-GEMM: bx 0-15 -> Q, 16-31 -> K, 32-47 -> V
    mgemm_h1<<<dim3(48, 64), 256, MG_SMEM_BYTES>>>(xs, ws, -1, nullptr,
                                                   v1, qs1, ks1);

    cudaFuncSetAttribute(flash_mma, cudaFuncAttributeMaxDynamicSharedMemorySize,
                         FL_SMEM_BYTES);
    flash_mma<<<dim3(SEQ / 128, BATCH * NH), 256, FL_SMEM_BYTES>>>(
        qs1, ks1, v1, as);

    mgemm_h1<<<dim3(16, 64), 256, MG_SMEM_BYTES>>>(as, ws + 3 * WU, 0, out,
                                                   nullptr, nullptr, nullptr);
}